// round 8
// baseline (speedup 1.0000x reference)
#include <cuda_runtime.h>
#include <cuda_bf16.h>
#include <math.h>
#include <stdint.h>

// Problem constants
#define BB   2
#define SS   2048
#define DD   4096
#define QH   32
#define KVH  8
#define HD   128
#define KVD  (KVH*HD)      // 1024
#define GROUP (QH/KVH)     // 4
#define TOK  (BB*SS)       // 4096
#define K3   (3*DD)        // 12288
#define NQKV (DD + 2*KVD)  // 6144

#define QSCALE (0.08838834764831845f * 1.4426950408889634f)

// ---------------------------------------------------------------------------
// Scratch
// ---------------------------------------------------------------------------
__device__ __align__(16) __nv_bfloat16 g_xc  [TOK*K3];
__device__ __align__(16) __nv_bfloat16 g_wqkv[(size_t)NQKV*K3];
__device__ __align__(16) __nv_bfloat16 g_woc [DD*K3];
__device__ __align__(16) __nv_bfloat16 g_cc  [TOK*K3];

__device__ __align__(16) __nv_bfloat16 g_qh[TOK*DD];
__device__ __align__(16) __nv_bfloat16 g_ql[TOK*DD];
__device__ __align__(16) __nv_bfloat16 g_kh[TOK*KVD];
__device__ __align__(16) __nv_bfloat16 g_kl[TOK*KVD];
__device__ __align__(16) __nv_bfloat16 g_vh[TOK*KVD];
__device__ __align__(16) __nv_bfloat16 g_vl[TOK*KVD];

// ---------------------------------------------------------------------------
// helpers
// ---------------------------------------------------------------------------
__device__ __forceinline__ uint32_t smem_u32(const void* p) {
    uint32_t a;
    asm("{ .reg .u64 t; cvta.to.shared.u64 t, %1; cvt.u32.u64 %0, t; }" : "=r"(a) : "l"(p));
    return a;
}

#define CP_ASYNC16(dst, src) \
    asm volatile("cp.async.cg.shared.global [%0], [%1], 16;" :: "r"(dst), "l"(src))
#define CP_COMMIT()   asm volatile("cp.async.commit_group;" ::: "memory")
#define CP_WAIT(n)    asm volatile("cp.async.wait_group %0;" :: "n"(n) : "memory")

#define LDM_X4(r0, r1, r2, r3, addr) \
    asm volatile("ldmatrix.sync.aligned.m8n8.x4.shared.b16 {%0,%1,%2,%3}, [%4];" \
        : "=r"(r0), "=r"(r1), "=r"(r2), "=r"(r3) : "r"(addr))

#define LDM_X4T(r0, r1, r2, r3, addr) \
    asm volatile("ldmatrix.sync.aligned.m8n8.x4.trans.shared.b16 {%0,%1,%2,%3}, [%4];" \
        : "=r"(r0), "=r"(r1), "=r"(r2), "=r"(r3) : "r"(addr))

#define MMA16816(d, a, b) \
    asm volatile("mma.sync.aligned.m16n8k16.row.col.f32.bf16.bf16.f32 " \
        "{%0,%1,%2,%3},{%4,%5,%6,%7},{%8,%9},{%0,%1,%2,%3};" \
        : "+f"((d)[0]), "+f"((d)[1]), "+f"((d)[2]), "+f"((d)[3]) \
        : "r"((a)[0]), "r"((a)[1]), "r"((a)[2]), "r"((a)[3]), \
          "r"((b)[0]), "r"((b)[1]))

__device__ __forceinline__ uint32_t pack_bf16(float a, float b) {
    uint32_t d;
    asm("cvt.rn.bf16x2.f32 %0, %1, %2;" : "=r"(d) : "f"(b), "f"(a));
    return d;
}
__device__ __forceinline__ float ex2f(float x) {
    float r; asm("ex2.approx.f32 %0, %1;" : "=f"(r) : "f"(x)); return r;
}

// ---------------------------------------------------------------------------
// fp32 -> 3-term bf16 split (concatenated K)
// mode 0 (A-form): [hi | lo | hi]   mode 1 (B-form): [hi | hi | lo]
// ---------------------------------------------------------------------------
__global__ void split_bf16_kernel(const float* __restrict__ in,
                                  __nv_bfloat16* __restrict__ out,
                                  int K, int total4, int mode)
{
    int idx = blockIdx.x * blockDim.x + threadIdx.x;
    if (idx >= total4) return;
    float4 v = ((const float4*)in)[idx];
    int K4 = K >> 2;
    int r  = idx / K4;
    int k  = (idx - r * K4) << 2;
    float vv[4] = {v.x, v.y, v.z, v.w};
    __nv_bfloat16 h[4], l[4];
#pragma unroll
    for (int i = 0; i < 4; i++) {
        h[i] = __float2bfloat16(vv[i]);
        l[i] = __float2bfloat16(vv[i] - __bfloat162float(h[i]));
    }
    __nv_bfloat16* row = out + (size_t)r * (3*K);
    if (mode == 0) {
        *(uint2*)(row + k)       = *(uint2*)h;
        *(uint2*)(row + K + k)   = *(uint2*)l;
        *(uint2*)(row + 2*K + k) = *(uint2*)h;
    } else {
        *(uint2*)(row + k)       = *(uint2*)h;
        *(uint2*)(row + K + k)   = *(uint2*)h;
        *(uint2*)(row + 2*K + k) = *(uint2*)l;
    }
}

// ---------------------------------------------------------------------------
// bf16 MMA GEMM: C = A[M,K3] @ B[N,K3]^T
// CTA 128x128, BK=64, 128 threads (4 warps, 2m x 2n of 64x64), 3 stages, occ 2.
// 64x64 warp tiles halve cross-warp LDSM redundancy (smem-crossbar bound fix).
// MODE 0: fp32 C = acc + bias (bias in bq)
// MODE 1: fused QKV epilogue: route by column segment, rope q/k, hi/lo split.
// ---------------------------------------------------------------------------
#define CTM   128
#define CTN   128
#define GBK   64
#define NST   3
#define NCH   (K3 / GBK)            // 192
#define ROWB  144                   // 64 bf16 (128B) + 16B pad
#define ATILE (CTM * ROWB)          // 18432
#define BTILE (CTN * ROWB)          // 18432
#define STAGE (ATILE + BTILE)       // 36864
#define GSMEM (NST * STAGE)         // 110592

template<int MODE>
__global__ __launch_bounds__(128, 2) void gemm_mma(
    const __nv_bfloat16* __restrict__ A, const __nv_bfloat16* __restrict__ B,
    const float* __restrict__ bq, const float* __restrict__ bk,
    const float* __restrict__ bv,
    float* __restrict__ C, int N,
    const float* __restrict__ fc, const int* __restrict__ spos,
    __nv_bfloat16* __restrict__ qh, __nv_bfloat16* __restrict__ ql,
    __nv_bfloat16* __restrict__ kh, __nv_bfloat16* __restrict__ kl,
    __nv_bfloat16* __restrict__ vh, __nv_bfloat16* __restrict__ vl)
{
    extern __shared__ char smraw[];
    const int t    = threadIdx.x;
    const int lane = t & 31;
    const int wid  = t >> 5;          // 0..3
    const int wm   = wid & 1;         // 64 rows each
    const int wn   = wid >> 1;        // 64 cols each
    const int m0   = blockIdx.x * CTM;
    const int n0   = blockIdx.y * CTN;
    const uint32_t sb = smem_u32(smraw);

    float acc[4][8][4];
#pragma unroll
    for (int i = 0; i < 4; i++)
#pragma unroll
        for (int j = 0; j < 8; j++)
#pragma unroll
            for (int r = 0; r < 4; r++) acc[i][j][r] = 0.f;

    // cp.async: per stage, A tile = 1024 16B chunks, B tile = 1024.
    // thread handles A chunks id = t + i*128 (i<8) and B likewise.
    // row = id>>3 = (t>>3) + 16*i ; c8 = t&7  (constant per thread)
    const __nv_bfloat16* Ag = A + (size_t)(m0 + (t >> 3)) * K3 + (t & 7) * 8;
    const __nv_bfloat16* Bg = B + (size_t)(n0 + (t >> 3)) * K3 + (t & 7) * 8;
    const uint32_t sOff = (t >> 3) * ROWB + (t & 7) * 16;

#define LOAD_STAGE(st, k0) do {                                            \
    uint32_t base = sb + (st) * STAGE;                                     \
    _Pragma("unroll")                                                      \
    for (int i = 0; i < 8; i++)                                            \
        CP_ASYNC16(base + sOff + i * (16 * ROWB), Ag + (k0) + (size_t)i * (16 * K3)); \
    _Pragma("unroll")                                                      \
    for (int i = 0; i < 8; i++)                                            \
        CP_ASYNC16(base + ATILE + sOff + i * (16 * ROWB), Bg + (k0) + (size_t)i * (16 * K3)); \
} while (0)

#pragma unroll
    for (int s = 0; s < NST - 1; s++) {
        LOAD_STAGE(s, s * GBK);
        CP_COMMIT();
    }

    const uint32_t aoffs = (wm * 64 + (lane & 15)) * ROWB + ((lane >> 4) << 4);
    const uint32_t boffs = (wn * 64 + (lane & 15)) * ROWB + ((lane >> 4) << 4);

    int st = 0;
    for (int c = 0; c < NCH; c++) {
        CP_WAIT(1);
        __syncthreads();
        if (c + NST - 1 < NCH) {
            int st2 = st + 2; if (st2 >= NST) st2 -= NST;
            LOAD_STAGE(st2, (c + NST - 1) * GBK);
        }
        CP_COMMIT();

        const uint32_t ab = sb + st * STAGE;
        const uint32_t bb = ab + ATILE;

#pragma unroll
        for (int ks = 0; ks < 4; ks++) {
            uint32_t a[4][4];
            uint32_t bf[8][2];
#pragma unroll
            for (int mi = 0; mi < 4; mi++)
                LDM_X4(a[mi][0], a[mi][1], a[mi][2], a[mi][3],
                       ab + aoffs + mi * (16 * ROWB) + ks * 32);
#pragma unroll
            for (int p = 0; p < 4; p++) {
                uint32_t r0, r1, r2, r3;
                LDM_X4(r0, r1, r2, r3, bb + boffs + p * (16 * ROWB) + ks * 32);
                bf[2*p][0]   = r0; bf[2*p][1]   = r2;
                bf[2*p+1][0] = r1; bf[2*p+1][1] = r3;
            }
#pragma unroll
            for (int mi = 0; mi < 4; mi++)
#pragma unroll
                for (int ni = 0; ni < 8; ni++)
                    MMA16816(acc[mi][ni], a[mi], bf[ni]);
        }
        if (++st == NST) st = 0;
    }
#undef LOAD_STAGE

    if (MODE == 0) {
#pragma unroll
        for (int mi = 0; mi < 4; mi++) {
            int r0 = m0 + wm * 64 + mi * 16 + (lane >> 2);
#pragma unroll
            for (int ni = 0; ni < 8; ni++) {
                int col = n0 + wn * 64 + ni * 8 + (lane & 3) * 2;
                float2 bv2 = *(const float2*)(bq + col);
                float2 o0 = make_float2(acc[mi][ni][0] + bv2.x, acc[mi][ni][1] + bv2.y);
                float2 o1 = make_float2(acc[mi][ni][2] + bv2.x, acc[mi][ni][3] + bv2.y);
                *(float2*)(C + (size_t)r0 * N + col)       = o0;
                *(float2*)(C + (size_t)(r0 + 8) * N + col) = o1;
            }
        }
    } else {
        const int spv = spos[0];
        int seg, cbase;
        if (n0 < DD)            { seg = 0; cbase = 0; }
        else if (n0 < DD + KVD) { seg = 1; cbase = DD; }
        else                    { seg = 2; cbase = DD + KVD; }
        const float* bias = (seg == 0) ? bq : (seg == 1 ? bk : bv);
        __nv_bfloat16* dh = (seg == 0) ? qh : (seg == 1 ? kh : vh);
        __nv_bfloat16* dl = (seg == 0) ? ql : (seg == 1 ? kl : vl);
        const int   ldd = (seg == 0) ? DD : KVD;
        const float sc  = (seg == 0) ? QSCALE : 1.0f;

#pragma unroll
        for (int mi = 0; mi < 4; mi++) {
            int ra = m0 + wm * 64 + mi * 16 + (lane >> 2);
            int rb = ra + 8;
            int sa  = ra & (SS - 1);
            int sbt = rb & (SS - 1);
#pragma unroll
            for (int ni = 0; ni < 8; ni++) {
                int c  = n0 + wn * 64 + ni * 8 + (lane & 3) * 2;
                int cl = c - cbase;
                float b0 = bias[cl], b1 = bias[cl + 1];
                float v0 = acc[mi][ni][0] + b0, v1 = acc[mi][ni][1] + b1;
                float v2 = acc[mi][ni][2] + b0, v3 = acc[mi][ni][3] + b1;
                if (seg < 2) {
                    int p = (c & 127) >> 1;
                    float2 fa = *(const float2*)(fc + ((size_t)(spv + sa)  * 64 + p) * 2);
                    float2 fb = *(const float2*)(fc + ((size_t)(spv + sbt) * 64 + p) * 2);
                    float o0 = (v0 * fa.x - v1 * fa.y) * sc;
                    float o1 = (v0 * fa.y + v1 * fa.x) * sc;
                    float o2 = (v2 * fb.x - v3 * fb.y) * sc;
                    float o3 = (v2 * fb.y + v3 * fb.x) * sc;
                    v0 = o0; v1 = o1; v2 = o2; v3 = o3;
                }
                uint32_t h0 = pack_bf16(v0, v1);
                uint32_t h1 = pack_bf16(v2, v3);
                float f0 = __uint_as_float(h0 << 16), f1 = __uint_as_float(h0 & 0xffff0000u);
                float f2 = __uint_as_float(h1 << 16), f3 = __uint_as_float(h1 & 0xffff0000u);
                uint32_t l0 = pack_bf16(v0 - f0, v1 - f1);
                uint32_t l1 = pack_bf16(v2 - f2, v3 - f3);
                *(uint32_t*)(dh + (size_t)ra * ldd + cl) = h0;
                *(uint32_t*)(dl + (size_t)ra * ldd + cl) = l0;
                *(uint32_t*)(dh + (size_t)rb * ldd + cl) = h1;
                *(uint32_t*)(dl + (size_t)rb * ldd + cl) = l1;
            }
        }
    }
}

// ---------------------------------------------------------------------------
// Tensor-core causal flash attention (unchanged)
// ---------------------------------------------------------------------------
#define AROW     272
#define SQ_SZ    (128 * AROW)
#define KT_SZ    (64 * AROW)
#define STG_KH   0
#define STG_KL   17408
#define STG_VH   34816
#define STG_VL   52224
#define STG_SZ   (4 * KT_SZ)
#define ATT_SMEM (2 * SQ_SZ + 2 * STG_SZ)

__device__ __forceinline__ void att_load_kv(
    uint32_t dst, const __nv_bfloat16* khb, const __nv_bfloat16* klb,
    const __nv_bfloat16* vhb, const __nv_bfloat16* vlb, int n0, int t)
{
#pragma unroll
    for (int i = 0; i < 4; ++i) {
        int id = t + i * 256;
        int r  = id >> 4, c = id & 15;
        uint32_t o  = r * AROW + c * 16;
        size_t   go = (size_t)(n0 + r) * (KVH*HD) + c * 8;
        CP_ASYNC16(dst + STG_KH + o, khb + go);
        CP_ASYNC16(dst + STG_KL + o, klb + go);
        CP_ASYNC16(dst + STG_VH + o, vhb + go);
        CP_ASYNC16(dst + STG_VL + o, vlb + go);
    }
}

__global__ __launch_bounds__(256, 1) void attn_mma(
    const __nv_bfloat16* __restrict__ qh, const __nv_bfloat16* __restrict__ ql,
    const __nv_bfloat16* __restrict__ kh, const __nv_bfloat16* __restrict__ kl,
    const __nv_bfloat16* __restrict__ vh, const __nv_bfloat16* __restrict__ vl,
    __nv_bfloat16* __restrict__ cc)
{
    extern __shared__ char sm[];
    const int b   = blockIdx.z;
    const int h   = blockIdx.y;
    const int mb  = gridDim.x - 1 - blockIdx.x;
    const int m0  = mb * 128;
    const int kvh = h / GROUP;
    const int t    = threadIdx.x;
    const int lane = t & 31;
    const int w    = t >> 5;

    const uint32_t sb   = smem_u32(sm);
    const uint32_t sQh  = sb;
    const uint32_t sQl  = sb + SQ_SZ;
    const uint32_t sStg = sb + 2 * SQ_SZ;

    const __nv_bfloat16* qhb = qh + ((size_t)(b*SS + m0) * QH + h) * HD;
    const __nv_bfloat16* qlb = ql + ((size_t)(b*SS + m0) * QH + h) * HD;
    const __nv_bfloat16* khb = kh + ((size_t)b*SS*KVH + kvh) * HD;
    const __nv_bfloat16* klb = kl + ((size_t)b*SS*KVH + kvh) * HD;
    const __nv_bfloat16* vhb = vh + ((size_t)b*SS*KVH + kvh) * HD;
    const __nv_bfloat16* vlb = vl + ((size_t)b*SS*KVH + kvh) * HD;

#pragma unroll
    for (int i = 0; i < 8; ++i) {
        int id = t + i * 256;
        int r  = id >> 4, c = id & 15;
        uint32_t o  = r * AROW + c * 16;
        size_t   go = (size_t)r * (QH*HD) + c * 8;
        CP_ASYNC16(sQh + o, qhb + go);
        CP_ASYNC16(sQl + o, qlb + go);
    }
    att_load_kv(sStg, khb, klb, vhb, vlb, 0, t);
    CP_COMMIT();
    const int ntiles = 2 * mb + 2;
    if (ntiles > 1) att_load_kv(sStg + STG_SZ, khb, klb, vhb, vlb, 64, t);
    CP_COMMIT();

    const uint32_t qoff = (w * 16 + (lane & 15)) * AROW + ((lane >> 4) << 4);
    const uint32_t koff = (lane & 15) * AROW + ((lane >> 4) << 4);
    const int vrow = (lane & 7) + ((lane >> 4) << 3);
    const uint32_t vcol = ((lane >> 3) & 1) << 4;

    float O[16][4];
#pragma unroll
    for (int i = 0; i < 16; i++)
#pragma unroll
        for (int j = 0; j < 4; j++) O[i][j] = 0.f;
    float mx0 = -INFINITY, mx1 = -INFINITY, l0 = 0.f, l1 = 0.f;

    const int row0 = m0 + w * 16 + (lane >> 2);
    const int row1 = row0 + 8;
    const int wrow_hi = m0 + w * 16 + 15;
    const int wrow_lo = m0 + w * 16;

    for (int it = 0; it < ntiles; ++it) {
        const int n0 = it * 64;
        CP_WAIT(1);
        __syncthreads();
        const uint32_t stg = sStg + (it & 1) * STG_SZ;

        if (n0 <= wrow_hi) {
            float S[8][4];
#pragma unroll
            for (int i = 0; i < 8; i++)
#pragma unroll
                for (int j = 0; j < 4; j++) S[i][j] = 0.f;

#pragma unroll
            for (int ch = 0; ch < 8; ++ch) {
                uint32_t aq[4], al[4];
                LDM_X4(aq[0], aq[1], aq[2], aq[3], sQh + qoff + ch * 32);
                LDM_X4(al[0], al[1], al[2], al[3], sQl + qoff + ch * 32);
#pragma unroll
                for (int p = 0; p < 4; ++p) {
                    uint32_t h0,h1,h2,h3, e0,e1,e2,e3;
                    LDM_X4(h0,h1,h2,h3, stg + STG_KH + koff + p*(16*AROW) + ch*32);
                    LDM_X4(e0,e1,e2,e3, stg + STG_KL + koff + p*(16*AROW) + ch*32);
                    uint32_t bh0[2] = {h0, h2}, bh1[2] = {h1, h3};
                    uint32_t bl0[2] = {e0, e2}, bl1[2] = {e1, e3};
                    MMA16816(S[2*p],   aq, bh0);
                    MMA16816(S[2*p+1], aq, bh1);
                    MMA16816(S[2*p],   al, bh0);
                    MMA16816(S[2*p+1], al, bh1);
                    MMA16816(S[2*p],   aq, bl0);
                    MMA16816(S[2*p+1], aq, bl1);
                }
            }

            if (n0 + 63 > wrow_lo) {
#pragma unroll
                for (int p = 0; p < 8; ++p) {
                    int c = n0 + p * 8 + (lane & 3) * 2;
                    if (c     > row0) S[p][0] = -INFINITY;
                    if (c + 1 > row0) S[p][1] = -INFINITY;
                    if (c     > row1) S[p][2] = -INFINITY;
                    if (c + 1 > row1) S[p][3] = -INFINITY;
                }
            }

            float t0 = -INFINITY, t1 = -INFINITY;
#pragma unroll
            for (int p = 0; p < 8; ++p) {
                t0 = fmaxf(t0, fmaxf(S[p][0], S[p][1]));
                t1 = fmaxf(t1, fmaxf(S[p][2], S[p][3]));
            }
            t0 = fmaxf(t0, __shfl_xor_sync(0xffffffffu, t0, 1));
            t0 = fmaxf(t0, __shfl_xor_sync(0xffffffffu, t0, 2));
            t1 = fmaxf(t1, __shfl_xor_sync(0xffffffffu, t1, 1));
            t1 = fmaxf(t1, __shfl_xor_sync(0xffffffffu, t1, 2));
            float mn0 = fmaxf(mx0, t0), mn1 = fmaxf(mx1, t1);
            float cr0 = ex2f(mx0 - mn0), cr1 = ex2f(mx1 - mn1);
            mx0 = mn0; mx1 = mn1;

            float sa0 = 0.f, sa1 = 0.f;
#pragma unroll
            for (int p = 0; p < 8; ++p) {
                S[p][0] = ex2f(S[p][0] - mn0);
                S[p][1] = ex2f(S[p][1] - mn0);
                S[p][2] = ex2f(S[p][2] - mn1);
                S[p][3] = ex2f(S[p][3] - mn1);
                sa0 += S[p][0] + S[p][1];
                sa1 += S[p][2] + S[p][3];
            }
            sa0 += __shfl_xor_sync(0xffffffffu, sa0, 1);
            sa0 += __shfl_xor_sync(0xffffffffu, sa0, 2);
            sa1 += __shfl_xor_sync(0xffffffffu, sa1, 1);
            sa1 += __shfl_xor_sync(0xffffffffu, sa1, 2);
            l0 = l0 * cr0 + sa0;
            l1 = l1 * cr1 + sa1;

#pragma unroll
            for (int i = 0; i < 16; i++) {
                O[i][0] *= cr0; O[i][1] *= cr0;
                O[i][2] *= cr1; O[i][3] *= cr1;
            }

#pragma unroll
            for (int jc = 0; jc < 4; ++jc) {
                uint32_t ph[4], pl[4];
#pragma unroll
                for (int q2 = 0; q2 < 2; ++q2) {
                    float p0 = S[2*jc + q2][0], p1 = S[2*jc + q2][1];
                    float p2 = S[2*jc + q2][2], p3 = S[2*jc + q2][3];
                    uint32_t hp0 = pack_bf16(p0, p1);
                    uint32_t hp1 = pack_bf16(p2, p3);
                    float f0 = __uint_as_float(hp0 << 16);
                    float f1 = __uint_as_float(hp0 & 0xffff0000u);
                    float f2 = __uint_as_float(hp1 << 16);
                    float f3 = __uint_as_float(hp1 & 0xffff0000u);
                    ph[2*q2]   = hp0;  ph[2*q2+1] = hp1;
                    pl[2*q2]   = pack_bf16(p0 - f0, p1 - f1);
                    pl[2*q2+1] = pack_bf16(p2 - f2, p3 - f3);
                }
                const uint32_t vro = (jc * 16 + vrow) * AROW + vcol;
#pragma unroll
                for (int db = 0; db < 8; ++db) {
                    uint32_t a0,a1,a2,a3, c0,c1,c2,c3;
                    LDM_X4T(a0,a1,a2,a3, stg + STG_VH + vro + db * 32);
                    LDM_X4T(c0,c1,c2,c3, stg + STG_VL + vro + db * 32);
                    uint32_t bh0[2] = {a0, a2}, bh1[2] = {a1, a3};
                    uint32_t bl0[2] = {c0, c2}, bl1[2] = {c1, c3};
                    MMA16816(O[2*db],   ph, bh0);
                    MMA16816(O[2*db+1], ph, bh1);
                    MMA16816(O[2*db],   pl, bh0);
                    MMA16816(O[2*db+1], pl, bh1);
                    MMA16816(O[2*db],   ph, bl0);
                    MMA16816(O[2*db+1], ph, bl1);
                }
            }
        }

        __syncthreads();
        if (it + 2 < ntiles)
            att_load_kv(sStg + (it & 1) * STG_SZ, khb, klb, vhb, vlb, n0 + 128, t);
        CP_COMMIT();
    }

    float inv0 = 1.0f / l0, inv1 = 1.0f / l1;
    const size_t base0 = (size_t)(b * SS + row0) * K3;
    const size_t base1 = (size_t)(b * SS + row1) * K3;
    const int colb = h * 128 + (lane & 3) * 2;
#pragma unroll
    for (int dt = 0; dt < 16; ++dt) {
        int col = colb + dt * 8;
        float v0 = O[dt][0] * inv0, v1 = O[dt][1] * inv0;
        float v2 = O[dt][2] * inv1, v3 = O[dt][3] * inv1;
        uint32_t hi0 = pack_bf16(v0, v1);
        uint32_t hi1 = pack_bf16(v2, v3);
        float f0 = __uint_as_float(hi0 << 16), f1 = __uint_as_float(hi0 & 0xffff0000u);
        float f2 = __uint_as_float(hi1 << 16), f3 = __uint_as_float(hi1 & 0xffff0000u);
        uint32_t lo0 = pack_bf16(v0 - f0, v1 - f1);
        uint32_t lo1 = pack_bf16(v2 - f2, v3 - f3);
        *(uint32_t*)(cc + base0 + col)        = hi0;
        *(uint32_t*)(cc + base0 + DD + col)   = lo0;
        *(uint32_t*)(cc + base0 + 2*DD + col) = hi0;
        *(uint32_t*)(cc + base1 + col)        = hi1;
        *(uint32_t*)(cc + base1 + DD + col)   = lo1;
        *(uint32_t*)(cc + base1 + 2*DD + col) = hi1;
    }
}

// ---------------------------------------------------------------------------
// launch
// ---------------------------------------------------------------------------
extern "C" void kernel_launch(void* const* d_in, const int* in_sizes, int n_in,
                              void* d_out, int out_size)
{
    const float* xs   = (const float*)d_in[0];
    const int*   spos = (const int*)  d_in[1];
    const float* fc   = (const float*)d_in[2];
    const float* Wq   = (const float*)d_in[3];
    const float* bq   = (const float*)d_in[4];
    const float* Wk   = (const float*)d_in[5];
    const float* bk   = (const float*)d_in[6];
    const float* Wv   = (const float*)d_in[7];
    const float* bv   = (const float*)d_in[8];
    const float* Wo   = (const float*)d_in[9];
    const float* bo   = (const float*)d_in[10];
    float* out = (float*)d_out;

    __nv_bfloat16 *xc, *wqkv, *woc, *cc;
    __nv_bfloat16 *qhp, *qlp, *khp, *klp, *vhp, *vlp;
    cudaGetSymbolAddress((void**)&xc,   g_xc);
    cudaGetSymbolAddress((void**)&wqkv, g_wqkv);
    cudaGetSymbolAddress((void**)&woc,  g_woc);
    cudaGetSymbolAddress((void**)&cc,   g_cc);
    cudaGetSymbolAddress((void**)&qhp,  g_qh);
    cudaGetSymbolAddress((void**)&qlp,  g_ql);
    cudaGetSymbolAddress((void**)&khp,  g_kh);
    cudaGetSymbolAddress((void**)&klp,  g_kl);
    cudaGetSymbolAddress((void**)&vhp,  g_vh);
    cudaGetSymbolAddress((void**)&vlp,  g_vl);

    cudaFuncSetAttribute(gemm_mma<0>, cudaFuncAttributeMaxDynamicSharedMemorySize, GSMEM);
    cudaFuncSetAttribute(gemm_mma<1>, cudaFuncAttributeMaxDynamicSharedMemorySize, GSMEM);
    cudaFuncSetAttribute(attn_mma,    cudaFuncAttributeMaxDynamicSharedMemorySize, ATT_SMEM);

    // splits (launches 1-5)
    {
        int n;
        n = TOK*DD/4;  split_bf16_kernel<<<(n+255)/256, 256>>>(xs, xc, DD, n, 0);
        n = DD*DD/4;   split_bf16_kernel<<<(n+255)/256, 256>>>(Wq, wqkv, DD, n, 1);
        n = KVD*DD/4;  split_bf16_kernel<<<(n+255)/256, 256>>>(Wk, wqkv + (size_t)DD*K3, DD, n, 1);
        n = KVD*DD/4;  split_bf16_kernel<<<(n+255)/256, 256>>>(Wv, wqkv + (size_t)(DD+KVD)*K3, DD, n, 1);
        n = DD*DD/4;   split_bf16_kernel<<<(n+255)/256, 256>>>(Wo, woc, DD, n, 1);
    }

    // fused QKV projection + rope + split (launch 6)
    gemm_mma<1><<<dim3(TOK/CTM, NQKV/CTN), 128, GSMEM>>>(
        xc, wqkv, bq, bk, bv, nullptr, 0, fc, spos,
        qhp, qlp, khp, klp, vhp, vlp);

    // attention (launch 7)
    attn_mma<<<dim3(SS/128, QH, BB), 256, ATT_SMEM>>>(qhp, qlp, khp, klp, vhp, vlp, cc);

    // output projection (launch 8)
    gemm_mma<0><<<dim3(TOK/CTM, DD/CTN), 128, GSMEM>>>(
        cc, woc, bo, nullptr, nullptr, out, DD, nullptr, nullptr,
        nullptr, nullptr, nullptr, nullptr, nullptr, nullptr);
}

// round 9
// speedup vs baseline: 1.0460x; 1.0460x over previous
#include <cuda_runtime.h>
#include <cuda_bf16.h>
#include <math.h>
#include <stdint.h>

// Problem constants
#define BB   2
#define SS   2048
#define DD   4096
#define QH   32
#define KVH  8
#define HD   128
#define KVD  (KVH*HD)      // 1024
#define GROUP (QH/KVH)     // 4
#define TOK  (BB*SS)       // 4096
#define K3   (3*DD)        // 12288
#define NQKV (DD + 2*KVD)  // 6144

#define QSCALE (0.08838834764831845f * 1.4426950408889634f)

// ---------------------------------------------------------------------------
// Scratch
// ---------------------------------------------------------------------------
__device__ __align__(16) __nv_bfloat16 g_xc  [TOK*K3];
__device__ __align__(16) __nv_bfloat16 g_wqkv[(size_t)NQKV*K3];
__device__ __align__(16) __nv_bfloat16 g_woc [DD*K3];
__device__ __align__(16) __nv_bfloat16 g_cc  [TOK*K3];

__device__ __align__(16) __nv_bfloat16 g_qh[TOK*DD];
__device__ __align__(16) __nv_bfloat16 g_ql[TOK*DD];
__device__ __align__(16) __nv_bfloat16 g_kh[TOK*KVD];
__device__ __align__(16) __nv_bfloat16 g_kl[TOK*KVD];
__device__ __align__(16) __nv_bfloat16 g_vh[TOK*KVD];
__device__ __align__(16) __nv_bfloat16 g_vl[TOK*KVD];

// ---------------------------------------------------------------------------
// helpers
// ---------------------------------------------------------------------------
__device__ __forceinline__ uint32_t smem_u32(const void* p) {
    uint32_t a;
    asm("{ .reg .u64 t; cvta.to.shared.u64 t, %1; cvt.u32.u64 %0, t; }" : "=r"(a) : "l"(p));
    return a;
}

#define CP_ASYNC16(dst, src) \
    asm volatile("cp.async.cg.shared.global [%0], [%1], 16;" :: "r"(dst), "l"(src))
#define CP_COMMIT()   asm volatile("cp.async.commit_group;" ::: "memory")
#define CP_WAIT(n)    asm volatile("cp.async.wait_group %0;" :: "n"(n) : "memory")

#define LDM_X4(r0, r1, r2, r3, addr) \
    asm volatile("ldmatrix.sync.aligned.m8n8.x4.shared.b16 {%0,%1,%2,%3}, [%4];" \
        : "=r"(r0), "=r"(r1), "=r"(r2), "=r"(r3) : "r"(addr))

#define LDM_X4T(r0, r1, r2, r3, addr) \
    asm volatile("ldmatrix.sync.aligned.m8n8.x4.trans.shared.b16 {%0,%1,%2,%3}, [%4];" \
        : "=r"(r0), "=r"(r1), "=r"(r2), "=r"(r3) : "r"(addr))

#define MMA16816(d, a, b) \
    asm volatile("mma.sync.aligned.m16n8k16.row.col.f32.bf16.bf16.f32 " \
        "{%0,%1,%2,%3},{%4,%5,%6,%7},{%8,%9},{%0,%1,%2,%3};" \
        : "+f"((d)[0]), "+f"((d)[1]), "+f"((d)[2]), "+f"((d)[3]) \
        : "r"((a)[0]), "r"((a)[1]), "r"((a)[2]), "r"((a)[3]), \
          "r"((b)[0]), "r"((b)[1]))

__device__ __forceinline__ uint32_t pack_bf16(float a, float b) {
    uint32_t d;
    asm("cvt.rn.bf16x2.f32 %0, %1, %2;" : "=r"(d) : "f"(b), "f"(a));
    return d;
}
__device__ __forceinline__ float ex2f(float x) {
    float r; asm("ex2.approx.f32 %0, %1;" : "=f"(r) : "f"(x)); return r;
}

// ---------------------------------------------------------------------------
// fp32 -> 3-term bf16 split (concatenated K)
// mode 0 (A-form): [hi | lo | hi]   mode 1 (B-form): [hi | hi | lo]
// ---------------------------------------------------------------------------
__global__ void split_bf16_kernel(const float* __restrict__ in,
                                  __nv_bfloat16* __restrict__ out,
                                  int K, int total4, int mode)
{
    int idx = blockIdx.x * blockDim.x + threadIdx.x;
    if (idx >= total4) return;
    float4 v = ((const float4*)in)[idx];
    int K4 = K >> 2;
    int r  = idx / K4;
    int k  = (idx - r * K4) << 2;
    float vv[4] = {v.x, v.y, v.z, v.w};
    __nv_bfloat16 h[4], l[4];
#pragma unroll
    for (int i = 0; i < 4; i++) {
        h[i] = __float2bfloat16(vv[i]);
        l[i] = __float2bfloat16(vv[i] - __bfloat162float(h[i]));
    }
    __nv_bfloat16* row = out + (size_t)r * (3*K);
    if (mode == 0) {
        *(uint2*)(row + k)       = *(uint2*)h;
        *(uint2*)(row + K + k)   = *(uint2*)l;
        *(uint2*)(row + 2*K + k) = *(uint2*)h;
    } else {
        *(uint2*)(row + k)       = *(uint2*)h;
        *(uint2*)(row + K + k)   = *(uint2*)h;
        *(uint2*)(row + 2*K + k) = *(uint2*)l;
    }
}

// ---------------------------------------------------------------------------
// bf16 MMA GEMM (R7-proven): CTA 128x128, BK=64, 256 threads (8 warps 2mx4n
// of 64x32), 3 stages, occ 2.
// MODE 0: fp32 C = acc + bias (bias in bq)
// MODE 1: fused QKV epilogue: route by column segment, rope q/k, hi/lo split.
// ---------------------------------------------------------------------------
#define CTM   128
#define CTN   128
#define GBK   64
#define NST   3
#define NCH   (K3 / GBK)            // 192
#define ROWB  144                   // 64 bf16 (128B) + 16B pad
#define ATILE (CTM * ROWB)          // 18432
#define BTILE (CTN * ROWB)          // 18432
#define STAGE (ATILE + BTILE)       // 36864
#define GSMEM (NST * STAGE)         // 110592

template<int MODE>
__global__ __launch_bounds__(256, 2) void gemm_mma(
    const __nv_bfloat16* __restrict__ A, const __nv_bfloat16* __restrict__ B,
    const float* __restrict__ bq, const float* __restrict__ bk,
    const float* __restrict__ bv,
    float* __restrict__ C, int N,
    const float* __restrict__ fc, const int* __restrict__ spos,
    __nv_bfloat16* __restrict__ qh, __nv_bfloat16* __restrict__ ql,
    __nv_bfloat16* __restrict__ kh, __nv_bfloat16* __restrict__ kl,
    __nv_bfloat16* __restrict__ vh, __nv_bfloat16* __restrict__ vl)
{
    extern __shared__ char smraw[];
    const int t    = threadIdx.x;
    const int lane = t & 31;
    const int wid  = t >> 5;
    const int wm   = wid & 1;
    const int wn   = wid >> 1;
    const int m0   = blockIdx.x * CTM;
    const int n0   = blockIdx.y * CTN;
    const uint32_t sb = smem_u32(smraw);

    float acc[4][4][4];
#pragma unroll
    for (int i = 0; i < 4; i++)
#pragma unroll
        for (int j = 0; j < 4; j++)
#pragma unroll
            for (int r = 0; r < 4; r++) acc[i][j][r] = 0.f;

    const __nv_bfloat16* gsrc[8];
    uint32_t doff[8];
#pragma unroll
    for (int i = 0; i < 8; i++) {
        int id  = t + (i & 3) * 256;
        int row = id >> 3;
        int c8  = id & 7;
        doff[i] = row * ROWB + c8 * 16 + ((i < 4) ? 0u : (uint32_t)ATILE);
        gsrc[i] = (i < 4)
                ? A + (size_t)(m0 + row) * K3 + c8 * 8
                : B + (size_t)(n0 + row) * K3 + c8 * 8;
    }

#define LOAD_STAGE(st, k0) do {                                        \
    uint32_t base = sb + (st) * STAGE;                                 \
    _Pragma("unroll")                                                  \
    for (int i = 0; i < 8; i++)                                        \
        CP_ASYNC16(base + doff[i], gsrc[i] + (k0));                    \
} while (0)

#pragma unroll
    for (int s = 0; s < NST - 1; s++) {
        LOAD_STAGE(s, s * GBK);
        CP_COMMIT();
    }

    const uint32_t aoffs = (wm * 64 + (lane & 15)) * ROWB + ((lane >> 4) << 4);
    const uint32_t boffs = (wn * 32 + (lane & 15)) * ROWB + ((lane >> 4) << 4);

    int st = 0;
    for (int c = 0; c < NCH; c++) {
        CP_WAIT(1);
        __syncthreads();
        if (c + NST - 1 < NCH) {
            int st2 = st + 2; if (st2 >= NST) st2 -= NST;
            LOAD_STAGE(st2, (c + NST - 1) * GBK);
        }
        CP_COMMIT();

        const uint32_t ab = sb + st * STAGE;
        const uint32_t bb = ab + ATILE;

#pragma unroll
        for (int ks = 0; ks < 4; ks++) {
            uint32_t a[4][4];
            uint32_t bf[4][2];
#pragma unroll
            for (int mi = 0; mi < 4; mi++)
                LDM_X4(a[mi][0], a[mi][1], a[mi][2], a[mi][3],
                       ab + aoffs + mi * 16 * ROWB + ks * 32);
#pragma unroll
            for (int p = 0; p < 2; p++) {
                uint32_t r0, r1, r2, r3;
                LDM_X4(r0, r1, r2, r3, bb + boffs + p * 16 * ROWB + ks * 32);
                bf[2*p][0]   = r0; bf[2*p][1]   = r2;
                bf[2*p+1][0] = r1; bf[2*p+1][1] = r3;
            }
#pragma unroll
            for (int mi = 0; mi < 4; mi++)
#pragma unroll
                for (int ni = 0; ni < 4; ni++)
                    MMA16816(acc[mi][ni], a[mi], bf[ni]);
        }
        if (++st == NST) st = 0;
    }
#undef LOAD_STAGE

    if (MODE == 0) {
#pragma unroll
        for (int mi = 0; mi < 4; mi++) {
            int r0 = m0 + wm * 64 + mi * 16 + (lane >> 2);
#pragma unroll
            for (int ni = 0; ni < 4; ni++) {
                int col = n0 + wn * 32 + ni * 8 + (lane & 3) * 2;
                float2 bv2 = *(const float2*)(bq + col);
                float2 o0 = make_float2(acc[mi][ni][0] + bv2.x, acc[mi][ni][1] + bv2.y);
                float2 o1 = make_float2(acc[mi][ni][2] + bv2.x, acc[mi][ni][3] + bv2.y);
                *(float2*)(C + (size_t)r0 * N + col)       = o0;
                *(float2*)(C + (size_t)(r0 + 8) * N + col) = o1;
            }
        }
    } else {
        const int spv = spos[0];
        int seg, cbase;
        if (n0 < DD)            { seg = 0; cbase = 0; }
        else if (n0 < DD + KVD) { seg = 1; cbase = DD; }
        else                    { seg = 2; cbase = DD + KVD; }
        const float* bias = (seg == 0) ? bq : (seg == 1 ? bk : bv);
        __nv_bfloat16* dh = (seg == 0) ? qh : (seg == 1 ? kh : vh);
        __nv_bfloat16* dl = (seg == 0) ? ql : (seg == 1 ? kl : vl);
        const int   ldd = (seg == 0) ? DD : KVD;
        const float sc  = (seg == 0) ? QSCALE : 1.0f;

#pragma unroll
        for (int mi = 0; mi < 4; mi++) {
            int ra = m0 + wm * 64 + mi * 16 + (lane >> 2);
            int rb = ra + 8;
            int sa  = ra & (SS - 1);
            int sbt = rb & (SS - 1);
#pragma unroll
            for (int ni = 0; ni < 4; ni++) {
                int c  = n0 + wn * 32 + ni * 8 + (lane & 3) * 2;
                int cl = c - cbase;
                float b0 = bias[cl], b1 = bias[cl + 1];
                float v0 = acc[mi][ni][0] + b0, v1 = acc[mi][ni][1] + b1;
                float v2 = acc[mi][ni][2] + b0, v3 = acc[mi][ni][3] + b1;
                if (seg < 2) {
                    int p = (c & 127) >> 1;
                    float2 fa = *(const float2*)(fc + ((size_t)(spv + sa)  * 64 + p) * 2);
                    float2 fb = *(const float2*)(fc + ((size_t)(spv + sbt) * 64 + p) * 2);
                    float o0 = (v0 * fa.x - v1 * fa.y) * sc;
                    float o1 = (v0 * fa.y + v1 * fa.x) * sc;
                    float o2 = (v2 * fb.x - v3 * fb.y) * sc;
                    float o3 = (v2 * fb.y + v3 * fb.x) * sc;
                    v0 = o0; v1 = o1; v2 = o2; v3 = o3;
                }
                uint32_t h0 = pack_bf16(v0, v1);
                uint32_t h1 = pack_bf16(v2, v3);
                float f0 = __uint_as_float(h0 << 16), f1 = __uint_as_float(h0 & 0xffff0000u);
                float f2 = __uint_as_float(h1 << 16), f3 = __uint_as_float(h1 & 0xffff0000u);
                uint32_t l0 = pack_bf16(v0 - f0, v1 - f1);
                uint32_t l1 = pack_bf16(v2 - f2, v3 - f3);
                *(uint32_t*)(dh + (size_t)ra * ldd + cl) = h0;
                *(uint32_t*)(dl + (size_t)ra * ldd + cl) = l0;
                *(uint32_t*)(dh + (size_t)rb * ldd + cl) = h1;
                *(uint32_t*)(dl + (size_t)rb * ldd + cl) = l1;
            }
        }
    }
}

// ---------------------------------------------------------------------------
// Tensor-core causal flash attention.
// Q fragments held in registers (loaded once); 3-stage KV ring (stage 2
// reuses the Q smem region after the one-time register load).
// ---------------------------------------------------------------------------
#define AROW     272
#define SQ_SZ    (128 * AROW)
#define KT_SZ    (64 * AROW)
#define STG_KH   0
#define STG_KL   17408
#define STG_VH   34816
#define STG_VL   52224
#define STG_SZ   (4 * KT_SZ)            // 69632 == 2*SQ_SZ
#define ATT_SMEM (3 * STG_SZ)           // 208896

__device__ __forceinline__ void att_load_kv(
    uint32_t dst, const __nv_bfloat16* khb, const __nv_bfloat16* klb,
    const __nv_bfloat16* vhb, const __nv_bfloat16* vlb, int n0, int t)
{
#pragma unroll
    for (int i = 0; i < 4; ++i) {
        int id = t + i * 256;
        int r  = id >> 4, c = id & 15;
        uint32_t o  = r * AROW + c * 16;
        size_t   go = (size_t)(n0 + r) * (KVH*HD) + c * 8;
        CP_ASYNC16(dst + STG_KH + o, khb + go);
        CP_ASYNC16(dst + STG_KL + o, klb + go);
        CP_ASYNC16(dst + STG_VH + o, vhb + go);
        CP_ASYNC16(dst + STG_VL + o, vlb + go);
    }
}

__global__ __launch_bounds__(256, 1) void attn_mma(
    const __nv_bfloat16* __restrict__ qh, const __nv_bfloat16* __restrict__ ql,
    const __nv_bfloat16* __restrict__ kh, const __nv_bfloat16* __restrict__ kl,
    const __nv_bfloat16* __restrict__ vh, const __nv_bfloat16* __restrict__ vl,
    __nv_bfloat16* __restrict__ cc)
{
    extern __shared__ char sm[];
    const int b   = blockIdx.z;
    const int h   = blockIdx.y;
    const int mb  = gridDim.x - 1 - blockIdx.x;
    const int m0  = mb * 128;
    const int kvh = h / GROUP;
    const int t    = threadIdx.x;
    const int lane = t & 31;
    const int w    = t >> 5;

    const uint32_t sb  = smem_u32(sm);
    const uint32_t sQh = sb + 2 * STG_SZ;          // stage-2 region (temp)
    const uint32_t sQl = sQh + SQ_SZ;

    const __nv_bfloat16* qhb = qh + ((size_t)(b*SS + m0) * QH + h) * HD;
    const __nv_bfloat16* qlb = ql + ((size_t)(b*SS + m0) * QH + h) * HD;
    const __nv_bfloat16* khb = kh + ((size_t)b*SS*KVH + kvh) * HD;
    const __nv_bfloat16* klb = kl + ((size_t)b*SS*KVH + kvh) * HD;
    const __nv_bfloat16* vhb = vh + ((size_t)b*SS*KVH + kvh) * HD;
    const __nv_bfloat16* vlb = vl + ((size_t)b*SS*KVH + kvh) * HD;

    const int ntiles = 2 * mb + 2;

    // group 0: Q + KV tile 0
#pragma unroll
    for (int i = 0; i < 8; ++i) {
        int id = t + i * 256;
        int r  = id >> 4, c = id & 15;
        uint32_t o  = r * AROW + c * 16;
        size_t   go = (size_t)r * (QH*HD) + c * 8;
        CP_ASYNC16(sQh + o, qhb + go);
        CP_ASYNC16(sQl + o, qlb + go);
    }
    att_load_kv(sb, khb, klb, vhb, vlb, 0, t);
    CP_COMMIT();
    // group 1: KV tile 1
    if (ntiles > 1) att_load_kv(sb + STG_SZ, khb, klb, vhb, vlb, 64, t);
    CP_COMMIT();

    const uint32_t qoff = (w * 16 + (lane & 15)) * AROW + ((lane >> 4) << 4);
    const uint32_t koff = (lane & 15) * AROW + ((lane >> 4) << 4);
    const int vrow = (lane & 7) + ((lane >> 4) << 3);
    const uint32_t vcol = ((lane >> 3) & 1) << 4;

    // one-time Q fragment load into registers
    CP_WAIT(1);
    __syncthreads();
    uint32_t Aq[8][4], Al[8][4];
#pragma unroll
    for (int ch = 0; ch < 8; ++ch) {
        LDM_X4(Aq[ch][0], Aq[ch][1], Aq[ch][2], Aq[ch][3], sQh + qoff + ch * 32);
        LDM_X4(Al[ch][0], Al[ch][1], Al[ch][2], Al[ch][3], sQl + qoff + ch * 32);
    }
    __syncthreads();   // all warps done reading Q before stage-2 prefetch
    // group 2: KV tile 2 into the (now free) Q region = stage 2
    if (ntiles > 2) att_load_kv(sb + 2 * STG_SZ, khb, klb, vhb, vlb, 128, t);
    CP_COMMIT();

    float O[16][4];
#pragma unroll
    for (int i = 0; i < 16; i++)
#pragma unroll
        for (int j = 0; j < 4; j++) O[i][j] = 0.f;
    float mx0 = -INFINITY, mx1 = -INFINITY, l0 = 0.f, l1 = 0.f;

    const int row0 = m0 + w * 16 + (lane >> 2);
    const int row1 = row0 + 8;
    const int wrow_hi = m0 + w * 16 + 15;
    const int wrow_lo = m0 + w * 16;

    int st = 0;
    for (int it = 0; it < ntiles; ++it) {
        const int n0 = it * 64;
        CP_WAIT(2);
        __syncthreads();
        const uint32_t stg = sb + st * STG_SZ;

        if (n0 <= wrow_hi) {
            float S[8][4];
#pragma unroll
            for (int i = 0; i < 8; i++)
#pragma unroll
                for (int j = 0; j < 4; j++) S[i][j] = 0.f;

#pragma unroll
            for (int ch = 0; ch < 8; ++ch) {
#pragma unroll
                for (int p = 0; p < 4; ++p) {
                    uint32_t h0,h1,h2,h3, e0,e1,e2,e3;
                    LDM_X4(h0,h1,h2,h3, stg + STG_KH + koff + p*(16*AROW) + ch*32);
                    LDM_X4(e0,e1,e2,e3, stg + STG_KL + koff + p*(16*AROW) + ch*32);
                    uint32_t bh0[2] = {h0, h2}, bh1[2] = {h1, h3};
                    uint32_t bl0[2] = {e0, e2}, bl1[2] = {e1, e3};
                    MMA16816(S[2*p],   Aq[ch], bh0);
                    MMA16816(S[2*p+1], Aq[ch], bh1);
                    MMA16816(S[2*p],   Al[ch], bh0);
                    MMA16816(S[2*p+1], Al[ch], bh1);
                    MMA16816(S[2*p],   Aq[ch], bl0);
                    MMA16816(S[2*p+1], Aq[ch], bl1);
                }
            }

            if (n0 + 63 > wrow_lo) {
#pragma unroll
                for (int p = 0; p < 8; ++p) {
                    int c = n0 + p * 8 + (lane & 3) * 2;
                    if (c     > row0) S[p][0] = -INFINITY;
                    if (c + 1 > row0) S[p][1] = -INFINITY;
                    if (c     > row1) S[p][2] = -INFINITY;
                    if (c + 1 > row1) S[p][3] = -INFINITY;
                }
            }

            float t0 = -INFINITY, t1 = -INFINITY;
#pragma unroll
            for (int p = 0; p < 8; ++p) {
                t0 = fmaxf(t0, fmaxf(S[p][0], S[p][1]));
                t1 = fmaxf(t1, fmaxf(S[p][2], S[p][3]));
            }
            t0 = fmaxf(t0, __shfl_xor_sync(0xffffffffu, t0, 1));
            t0 = fmaxf(t0, __shfl_xor_sync(0xffffffffu, t0, 2));
            t1 = fmaxf(t1, __shfl_xor_sync(0xffffffffu, t1, 1));
            t1 = fmaxf(t1, __shfl_xor_sync(0xffffffffu, t1, 2));
            float mn0 = fmaxf(mx0, t0), mn1 = fmaxf(mx1, t1);
            float cr0 = ex2f(mx0 - mn0), cr1 = ex2f(mx1 - mn1);
            mx0 = mn0; mx1 = mn1;

            float sa0 = 0.f, sa1 = 0.f;
#pragma unroll
            for (int p = 0; p < 8; ++p) {
                S[p][0] = ex2f(S[p][0] - mn0);
                S[p][1] = ex2f(S[p][1] - mn0);
                S[p][2] = ex2f(S[p][2] - mn1);
                S[p][3] = ex2f(S[p][3] - mn1);
                sa0 += S[p][0] + S[p][1];
                sa1 += S[p][2] + S[p][3];
            }
            sa0 += __shfl_xor_sync(0xffffffffu, sa0, 1);
            sa0 += __shfl_xor_sync(0xffffffffu, sa0, 2);
            sa1 += __shfl_xor_sync(0xffffffffu, sa1, 1);
            sa1 += __shfl_xor_sync(0xffffffffu, sa1, 2);
            l0 = l0 * cr0 + sa0;
            l1 = l1 * cr1 + sa1;

#pragma unroll
            for (int i = 0; i < 16; i++) {
                O[i][0] *= cr0; O[i][1] *= cr0;
                O[i][2] *= cr1; O[i][3] *= cr1;
            }

#pragma unroll
            for (int jc = 0; jc < 4; ++jc) {
                uint32_t ph[4], pl[4];
#pragma unroll
                for (int q2 = 0; q2 < 2; ++q2) {
                    float p0 = S[2*jc + q2][0], p1 = S[2*jc + q2][1];
                    float p2 = S[2*jc + q2][2], p3 = S[2*jc + q2][3];
                    uint32_t hp0 = pack_bf16(p0, p1);
                    uint32_t hp1 = pack_bf16(p2, p3);
                    float f0 = __uint_as_float(hp0 << 16);
                    float f1 = __uint_as_float(hp0 & 0xffff0000u);
                    float f2 = __uint_as_float(hp1 << 16);
                    float f3 = __uint_as_float(hp1 & 0xffff0000u);
                    ph[2*q2]   = hp0;  ph[2*q2+1] = hp1;
                    pl[2*q2]   = pack_bf16(p0 - f0, p1 - f1);
                    pl[2*q2+1] = pack_bf16(p2 - f2, p3 - f3);
                }
                const uint32_t vro = (jc * 16 + vrow) * AROW + vcol;
#pragma unroll
                for (int db = 0; db < 8; ++db) {
                    uint32_t a0,a1,a2,a3, c0,c1,c2,c3;
                    LDM_X4T(a0,a1,a2,a3, stg + STG_VH + vro + db * 32);
                    LDM_X4T(c0,c1,c2,c3, stg + STG_VL + vro + db * 32);
                    uint32_t bh0[2] = {a0, a2}, bh1[2] = {a1, a3};
                    uint32_t bl0[2] = {c0, c2}, bl1[2] = {c1, c3};
                    MMA16816(O[2*db],   ph, bh0);
                    MMA16816(O[2*db+1], ph, bh1);
                    MMA16816(O[2*db],   pl, bh0);
                    MMA16816(O[2*db+1], pl, bh1);
                    MMA16816(O[2*db],   ph, bl0);
                    MMA16816(O[2*db+1], ph, bl1);
                }
            }
        }

        __syncthreads();
        if (it + 3 < ntiles)
            att_load_kv(stg, khb, klb, vhb, vlb, (it + 3) * 64, t);
        CP_COMMIT();
        if (++st == 3) st = 0;
    }

    float inv0 = 1.0f / l0, inv1 = 1.0f / l1;
    const size_t base0 = (size_t)(b * SS + row0) * K3;
    const size_t base1 = (size_t)(b * SS + row1) * K3;
    const int colb = h * 128 + (lane & 3) * 2;
#pragma unroll
    for (int dt = 0; dt < 16; ++dt) {
        int col = colb + dt * 8;
        float v0 = O[dt][0] * inv0, v1 = O[dt][1] * inv0;
        float v2 = O[dt][2] * inv1, v3 = O[dt][3] * inv1;
        uint32_t hi0 = pack_bf16(v0, v1);
        uint32_t hi1 = pack_bf16(v2, v3);
        float f0 = __uint_as_float(hi0 << 16), f1 = __uint_as_float(hi0 & 0xffff0000u);
        float f2 = __uint_as_float(hi1 << 16), f3 = __uint_as_float(hi1 & 0xffff0000u);
        uint32_t lo0 = pack_bf16(v0 - f0, v1 - f1);
        uint32_t lo1 = pack_bf16(v2 - f2, v3 - f3);
        *(uint32_t*)(cc + base0 + col)        = hi0;
        *(uint32_t*)(cc + base0 + DD + col)   = lo0;
        *(uint32_t*)(cc + base0 + 2*DD + col) = hi0;
        *(uint32_t*)(cc + base1 + col)        = hi1;
        *(uint32_t*)(cc + base1 + DD + col)   = lo1;
        *(uint32_t*)(cc + base1 + 2*DD + col) = hi1;
    }
}

// ---------------------------------------------------------------------------
// launch
// ---------------------------------------------------------------------------
extern "C" void kernel_launch(void* const* d_in, const int* in_sizes, int n_in,
                              void* d_out, int out_size)
{
    const float* xs   = (const float*)d_in[0];
    const int*   spos = (const int*)  d_in[1];
    const float* fc   = (const float*)d_in[2];
    const float* Wq   = (const float*)d_in[3];
    const float* bq   = (const float*)d_in[4];
    const float* Wk   = (const float*)d_in[5];
    const float* bk   = (const float*)d_in[6];
    const float* Wv   = (const float*)d_in[7];
    const float* bv   = (const float*)d_in[8];
    const float* Wo   = (const float*)d_in[9];
    const float* bo   = (const float*)d_in[10];
    float* out = (float*)d_out;

    __nv_bfloat16 *xc, *wqkv, *woc, *cc;
    __nv_bfloat16 *qhp, *qlp, *khp, *klp, *vhp, *vlp;
    cudaGetSymbolAddress((void**)&xc,   g_xc);
    cudaGetSymbolAddress((void**)&wqkv, g_wqkv);
    cudaGetSymbolAddress((void**)&woc,  g_woc);
    cudaGetSymbolAddress((void**)&cc,   g_cc);
    cudaGetSymbolAddress((void**)&qhp,  g_qh);
    cudaGetSymbolAddress((void**)&qlp,  g_ql);
    cudaGetSymbolAddress((void**)&khp,  g_kh);
    cudaGetSymbolAddress((void**)&klp,  g_kl);
    cudaGetSymbolAddress((void**)&vhp,  g_vh);
    cudaGetSymbolAddress((void**)&vlp,  g_vl);

    cudaFuncSetAttribute(gemm_mma<0>, cudaFuncAttributeMaxDynamicSharedMemorySize, GSMEM);
    cudaFuncSetAttribute(gemm_mma<1>, cudaFuncAttributeMaxDynamicSharedMemorySize, GSMEM);
    cudaFuncSetAttribute(attn_mma,    cudaFuncAttributeMaxDynamicSharedMemorySize, ATT_SMEM);

    // splits (launches 1-5)
    {
        int n;
        n = TOK*DD/4;  split_bf16_kernel<<<(n+255)/256, 256>>>(xs, xc, DD, n, 0);
        n = DD*DD/4;   split_bf16_kernel<<<(n+255)/256, 256>>>(Wq, wqkv, DD, n, 1);
        n = KVD*DD/4;  split_bf16_kernel<<<(n+255)/256, 256>>>(Wk, wqkv + (size_t)DD*K3, DD, n, 1);
        n = KVD*DD/4;  split_bf16_kernel<<<(n+255)/256, 256>>>(Wv, wqkv + (size_t)(DD+KVD)*K3, DD, n, 1);
        n = DD*DD/4;   split_bf16_kernel<<<(n+255)/256, 256>>>(Wo, woc, DD, n, 1);
    }

    // fused QKV projection + rope + split (launch 6)
    gemm_mma<1><<<dim3(TOK/CTM, NQKV/CTN), 256, GSMEM>>>(
        xc, wqkv, bq, bk, bv, nullptr, 0, fc, spos,
        qhp, qlp, khp, klp, vhp, vlp);

    // attention (launch 7)
    attn_mma<<<dim3(SS/128, QH, BB), 256, ATT_SMEM>>>(qhp, qlp, khp, klp, vhp, vlp, cc);

    // output projection (launch 8)
    gemm_mma<0><<<dim3(TOK/CTM, DD/CTN), 256, GSMEM>>>(
        cc, woc, bo, nullptr, nullptr, out, DD, nullptr, nullptr,
        nullptr, nullptr, nullptr, nullptr, nullptr, nullptr);
}

// round 10
// speedup vs baseline: 1.5775x; 1.5082x over previous
#include <cuda_runtime.h>
#include <cuda_fp16.h>
#include <math.h>
#include <stdint.h>

// Problem constants
#define BB   2
#define SS   2048
#define DD   4096
#define QH   32
#define KVH  8
#define HD   128
#define KVD  (KVH*HD)      // 1024
#define GROUP (QH/KVH)     // 4
#define TOK  (BB*SS)       // 4096
#define K2   (2*DD)        // 8192 : A-side split length [hi|lo]
#define NQKV (DD + 2*KVD)  // 6144

#define QSCALE (0.08838834764831845f * 1.4426950408889634f)

// ---------------------------------------------------------------------------
// Scratch
// ---------------------------------------------------------------------------
__device__ __align__(16) __half g_xc  [(size_t)TOK*K2];    // [xh | xl]
__device__ __align__(16) __half g_wqkv[(size_t)NQKV*DD];   // fp16 weights
__device__ __align__(16) __half g_woc [(size_t)DD*DD];
__device__ __align__(16) __half g_cc  [(size_t)TOK*K2];    // ctx [hi | lo]

__device__ __align__(16) __half g_qh[TOK*DD];
__device__ __align__(16) __half g_ql[TOK*DD];
__device__ __align__(16) __half g_kh[TOK*KVD];
__device__ __align__(16) __half g_vh[TOK*KVD];

// ---------------------------------------------------------------------------
// helpers
// ---------------------------------------------------------------------------
__device__ __forceinline__ uint32_t smem_u32(const void* p) {
    uint32_t a;
    asm("{ .reg .u64 t; cvta.to.shared.u64 t, %1; cvt.u32.u64 %0, t; }" : "=r"(a) : "l"(p));
    return a;
}

#define CP_ASYNC16(dst, src) \
    asm volatile("cp.async.cg.shared.global [%0], [%1], 16;" :: "r"(dst), "l"(src))
#define CP_COMMIT()   asm volatile("cp.async.commit_group;" ::: "memory")
#define CP_WAIT(n)    asm volatile("cp.async.wait_group %0;" :: "n"(n) : "memory")

#define LDM_X4(r0, r1, r2, r3, addr) \
    asm volatile("ldmatrix.sync.aligned.m8n8.x4.shared.b16 {%0,%1,%2,%3}, [%4];" \
        : "=r"(r0), "=r"(r1), "=r"(r2), "=r"(r3) : "r"(addr))

#define LDM_X4T(r0, r1, r2, r3, addr) \
    asm volatile("ldmatrix.sync.aligned.m8n8.x4.trans.shared.b16 {%0,%1,%2,%3}, [%4];" \
        : "=r"(r0), "=r"(r1), "=r"(r2), "=r"(r3) : "r"(addr))

#define MMA16816(d, a, b) \
    asm volatile("mma.sync.aligned.m16n8k16.row.col.f32.f16.f16.f32 " \
        "{%0,%1,%2,%3},{%4,%5,%6,%7},{%8,%9},{%0,%1,%2,%3};" \
        : "+f"((d)[0]), "+f"((d)[1]), "+f"((d)[2]), "+f"((d)[3]) \
        : "r"((a)[0]), "r"((a)[1]), "r"((a)[2]), "r"((a)[3]), \
          "r"((b)[0]), "r"((b)[1]))

__device__ __forceinline__ uint32_t pack_f16(float a, float b) {
    __half2 h = __floats2half2_rn(a, b);
    return *reinterpret_cast<uint32_t*>(&h);
}
__device__ __forceinline__ float2 unpack_f16(uint32_t u) {
    __half2 h = *reinterpret_cast<__half2*>(&u);
    return __half22float2(h);
}
__device__ __forceinline__ float ex2f(float x) {
    float r; asm("ex2.approx.f32 %0, %1;" : "=f"(r) : "f"(x)); return r;
}

// ---------------------------------------------------------------------------
// fp32 -> [hi | lo] fp16 split (row length 2K)
// ---------------------------------------------------------------------------
__global__ void split_f16_kernel(const float* __restrict__ in,
                                 __half* __restrict__ out, int K, int total4)
{
    int idx = blockIdx.x * blockDim.x + threadIdx.x;
    if (idx >= total4) return;
    float4 v = ((const float4*)in)[idx];
    int K4 = K >> 2;
    int r  = idx / K4;
    int k  = (idx - r * K4) << 2;
    uint32_t h0 = pack_f16(v.x, v.y);
    uint32_t h1 = pack_f16(v.z, v.w);
    float2 f0 = unpack_f16(h0), f1 = unpack_f16(h1);
    uint32_t l0 = pack_f16(v.x - f0.x, v.y - f0.y);
    uint32_t l1 = pack_f16(v.z - f1.x, v.w - f1.y);
    __half* row = out + (size_t)r * (2*K);
    *(uint2*)(row + k)     = make_uint2(h0, h1);
    *(uint2*)(row + K + k) = make_uint2(l0, l1);
}

// fp32 -> fp16 plain convert
__global__ void conv_f16_kernel(const float* __restrict__ in,
                                __half* __restrict__ out, int total4)
{
    int idx = blockIdx.x * blockDim.x + threadIdx.x;
    if (idx >= total4) return;
    float4 v = ((const float4*)in)[idx];
    ((uint2*)out)[idx] = make_uint2(pack_f16(v.x, v.y), pack_f16(v.z, v.w));
}

// ---------------------------------------------------------------------------
// fp16 MMA GEMM: C = [Ah|Al][M,K2] @ (B[N,DD] wrapped)^T
//   = A_exact @ fp16(B)^T.  CTA 128x128, BK=64, 256 threads (8 warps 2m x 4n),
//   3 stages, occ 2. B k-index wraps mod DD (chunks 64..127 re-read B).
// MODE 0: fp32 C = acc + bias (bias in bq)
// MODE 1: fused QKV epilogue: route by column segment, rope q/k,
//         q -> hi/lo fp16 split; k,v -> single fp16.
// ---------------------------------------------------------------------------
#define CTM   128
#define CTN   128
#define GBK   64
#define NST   3
#define NCH   (K2 / GBK)            // 128
#define ROWB  144                   // 64 fp16 (128B) + 16B pad
#define ATILE (CTM * ROWB)
#define BTILE (CTN * ROWB)
#define STAGE (ATILE + BTILE)       // 36864
#define GSMEM (NST * STAGE)         // 110592

template<int MODE>
__global__ __launch_bounds__(256, 2) void gemm_mma(
    const __half* __restrict__ A, const __half* __restrict__ B,
    const float* __restrict__ bq, const float* __restrict__ bk,
    const float* __restrict__ bv,
    float* __restrict__ C, int N,
    const float* __restrict__ fc, const int* __restrict__ spos,
    __half* __restrict__ qh, __half* __restrict__ ql,
    __half* __restrict__ kh, __half* __restrict__ vh)
{
    extern __shared__ char smraw[];
    const int t    = threadIdx.x;
    const int lane = t & 31;
    const int wid  = t >> 5;
    const int wm   = wid & 1;
    const int wn   = wid >> 1;
    const int m0   = blockIdx.x * CTM;
    const int n0   = blockIdx.y * CTN;
    const uint32_t sb = smem_u32(smraw);

    float acc[4][4][4];
#pragma unroll
    for (int i = 0; i < 4; i++)
#pragma unroll
        for (int j = 0; j < 4; j++)
#pragma unroll
            for (int r = 0; r < 4; r++) acc[i][j][r] = 0.f;

    const __half* gsrc[8];
    uint32_t doff[8];
#pragma unroll
    for (int i = 0; i < 8; i++) {
        int id  = t + (i & 3) * 256;
        int row = id >> 3;
        int c8  = id & 7;
        doff[i] = row * ROWB + c8 * 16 + ((i < 4) ? 0u : (uint32_t)ATILE);
        gsrc[i] = (i < 4)
                ? A + (size_t)(m0 + row) * K2 + c8 * 8
                : B + (size_t)(n0 + row) * DD + c8 * 8;
    }

#define LOAD_STAGE(st, ka, kb) do {                                    \
    uint32_t base = sb + (st) * STAGE;                                 \
    _Pragma("unroll")                                                  \
    for (int i = 0; i < 4; i++)                                        \
        CP_ASYNC16(base + doff[i], gsrc[i] + (ka));                    \
    _Pragma("unroll")                                                  \
    for (int i = 4; i < 8; i++)                                        \
        CP_ASYNC16(base + doff[i], gsrc[i] + (kb));                    \
} while (0)

#pragma unroll
    for (int s = 0; s < NST - 1; s++) {
        LOAD_STAGE(s, s * GBK, s * GBK);
        CP_COMMIT();
    }

    const uint32_t aoffs = (wm * 64 + (lane & 15)) * ROWB + ((lane >> 4) << 4);
    const uint32_t boffs = (wn * 32 + (lane & 15)) * ROWB + ((lane >> 4) << 4);

    int st = 0;
    for (int c = 0; c < NCH; c++) {
        CP_WAIT(1);
        __syncthreads();
        if (c + NST - 1 < NCH) {
            int st2 = st + 2; if (st2 >= NST) st2 -= NST;
            int cn = c + NST - 1;
            LOAD_STAGE(st2, cn * GBK, (cn & 63) * GBK);
        }
        CP_COMMIT();

        const uint32_t ab = sb + st * STAGE;
        const uint32_t bb = ab + ATILE;

#pragma unroll
        for (int ks = 0; ks < 4; ks++) {
            uint32_t a[4][4];
            uint32_t bf[4][2];
#pragma unroll
            for (int mi = 0; mi < 4; mi++)
                LDM_X4(a[mi][0], a[mi][1], a[mi][2], a[mi][3],
                       ab + aoffs + mi * 16 * ROWB + ks * 32);
#pragma unroll
            for (int p = 0; p < 2; p++) {
                uint32_t r0, r1, r2, r3;
                LDM_X4(r0, r1, r2, r3, bb + boffs + p * 16 * ROWB + ks * 32);
                bf[2*p][0]   = r0; bf[2*p][1]   = r2;
                bf[2*p+1][0] = r1; bf[2*p+1][1] = r3;
            }
#pragma unroll
            for (int mi = 0; mi < 4; mi++)
#pragma unroll
                for (int ni = 0; ni < 4; ni++)
                    MMA16816(acc[mi][ni], a[mi], bf[ni]);
        }
        if (++st == NST) st = 0;
    }
#undef LOAD_STAGE

    if (MODE == 0) {
#pragma unroll
        for (int mi = 0; mi < 4; mi++) {
            int r0 = m0 + wm * 64 + mi * 16 + (lane >> 2);
#pragma unroll
            for (int ni = 0; ni < 4; ni++) {
                int col = n0 + wn * 32 + ni * 8 + (lane & 3) * 2;
                float2 bv2 = *(const float2*)(bq + col);
                float2 o0 = make_float2(acc[mi][ni][0] + bv2.x, acc[mi][ni][1] + bv2.y);
                float2 o1 = make_float2(acc[mi][ni][2] + bv2.x, acc[mi][ni][3] + bv2.y);
                *(float2*)(C + (size_t)r0 * N + col)       = o0;
                *(float2*)(C + (size_t)(r0 + 8) * N + col) = o1;
            }
        }
    } else {
        const int spv = spos[0];
        int seg, cbase;
        if (n0 < DD)            { seg = 0; cbase = 0; }
        else if (n0 < DD + KVD) { seg = 1; cbase = DD; }
        else                    { seg = 2; cbase = DD + KVD; }
        const float* bias = (seg == 0) ? bq : (seg == 1 ? bk : bv);
        __half* dh = (seg == 0) ? qh : (seg == 1 ? kh : vh);
        const int   ldd = (seg == 0) ? DD : KVD;
        const float sc  = (seg == 0) ? QSCALE : 1.0f;

#pragma unroll
        for (int mi = 0; mi < 4; mi++) {
            int ra = m0 + wm * 64 + mi * 16 + (lane >> 2);
            int rb = ra + 8;
            int sa  = ra & (SS - 1);
            int sbt = rb & (SS - 1);
#pragma unroll
            for (int ni = 0; ni < 4; ni++) {
                int c  = n0 + wn * 32 + ni * 8 + (lane & 3) * 2;
                int cl = c - cbase;
                float b0 = bias[cl], b1 = bias[cl + 1];
                float v0 = acc[mi][ni][0] + b0, v1 = acc[mi][ni][1] + b1;
                float v2 = acc[mi][ni][2] + b0, v3 = acc[mi][ni][3] + b1;
                if (seg < 2) {
                    int p = (c & 127) >> 1;
                    float2 fa = *(const float2*)(fc + ((size_t)(spv + sa)  * 64 + p) * 2);
                    float2 fb = *(const float2*)(fc + ((size_t)(spv + sbt) * 64 + p) * 2);
                    float o0 = (v0 * fa.x - v1 * fa.y) * sc;
                    float o1 = (v0 * fa.y + v1 * fa.x) * sc;
                    float o2 = (v2 * fb.x - v3 * fb.y) * sc;
                    float o3 = (v2 * fb.y + v3 * fb.x) * sc;
                    v0 = o0; v1 = o1; v2 = o2; v3 = o3;
                }
                uint32_t h0 = pack_f16(v0, v1);
                uint32_t h1 = pack_f16(v2, v3);
                *(uint32_t*)(dh + (size_t)ra * ldd + cl) = h0;
                *(uint32_t*)(dh + (size_t)rb * ldd + cl) = h1;
                if (seg == 0) {
                    float2 f0 = unpack_f16(h0), f1 = unpack_f16(h1);
                    *(uint32_t*)(ql + (size_t)ra * ldd + cl) = pack_f16(v0 - f0.x, v1 - f0.y);
                    *(uint32_t*)(ql + (size_t)rb * ldd + cl) = pack_f16(v2 - f1.x, v3 - f1.y);
                }
            }
        }
    }
}

// ---------------------------------------------------------------------------
// Tensor-core causal flash attention, fp16.
// Q (hi+lo) in registers; K,V single fp16; 4-stage KV ring.
// S = (qh+ql)kh ; O = (ph+pl)vh.
// ---------------------------------------------------------------------------
#define AROW     272
#define SQ_SZ    (128 * AROW)           // 34816
#define KT_SZ    (64 * AROW)            // 17408
#define STG_VH   KT_SZ
#define STG_SZ   (2 * KT_SZ)            // 34816
#define ATT_NST  4
#define ATT_SMEM (ATT_NST * STG_SZ)     // 139264

__device__ __forceinline__ void att_load_kv(
    uint32_t dst, const __half* khb, const __half* vhb, int n0, int t)
{
#pragma unroll
    for (int i = 0; i < 4; ++i) {
        int id = t + i * 256;
        int r  = id >> 4, c = id & 15;
        uint32_t o  = r * AROW + c * 16;
        size_t   go = (size_t)(n0 + r) * KVD + c * 8;
        CP_ASYNC16(dst + o, khb + go);
        CP_ASYNC16(dst + STG_VH + o, vhb + go);
    }
}

__global__ __launch_bounds__(256, 1) void attn_mma(
    const __half* __restrict__ qh, const __half* __restrict__ ql,
    const __half* __restrict__ kh, const __half* __restrict__ vh,
    __half* __restrict__ cc)
{
    extern __shared__ char sm[];
    const int b   = blockIdx.z;
    const int h   = blockIdx.y;
    const int mb  = gridDim.x - 1 - blockIdx.x;
    const int m0  = mb * 128;
    const int kvh = h / GROUP;
    const int t    = threadIdx.x;
    const int lane = t & 31;
    const int w    = t >> 5;

    const uint32_t sb  = smem_u32(sm);
    const uint32_t sQh = sb + 2 * STG_SZ;        // temp in stages 2-3
    const uint32_t sQl = sb + 3 * STG_SZ;

    const __half* qhb = qh + ((size_t)(b*SS + m0) * QH + h) * HD;
    const __half* qlb = ql + ((size_t)(b*SS + m0) * QH + h) * HD;
    const __half* khb = kh + ((size_t)b*SS*KVH + kvh) * HD;
    const __half* vhb = vh + ((size_t)b*SS*KVH + kvh) * HD;

    const int ntiles = 2 * mb + 2;

    // group 0: Q + kv0
#pragma unroll
    for (int i = 0; i < 8; ++i) {
        int id = t + i * 256;
        int r  = id >> 4, c = id & 15;
        uint32_t o  = r * AROW + c * 16;
        size_t   go = (size_t)r * (QH*HD) + c * 8;
        CP_ASYNC16(sQh + o, qhb + go);
        CP_ASYNC16(sQl + o, qlb + go);
    }
    att_load_kv(sb, khb, vhb, 0, t);
    CP_COMMIT();
    // group 1: kv1
    if (ntiles > 1) att_load_kv(sb + STG_SZ, khb, vhb, 64, t);
    CP_COMMIT();

    const uint32_t qoff = (w * 16 + (lane & 15)) * AROW + ((lane >> 4) << 4);
    const uint32_t koff = (lane & 15) * AROW + ((lane >> 4) << 4);
    const int vrow = (lane & 7) + ((lane >> 4) << 3);
    const uint32_t vcol = ((lane >> 3) & 1) << 4;

    // one-time Q fragment load
    CP_WAIT(1);
    __syncthreads();
    uint32_t Aq[8][4], Al[8][4];
#pragma unroll
    for (int ch = 0; ch < 8; ++ch) {
        LDM_X4(Aq[ch][0], Aq[ch][1], Aq[ch][2], Aq[ch][3], sQh + qoff + ch * 32);
        LDM_X4(Al[ch][0], Al[ch][1], Al[ch][2], Al[ch][3], sQl + qoff + ch * 32);
    }
    __syncthreads();
    // groups 2,3: kv2, kv3 into stages 2,3 (Q region now free)
    if (ntiles > 2) att_load_kv(sb + 2 * STG_SZ, khb, vhb, 128, t);
    CP_COMMIT();
    if (ntiles > 3) att_load_kv(sb + 3 * STG_SZ, khb, vhb, 192, t);
    CP_COMMIT();

    float O[16][4];
#pragma unroll
    for (int i = 0; i < 16; i++)
#pragma unroll
        for (int j = 0; j < 4; j++) O[i][j] = 0.f;
    float mx0 = -INFINITY, mx1 = -INFINITY, l0 = 0.f, l1 = 0.f;

    const int row0 = m0 + w * 16 + (lane >> 2);
    const int row1 = row0 + 8;
    const int wrow_hi = m0 + w * 16 + 15;
    const int wrow_lo = m0 + w * 16;

    for (int it = 0; it < ntiles; ++it) {
        const int n0 = it * 64;
        CP_WAIT(3);
        __syncthreads();
        const uint32_t stg = sb + (it & 3) * STG_SZ;

        if (n0 <= wrow_hi) {
            float S[8][4];
#pragma unroll
            for (int i = 0; i < 8; i++)
#pragma unroll
                for (int j = 0; j < 4; j++) S[i][j] = 0.f;

#pragma unroll
            for (int ch = 0; ch < 8; ++ch) {
#pragma unroll
                for (int p = 0; p < 4; ++p) {
                    uint32_t h0,h1,h2,h3;
                    LDM_X4(h0,h1,h2,h3, stg + koff + p*(16*AROW) + ch*32);
                    uint32_t bh0[2] = {h0, h2}, bh1[2] = {h1, h3};
                    MMA16816(S[2*p],   Aq[ch], bh0);
                    MMA16816(S[2*p+1], Aq[ch], bh1);
                    MMA16816(S[2*p],   Al[ch], bh0);
                    MMA16816(S[2*p+1], Al[ch], bh1);
                }
            }

            if (n0 + 63 > wrow_lo) {
#pragma unroll
                for (int p = 0; p < 8; ++p) {
                    int c = n0 + p * 8 + (lane & 3) * 2;
                    if (c     > row0) S[p][0] = -INFINITY;
                    if (c + 1 > row0) S[p][1] = -INFINITY;
                    if (c     > row1) S[p][2] = -INFINITY;
                    if (c + 1 > row1) S[p][3] = -INFINITY;
                }
            }

            float t0 = -INFINITY, t1 = -INFINITY;
#pragma unroll
            for (int p = 0; p < 8; ++p) {
                t0 = fmaxf(t0, fmaxf(S[p][0], S[p][1]));
                t1 = fmaxf(t1, fmaxf(S[p][2], S[p][3]));
            }
            t0 = fmaxf(t0, __shfl_xor_sync(0xffffffffu, t0, 1));
            t0 = fmaxf(t0, __shfl_xor_sync(0xffffffffu, t0, 2));
            t1 = fmaxf(t1, __shfl_xor_sync(0xffffffffu, t1, 1));
            t1 = fmaxf(t1, __shfl_xor_sync(0xffffffffu, t1, 2));
            float mn0 = fmaxf(mx0, t0), mn1 = fmaxf(mx1, t1);
            float cr0 = ex2f(mx0 - mn0), cr1 = ex2f(mx1 - mn1);
            mx0 = mn0; mx1 = mn1;

            float sa0 = 0.f, sa1 = 0.f;
#pragma unroll
            for (int p = 0; p < 8; ++p) {
                S[p][0] = ex2f(S[p][0] - mn0);
                S[p][1] = ex2f(S[p][1] - mn0);
                S[p][2] = ex2f(S[p][2] - mn1);
                S[p][3] = ex2f(S[p][3] - mn1);
                sa0 += S[p][0] + S[p][1];
                sa1 += S[p][2] + S[p][3];
            }
            sa0 += __shfl_xor_sync(0xffffffffu, sa0, 1);
            sa0 += __shfl_xor_sync(0xffffffffu, sa0, 2);
            sa1 += __shfl_xor_sync(0xffffffffu, sa1, 1);
            sa1 += __shfl_xor_sync(0xffffffffu, sa1, 2);
            l0 = l0 * cr0 + sa0;
            l1 = l1 * cr1 + sa1;

#pragma unroll
            for (int i = 0; i < 16; i++) {
                O[i][0] *= cr0; O[i][1] *= cr0;
                O[i][2] *= cr1; O[i][3] *= cr1;
            }

#pragma unroll
            for (int jc = 0; jc < 4; ++jc) {
                uint32_t ph[4], pl[4];
#pragma unroll
                for (int q2 = 0; q2 < 2; ++q2) {
                    float p0 = S[2*jc + q2][0], p1 = S[2*jc + q2][1];
                    float p2 = S[2*jc + q2][2], p3 = S[2*jc + q2][3];
                    uint32_t hp0 = pack_f16(p0, p1);
                    uint32_t hp1 = pack_f16(p2, p3);
                    float2 f0 = unpack_f16(hp0), f1 = unpack_f16(hp1);
                    ph[2*q2]   = hp0;  ph[2*q2+1] = hp1;
                    pl[2*q2]   = pack_f16(p0 - f0.x, p1 - f0.y);
                    pl[2*q2+1] = pack_f16(p2 - f1.x, p3 - f1.y);
                }
                const uint32_t vro = (jc * 16 + vrow) * AROW + vcol;
#pragma unroll
                for (int db = 0; db < 8; ++db) {
                    uint32_t a0,a1,a2,a3;
                    LDM_X4T(a0,a1,a2,a3, stg + STG_VH + vro + db * 32);
                    uint32_t bh0[2] = {a0, a2}, bh1[2] = {a1, a3};
                    MMA16816(O[2*db],   ph, bh0);
                    MMA16816(O[2*db+1], ph, bh1);
                    MMA16816(O[2*db],   pl, bh0);
                    MMA16816(O[2*db+1], pl, bh1);
                }
            }
        }

        __syncthreads();
        if (it + ATT_NST < ntiles)
            att_load_kv(stg, khb, vhb, (it + ATT_NST) * 64, t);
        CP_COMMIT();
    }

    // normalize + [hi|lo] fp16 write to cc (row length K2)
    float inv0 = 1.0f / l0, inv1 = 1.0f / l1;
    const size_t base0 = (size_t)(b * SS + row0) * K2;
    const size_t base1 = (size_t)(b * SS + row1) * K2;
    const int colb = h * 128 + (lane & 3) * 2;
#pragma unroll
    for (int dt = 0; dt < 16; ++dt) {
        int col = colb + dt * 8;
        float v0 = O[dt][0] * inv0, v1 = O[dt][1] * inv0;
        float v2 = O[dt][2] * inv1, v3 = O[dt][3] * inv1;
        uint32_t hi0 = pack_f16(v0, v1);
        uint32_t hi1 = pack_f16(v2, v3);
        float2 f0 = unpack_f16(hi0), f1 = unpack_f16(hi1);
        uint32_t lo0 = pack_f16(v0 - f0.x, v1 - f0.y);
        uint32_t lo1 = pack_f16(v2 - f1.x, v3 - f1.y);
        *(uint32_t*)(cc + base0 + col)      = hi0;
        *(uint32_t*)(cc + base0 + DD + col) = lo0;
        *(uint32_t*)(cc + base1 + col)      = hi1;
        *(uint32_t*)(cc + base1 + DD + col) = lo1;
    }
}

// ---------------------------------------------------------------------------
// launch
// ---------------------------------------------------------------------------
extern "C" void kernel_launch(void* const* d_in, const int* in_sizes, int n_in,
                              void* d_out, int out_size)
{
    const float* xs   = (const float*)d_in[0];
    const int*   spos = (const int*)  d_in[1];
    const float* fc   = (const float*)d_in[2];
    const float* Wq   = (const float*)d_in[3];
    const float* bq   = (const float*)d_in[4];
    const float* Wk   = (const float*)d_in[5];
    const float* bk   = (const float*)d_in[6];
    const float* Wv   = (const float*)d_in[7];
    const float* bv   = (const float*)d_in[8];
    const float* Wo   = (const float*)d_in[9];
    const float* bo   = (const float*)d_in[10];
    float* out = (float*)d_out;

    __half *xc, *wqkv, *woc, *cc, *qhp, *qlp, *khp, *vhp;
    cudaGetSymbolAddress((void**)&xc,   g_xc);
    cudaGetSymbolAddress((void**)&wqkv, g_wqkv);
    cudaGetSymbolAddress((void**)&woc,  g_woc);
    cudaGetSymbolAddress((void**)&cc,   g_cc);
    cudaGetSymbolAddress((void**)&qhp,  g_qh);
    cudaGetSymbolAddress((void**)&qlp,  g_ql);
    cudaGetSymbolAddress((void**)&khp,  g_kh);
    cudaGetSymbolAddress((void**)&vhp,  g_vh);

    cudaFuncSetAttribute(gemm_mma<0>, cudaFuncAttributeMaxDynamicSharedMemorySize, GSMEM);
    cudaFuncSetAttribute(gemm_mma<1>, cudaFuncAttributeMaxDynamicSharedMemorySize, GSMEM);
    cudaFuncSetAttribute(attn_mma,    cudaFuncAttributeMaxDynamicSharedMemorySize, ATT_SMEM);

    // conversions (launches 1-5)
    {
        int n;
        n = TOK*DD/4;  split_f16_kernel<<<(n+255)/256, 256>>>(xs, xc, DD, n);
        n = DD*DD/4;   conv_f16_kernel<<<(n+255)/256, 256>>>(Wq, wqkv, n);
        n = KVD*DD/4;  conv_f16_kernel<<<(n+255)/256, 256>>>(Wk, wqkv + (size_t)DD*DD, n);
        n = KVD*DD/4;  conv_f16_kernel<<<(n+255)/256, 256>>>(Wv, wqkv + (size_t)(DD+KVD)*DD, n);
        n = DD*DD/4;   conv_f16_kernel<<<(n+255)/256, 256>>>(Wo, woc, n);
    }

    // fused QKV projection + rope + split (launch 6)
    gemm_mma<1><<<dim3(TOK/CTM, NQKV/CTN), 256, GSMEM>>>(
        xc, wqkv, bq, bk, bv, nullptr, 0, fc, spos,
        qhp, qlp, khp, vhp);

    // attention (launch 7)
    attn_mma<<<dim3(SS/128, QH, BB), 256, ATT_SMEM>>>(qhp, qlp, khp, vhp, cc);

    // output projection (launch 8)
    gemm_mma<0><<<dim3(TOK/CTM, DD/CTN), 256, GSMEM>>>(
        cc, woc, bo, nullptr, nullptr, out, DD, nullptr, nullptr,
        nullptr, nullptr, nullptr, nullptr);
}

// round 11
// speedup vs baseline: 1.6516x; 1.0470x over previous
#include <cuda_runtime.h>
#include <cuda_fp16.h>
#include <math.h>
#include <stdint.h>

// Problem constants
#define BB   2
#define SS   2048
#define DD   4096
#define QH   32
#define KVH  8
#define HD   128
#define KVD  (KVH*HD)      // 1024
#define GROUP (QH/KVH)     // 4
#define TOK  (BB*SS)       // 4096
#define K2   (2*DD)        // 8192 : A-side split length [hi|lo]
#define NQKV (DD + 2*KVD)  // 6144

#define QSCALE (0.08838834764831845f * 1.4426950408889634f)

// ---------------------------------------------------------------------------
// Scratch
// ---------------------------------------------------------------------------
__device__ __align__(16) __half g_xc  [(size_t)TOK*K2];    // [xh | xl]
__device__ __align__(16) __half g_wqkv[(size_t)NQKV*DD];   // fp16 weights
__device__ __align__(16) __half g_woc [(size_t)DD*DD];
__device__ __align__(16) __half g_cc  [(size_t)TOK*K2];    // ctx [hi | lo]

__device__ __align__(16) __half g_qh[TOK*DD];
__device__ __align__(16) __half g_ql[TOK*DD];
__device__ __align__(16) __half g_kh[TOK*KVD];
__device__ __align__(16) __half g_vh[TOK*KVD];

// ---------------------------------------------------------------------------
// helpers
// ---------------------------------------------------------------------------
__device__ __forceinline__ uint32_t smem_u32(const void* p) {
    uint32_t a;
    asm("{ .reg .u64 t; cvta.to.shared.u64 t, %1; cvt.u32.u64 %0, t; }" : "=r"(a) : "l"(p));
    return a;
}

#define CP_ASYNC16(dst, src) \
    asm volatile("cp.async.cg.shared.global [%0], [%1], 16;" :: "r"(dst), "l"(src))
#define CP_COMMIT()   asm volatile("cp.async.commit_group;" ::: "memory")
#define CP_WAIT(n)    asm volatile("cp.async.wait_group %0;" :: "n"(n) : "memory")

#define LDM_X4(r0, r1, r2, r3, addr) \
    asm volatile("ldmatrix.sync.aligned.m8n8.x4.shared.b16 {%0,%1,%2,%3}, [%4];" \
        : "=r"(r0), "=r"(r1), "=r"(r2), "=r"(r3) : "r"(addr))

#define LDM_X4T(r0, r1, r2, r3, addr) \
    asm volatile("ldmatrix.sync.aligned.m8n8.x4.trans.shared.b16 {%0,%1,%2,%3}, [%4];" \
        : "=r"(r0), "=r"(r1), "=r"(r2), "=r"(r3) : "r"(addr))

#define MMA16816(d, a, b) \
    asm volatile("mma.sync.aligned.m16n8k16.row.col.f32.f16.f16.f32 " \
        "{%0,%1,%2,%3},{%4,%5,%6,%7},{%8,%9},{%0,%1,%2,%3};" \
        : "+f"((d)[0]), "+f"((d)[1]), "+f"((d)[2]), "+f"((d)[3]) \
        : "r"((a)[0]), "r"((a)[1]), "r"((a)[2]), "r"((a)[3]), \
          "r"((b)[0]), "r"((b)[1]))

__device__ __forceinline__ uint32_t pack_f16(float a, float b) {
    __half2 h = __floats2half2_rn(a, b);
    return *reinterpret_cast<uint32_t*>(&h);
}
__device__ __forceinline__ float2 unpack_f16(uint32_t u) {
    __half2 h = *reinterpret_cast<__half2*>(&u);
    return __half22float2(h);
}
__device__ __forceinline__ float ex2f(float x) {
    float r; asm("ex2.approx.f32 %0, %1;" : "=f"(r) : "f"(x)); return r;
}

// ---------------------------------------------------------------------------
// fp32 -> [hi | lo] fp16 split (row length 2K)
// ---------------------------------------------------------------------------
__global__ void split_f16_kernel(const float* __restrict__ in,
                                 __half* __restrict__ out, int K, int total4)
{
    int idx = blockIdx.x * blockDim.x + threadIdx.x;
    if (idx >= total4) return;
    float4 v = ((const float4*)in)[idx];
    int K4 = K >> 2;
    int r  = idx / K4;
    int k  = (idx - r * K4) << 2;
    uint32_t h0 = pack_f16(v.x, v.y);
    uint32_t h1 = pack_f16(v.z, v.w);
    float2 f0 = unpack_f16(h0), f1 = unpack_f16(h1);
    uint32_t l0 = pack_f16(v.x - f0.x, v.y - f0.y);
    uint32_t l1 = pack_f16(v.z - f1.x, v.w - f1.y);
    __half* row = out + (size_t)r * (2*K);
    *(uint2*)(row + k)     = make_uint2(h0, h1);
    *(uint2*)(row + K + k) = make_uint2(l0, l1);
}

// fp32 -> fp16 plain convert
__global__ void conv_f16_kernel(const float* __restrict__ in,
                                __half* __restrict__ out, int total4)
{
    int idx = blockIdx.x * blockDim.x + threadIdx.x;
    if (idx >= total4) return;
    float4 v = ((const float4*)in)[idx];
    ((uint2*)out)[idx] = make_uint2(pack_f16(v.x, v.y), pack_f16(v.z, v.w));
}

// ---------------------------------------------------------------------------
// fp16 MMA GEMM, shared-B one-pass: C = (Ah + Al)[M,DD] @ fp16(B)[N,DD]^T
// Per K-chunk the B tile is loaded/LDSM'd ONCE and consumed by both A passes.
// CTA 128x128, BK=64, 256 threads (8 warps 2m x 4n), 2 stages, occ 2.
// MODE 0: fp32 C = acc + bias (bias in bq)
// MODE 1: fused QKV epilogue: route by column segment, rope q/k,
//         q -> hi/lo fp16 split; k,v -> single fp16.
// ---------------------------------------------------------------------------
#define CTM   128
#define CTN   128
#define GBK   64
#define NST   2
#define NCH   (DD / GBK)            // 64
#define ROWB  144                   // 64 fp16 (128B) + 16B pad
#define TILE  (128 * ROWB)          // 18432
#define STAGE (3 * TILE)            // 55296 : [Ah | Al | B]
#define GSMEM (NST * STAGE)         // 110592

template<int MODE>
__global__ __launch_bounds__(256, 2) void gemm_mma(
    const __half* __restrict__ A, const __half* __restrict__ B,
    const float* __restrict__ bq, const float* __restrict__ bk,
    const float* __restrict__ bv,
    float* __restrict__ C, int N,
    const float* __restrict__ fc, const int* __restrict__ spos,
    __half* __restrict__ qh, __half* __restrict__ ql,
    __half* __restrict__ kh, __half* __restrict__ vh)
{
    extern __shared__ char smraw[];
    const int t    = threadIdx.x;
    const int lane = t & 31;
    const int wid  = t >> 5;
    const int wm   = wid & 1;
    const int wn   = wid >> 1;
    const int m0   = blockIdx.x * CTM;
    const int n0   = blockIdx.y * CTN;
    const uint32_t sb = smem_u32(smraw);

    float acc[4][4][4];
#pragma unroll
    for (int i = 0; i < 4; i++)
#pragma unroll
        for (int j = 0; j < 4; j++)
#pragma unroll
            for (int r = 0; r < 4; r++) acc[i][j][r] = 0.f;

    // per-thread cp.async mapping: each tile = 1024 16B chunks; 4 per thread.
    // chunk id = t + i*256 (i<4): row = id>>3, c8 = id&7.
    const __half* Ahs[4];
    const __half* Bs[4];
    uint32_t doff[4];
#pragma unroll
    for (int i = 0; i < 4; i++) {
        int id  = t + i * 256;
        int row = id >> 3;
        int c8  = id & 7;
        doff[i] = row * ROWB + c8 * 16;
        Ahs[i]  = A + (size_t)(m0 + row) * K2 + c8 * 8;
        Bs[i]   = B + (size_t)(n0 + row) * DD + c8 * 8;
    }

#define LOAD_STAGE(st, k0) do {                                        \
    uint32_t base = sb + (st) * STAGE;                                 \
    _Pragma("unroll")                                                  \
    for (int i = 0; i < 4; i++)                                        \
        CP_ASYNC16(base + doff[i], Ahs[i] + (k0));                     \
    _Pragma("unroll")                                                  \
    for (int i = 0; i < 4; i++)                                        \
        CP_ASYNC16(base + TILE + doff[i], Ahs[i] + DD + (k0));         \
    _Pragma("unroll")                                                  \
    for (int i = 0; i < 4; i++)                                        \
        CP_ASYNC16(base + 2 * TILE + doff[i], Bs[i] + (k0));           \
} while (0)

    LOAD_STAGE(0, 0);
    CP_COMMIT();

    const uint32_t aoffs = (wm * 64 + (lane & 15)) * ROWB + ((lane >> 4) << 4);
    const uint32_t boffs = (wn * 32 + (lane & 15)) * ROWB + ((lane >> 4) << 4);

    for (int c = 0; c < NCH; c++) {
        const int st = c & 1;
        CP_WAIT(0);
        __syncthreads();
        if (c + 1 < NCH) {
            LOAD_STAGE(st ^ 1, (c + 1) * GBK);
            CP_COMMIT();
        }

        const uint32_t ab  = sb + st * STAGE;        // Ah
        const uint32_t ab2 = ab + TILE;              // Al
        const uint32_t bb  = ab + 2 * TILE;          // B

#pragma unroll
        for (int ks = 0; ks < 4; ks++) {
            uint32_t a[4][4], a2[4][4];
            uint32_t bf[4][2];
#pragma unroll
            for (int mi = 0; mi < 4; mi++) {
                LDM_X4(a[mi][0], a[mi][1], a[mi][2], a[mi][3],
                       ab + aoffs + mi * 16 * ROWB + ks * 32);
                LDM_X4(a2[mi][0], a2[mi][1], a2[mi][2], a2[mi][3],
                       ab2 + aoffs + mi * 16 * ROWB + ks * 32);
            }
#pragma unroll
            for (int p = 0; p < 2; p++) {
                uint32_t r0, r1, r2, r3;
                LDM_X4(r0, r1, r2, r3, bb + boffs + p * 16 * ROWB + ks * 32);
                bf[2*p][0]   = r0; bf[2*p][1]   = r2;
                bf[2*p+1][0] = r1; bf[2*p+1][1] = r3;
            }
#pragma unroll
            for (int mi = 0; mi < 4; mi++)
#pragma unroll
                for (int ni = 0; ni < 4; ni++) {
                    MMA16816(acc[mi][ni], a[mi],  bf[ni]);
                    MMA16816(acc[mi][ni], a2[mi], bf[ni]);
                }
        }
    }
#undef LOAD_STAGE

    if (MODE == 0) {
#pragma unroll
        for (int mi = 0; mi < 4; mi++) {
            int r0 = m0 + wm * 64 + mi * 16 + (lane >> 2);
#pragma unroll
            for (int ni = 0; ni < 4; ni++) {
                int col = n0 + wn * 32 + ni * 8 + (lane & 3) * 2;
                float2 bv2 = *(const float2*)(bq + col);
                float2 o0 = make_float2(acc[mi][ni][0] + bv2.x, acc[mi][ni][1] + bv2.y);
                float2 o1 = make_float2(acc[mi][ni][2] + bv2.x, acc[mi][ni][3] + bv2.y);
                *(float2*)(C + (size_t)r0 * N + col)       = o0;
                *(float2*)(C + (size_t)(r0 + 8) * N + col) = o1;
            }
        }
    } else {
        const int spv = spos[0];
        int seg, cbase;
        if (n0 < DD)            { seg = 0; cbase = 0; }
        else if (n0 < DD + KVD) { seg = 1; cbase = DD; }
        else                    { seg = 2; cbase = DD + KVD; }
        const float* bias = (seg == 0) ? bq : (seg == 1 ? bk : bv);
        __half* dh = (seg == 0) ? qh : (seg == 1 ? kh : vh);
        const int   ldd = (seg == 0) ? DD : KVD;
        const float sc  = (seg == 0) ? QSCALE : 1.0f;

#pragma unroll
        for (int mi = 0; mi < 4; mi++) {
            int ra = m0 + wm * 64 + mi * 16 + (lane >> 2);
            int rb = ra + 8;
            int sa  = ra & (SS - 1);
            int sbt = rb & (SS - 1);
#pragma unroll
            for (int ni = 0; ni < 4; ni++) {
                int c  = n0 + wn * 32 + ni * 8 + (lane & 3) * 2;
                int cl = c - cbase;
                float b0 = bias[cl], b1 = bias[cl + 1];
                float v0 = acc[mi][ni][0] + b0, v1 = acc[mi][ni][1] + b1;
                float v2 = acc[mi][ni][2] + b0, v3 = acc[mi][ni][3] + b1;
                if (seg < 2) {
                    int p = (c & 127) >> 1;
                    float2 fa = *(const float2*)(fc + ((size_t)(spv + sa)  * 64 + p) * 2);
                    float2 fb = *(const float2*)(fc + ((size_t)(spv + sbt) * 64 + p) * 2);
                    float o0 = (v0 * fa.x - v1 * fa.y) * sc;
                    float o1 = (v0 * fa.y + v1 * fa.x) * sc;
                    float o2 = (v2 * fb.x - v3 * fb.y) * sc;
                    float o3 = (v2 * fb.y + v3 * fb.x) * sc;
                    v0 = o0; v1 = o1; v2 = o2; v3 = o3;
                }
                uint32_t h0 = pack_f16(v0, v1);
                uint32_t h1 = pack_f16(v2, v3);
                *(uint32_t*)(dh + (size_t)ra * ldd + cl) = h0;
                *(uint32_t*)(dh + (size_t)rb * ldd + cl) = h1;
                if (seg == 0) {
                    float2 f0 = unpack_f16(h0), f1 = unpack_f16(h1);
                    *(uint32_t*)(ql + (size_t)ra * ldd + cl) = pack_f16(v0 - f0.x, v1 - f0.y);
                    *(uint32_t*)(ql + (size_t)rb * ldd + cl) = pack_f16(v2 - f1.x, v3 - f1.y);
                }
            }
        }
    }
}

// ---------------------------------------------------------------------------
// Tensor-core causal flash attention, fp16 (unchanged from R10).
// Q (hi+lo) in registers; K,V single fp16; 4-stage KV ring.
// ---------------------------------------------------------------------------
#define AROW     272
#define SQ_SZ    (128 * AROW)
#define KT_SZ    (64 * AROW)
#define STG_VH   KT_SZ
#define STG_SZ   (2 * KT_SZ)
#define ATT_NST  4
#define ATT_SMEM (ATT_NST * STG_SZ)

__device__ __forceinline__ void att_load_kv(
    uint32_t dst, const __half* khb, const __half* vhb, int n0, int t)
{
#pragma unroll
    for (int i = 0; i < 4; ++i) {
        int id = t + i * 256;
        int r  = id >> 4, c = id & 15;
        uint32_t o  = r * AROW + c * 16;
        size_t   go = (size_t)(n0 + r) * KVD + c * 8;
        CP_ASYNC16(dst + o, khb + go);
        CP_ASYNC16(dst + STG_VH + o, vhb + go);
    }
}

__global__ __launch_bounds__(256, 1) void attn_mma(
    const __half* __restrict__ qh, const __half* __restrict__ ql,
    const __half* __restrict__ kh, const __half* __restrict__ vh,
    __half* __restrict__ cc)
{
    extern __shared__ char sm[];
    const int b   = blockIdx.z;
    const int h   = blockIdx.y;
    const int mb  = gridDim.x - 1 - blockIdx.x;
    const int m0  = mb * 128;
    const int kvh = h / GROUP;
    const int t    = threadIdx.x;
    const int lane = t & 31;
    const int w    = t >> 5;

    const uint32_t sb  = smem_u32(sm);
    const uint32_t sQh = sb + 2 * STG_SZ;
    const uint32_t sQl = sb + 3 * STG_SZ;

    const __half* qhb = qh + ((size_t)(b*SS + m0) * QH + h) * HD;
    const __half* qlb = ql + ((size_t)(b*SS + m0) * QH + h) * HD;
    const __half* khb = kh + ((size_t)b*SS*KVH + kvh) * HD;
    const __half* vhb = vh + ((size_t)b*SS*KVH + kvh) * HD;

    const int ntiles = 2 * mb + 2;

#pragma unroll
    for (int i = 0; i < 8; ++i) {
        int id = t + i * 256;
        int r  = id >> 4, c = id & 15;
        uint32_t o  = r * AROW + c * 16;
        size_t   go = (size_t)r * (QH*HD) + c * 8;
        CP_ASYNC16(sQh + o, qhb + go);
        CP_ASYNC16(sQl + o, qlb + go);
    }
    att_load_kv(sb, khb, vhb, 0, t);
    CP_COMMIT();
    if (ntiles > 1) att_load_kv(sb + STG_SZ, khb, vhb, 64, t);
    CP_COMMIT();

    const uint32_t qoff = (w * 16 + (lane & 15)) * AROW + ((lane >> 4) << 4);
    const uint32_t koff = (lane & 15) * AROW + ((lane >> 4) << 4);
    const int vrow = (lane & 7) + ((lane >> 4) << 3);
    const uint32_t vcol = ((lane >> 3) & 1) << 4;

    CP_WAIT(1);
    __syncthreads();
    uint32_t Aq[8][4], Al[8][4];
#pragma unroll
    for (int ch = 0; ch < 8; ++ch) {
        LDM_X4(Aq[ch][0], Aq[ch][1], Aq[ch][2], Aq[ch][3], sQh + qoff + ch * 32);
        LDM_X4(Al[ch][0], Al[ch][1], Al[ch][2], Al[ch][3], sQl + qoff + ch * 32);
    }
    __syncthreads();
    if (ntiles > 2) att_load_kv(sb + 2 * STG_SZ, khb, vhb, 128, t);
    CP_COMMIT();
    if (ntiles > 3) att_load_kv(sb + 3 * STG_SZ, khb, vhb, 192, t);
    CP_COMMIT();

    float O[16][4];
#pragma unroll
    for (int i = 0; i < 16; i++)
#pragma unroll
        for (int j = 0; j < 4; j++) O[i][j] = 0.f;
    float mx0 = -INFINITY, mx1 = -INFINITY, l0 = 0.f, l1 = 0.f;

    const int row0 = m0 + w * 16 + (lane >> 2);
    const int row1 = row0 + 8;
    const int wrow_hi = m0 + w * 16 + 15;
    const int wrow_lo = m0 + w * 16;

    for (int it = 0; it < ntiles; ++it) {
        const int n0 = it * 64;
        CP_WAIT(3);
        __syncthreads();
        const uint32_t stg = sb + (it & 3) * STG_SZ;

        if (n0 <= wrow_hi) {
            float S[8][4];
#pragma unroll
            for (int i = 0; i < 8; i++)
#pragma unroll
                for (int j = 0; j < 4; j++) S[i][j] = 0.f;

#pragma unroll
            for (int ch = 0; ch < 8; ++ch) {
#pragma unroll
                for (int p = 0; p < 4; ++p) {
                    uint32_t h0,h1,h2,h3;
                    LDM_X4(h0,h1,h2,h3, stg + koff + p*(16*AROW) + ch*32);
                    uint32_t bh0[2] = {h0, h2}, bh1[2] = {h1, h3};
                    MMA16816(S[2*p],   Aq[ch], bh0);
                    MMA16816(S[2*p+1], Aq[ch], bh1);
                    MMA16816(S[2*p],   Al[ch], bh0);
                    MMA16816(S[2*p+1], Al[ch], bh1);
                }
            }

            if (n0 + 63 > wrow_lo) {
#pragma unroll
                for (int p = 0; p < 8; ++p) {
                    int c = n0 + p * 8 + (lane & 3) * 2;
                    if (c     > row0) S[p][0] = -INFINITY;
                    if (c + 1 > row0) S[p][1] = -INFINITY;
                    if (c     > row1) S[p][2] = -INFINITY;
                    if (c + 1 > row1) S[p][3] = -INFINITY;
                }
            }

            float t0 = -INFINITY, t1 = -INFINITY;
#pragma unroll
            for (int p = 0; p < 8; ++p) {
                t0 = fmaxf(t0, fmaxf(S[p][0], S[p][1]));
                t1 = fmaxf(t1, fmaxf(S[p][2], S[p][3]));
            }
            t0 = fmaxf(t0, __shfl_xor_sync(0xffffffffu, t0, 1));
            t0 = fmaxf(t0, __shfl_xor_sync(0xffffffffu, t0, 2));
            t1 = fmaxf(t1, __shfl_xor_sync(0xffffffffu, t1, 1));
            t1 = fmaxf(t1, __shfl_xor_sync(0xffffffffu, t1, 2));
            float mn0 = fmaxf(mx0, t0), mn1 = fmaxf(mx1, t1);
            float cr0 = ex2f(mx0 - mn0), cr1 = ex2f(mx1 - mn1);
            mx0 = mn0; mx1 = mn1;

            float sa0 = 0.f, sa1 = 0.f;
#pragma unroll
            for (int p = 0; p < 8; ++p) {
                S[p][0] = ex2f(S[p][0] - mn0);
                S[p][1] = ex2f(S[p][1] - mn0);
                S[p][2] = ex2f(S[p][2] - mn1);
                S[p][3] = ex2f(S[p][3] - mn1);
                sa0 += S[p][0] + S[p][1];
                sa1 += S[p][2] + S[p][3];
            }
            sa0 += __shfl_xor_sync(0xffffffffu, sa0, 1);
            sa0 += __shfl_xor_sync(0xffffffffu, sa0, 2);
            sa1 += __shfl_xor_sync(0xffffffffu, sa1, 1);
            sa1 += __shfl_xor_sync(0xffffffffu, sa1, 2);
            l0 = l0 * cr0 + sa0;
            l1 = l1 * cr1 + sa1;

#pragma unroll
            for (int i = 0; i < 16; i++) {
                O[i][0] *= cr0; O[i][1] *= cr0;
                O[i][2] *= cr1; O[i][3] *= cr1;
            }

#pragma unroll
            for (int jc = 0; jc < 4; ++jc) {
                uint32_t ph[4], pl[4];
#pragma unroll
                for (int q2 = 0; q2 < 2; ++q2) {
                    float p0 = S[2*jc + q2][0], p1 = S[2*jc + q2][1];
                    float p2 = S[2*jc + q2][2], p3 = S[2*jc + q2][3];
                    uint32_t hp0 = pack_f16(p0, p1);
                    uint32_t hp1 = pack_f16(p2, p3);
                    float2 f0 = unpack_f16(hp0), f1 = unpack_f16(hp1);
                    ph[2*q2]   = hp0;  ph[2*q2+1] = hp1;
                    pl[2*q2]   = pack_f16(p0 - f0.x, p1 - f0.y);
                    pl[2*q2+1] = pack_f16(p2 - f1.x, p3 - f1.y);
                }
                const uint32_t vro = (jc * 16 + vrow) * AROW + vcol;
#pragma unroll
                for (int db = 0; db < 8; ++db) {
                    uint32_t a0,a1,a2,a3;
                    LDM_X4T(a0,a1,a2,a3, stg + STG_VH + vro + db * 32);
                    uint32_t bh0[2] = {a0, a2}, bh1[2] = {a1, a3};
                    MMA16816(O[2*db],   ph, bh0);
                    MMA16816(O[2*db+1], ph, bh1);
                    MMA16816(O[2*db],   pl, bh0);
                    MMA16816(O[2*db+1], pl, bh1);
                }
            }
        }

        __syncthreads();
        if (it + ATT_NST < ntiles)
            att_load_kv(stg, khb, vhb, (it + ATT_NST) * 64, t);
        CP_COMMIT();
    }

    float inv0 = 1.0f / l0, inv1 = 1.0f / l1;
    const size_t base0 = (size_t)(b * SS + row0) * K2;
    const size_t base1 = (size_t)(b * SS + row1) * K2;
    const int colb = h * 128 + (lane & 3) * 2;
#pragma unroll
    for (int dt = 0; dt < 16; ++dt) {
        int col = colb + dt * 8;
        float v0 = O[dt][0] * inv0, v1 = O[dt][1] * inv0;
        float v2 = O[dt][2] * inv1, v3 = O[dt][3] * inv1;
        uint32_t hi0 = pack_f16(v0, v1);
        uint32_t hi1 = pack_f16(v2, v3);
        float2 f0 = unpack_f16(hi0), f1 = unpack_f16(hi1);
        uint32_t lo0 = pack_f16(v0 - f0.x, v1 - f0.y);
        uint32_t lo1 = pack_f16(v2 - f1.x, v3 - f1.y);
        *(uint32_t*)(cc + base0 + col)      = hi0;
        *(uint32_t*)(cc + base0 + DD + col) = lo0;
        *(uint32_t*)(cc + base1 + col)      = hi1;
        *(uint32_t*)(cc + base1 + DD + col) = lo1;
    }
}

// ---------------------------------------------------------------------------
// launch
// ---------------------------------------------------------------------------
extern "C" void kernel_launch(void* const* d_in, const int* in_sizes, int n_in,
                              void* d_out, int out_size)
{
    const float* xs   = (const float*)d_in[0];
    const int*   spos = (const int*)  d_in[1];
    const float* fc   = (const float*)d_in[2];
    const float* Wq   = (const float*)d_in[3];
    const float* bq   = (const float*)d_in[4];
    const float* Wk   = (const float*)d_in[5];
    const float* bk   = (const float*)d_in[6];
    const float* Wv   = (const float*)d_in[7];
    const float* bv   = (const float*)d_in[8];
    const float* Wo   = (const float*)d_in[9];
    const float* bo   = (const float*)d_in[10];
    float* out = (float*)d_out;

    __half *xc, *wqkv, *woc, *cc, *qhp, *qlp, *khp, *vhp;
    cudaGetSymbolAddress((void**)&xc,   g_xc);
    cudaGetSymbolAddress((void**)&wqkv, g_wqkv);
    cudaGetSymbolAddress((void**)&woc,  g_woc);
    cudaGetSymbolAddress((void**)&cc,   g_cc);
    cudaGetSymbolAddress((void**)&qhp,  g_qh);
    cudaGetSymbolAddress((void**)&qlp,  g_ql);
    cudaGetSymbolAddress((void**)&khp,  g_kh);
    cudaGetSymbolAddress((void**)&vhp,  g_vh);

    cudaFuncSetAttribute(gemm_mma<0>, cudaFuncAttributeMaxDynamicSharedMemorySize, GSMEM);
    cudaFuncSetAttribute(gemm_mma<1>, cudaFuncAttributeMaxDynamicSharedMemorySize, GSMEM);
    cudaFuncSetAttribute(attn_mma,    cudaFuncAttributeMaxDynamicSharedMemorySize, ATT_SMEM);

    // conversions (launches 1-5)
    {
        int n;
        n = TOK*DD/4;  split_f16_kernel<<<(n+255)/256, 256>>>(xs, xc, DD, n);
        n = DD*DD/4;   conv_f16_kernel<<<(n+255)/256, 256>>>(Wq, wqkv, n);
        n = KVD*DD/4;  conv_f16_kernel<<<(n+255)/256, 256>>>(Wk, wqkv + (size_t)DD*DD, n);
        n = KVD*DD/4;  conv_f16_kernel<<<(n+255)/256, 256>>>(Wv, wqkv + (size_t)(DD+KVD)*DD, n);
        n = DD*DD/4;   conv_f16_kernel<<<(n+255)/256, 256>>>(Wo, woc, n);
    }

    // fused QKV projection + rope + split (launch 6)
    gemm_mma<1><<<dim3(TOK/CTM, NQKV/CTN), 256, GSMEM>>>(
        xc, wqkv, bq, bk, bv, nullptr, 0, fc, spos,
        qhp, qlp, khp, vhp);

    // attention (launch 7)
    attn_mma<<<dim3(SS/128, QH, BB), 256, ATT_SMEM>>>(qhp, qlp, khp, vhp, cc);

    // output projection (launch 8)
    gemm_mma<0><<<dim3(TOK/CTM, DD/CTN), 256, GSMEM>>>(
        cc, woc, bo, nullptr, nullptr, out, DD, nullptr, nullptr,
        nullptr, nullptr, nullptr, nullptr);
}

// round 12
// speedup vs baseline: 1.9337x; 1.1708x over previous
#include <cuda_runtime.h>
#include <cuda_fp16.h>
#include <math.h>
#include <stdint.h>

// Problem constants
#define BB   2
#define SS   2048
#define DD   4096
#define QH   32
#define KVH  8
#define HD   128
#define KVD  (KVH*HD)      // 1024
#define GROUP (QH/KVH)     // 4
#define TOK  (BB*SS)       // 4096
#define K2   (2*DD)        // 8192 : x split length [hi|lo]
#define NQKV (DD + 2*KVD)  // 6144

#define QSCALE (0.08838834764831845f * 1.4426950408889634f)

// ---------------------------------------------------------------------------
// Scratch
// ---------------------------------------------------------------------------
__device__ __align__(16) __half g_xc  [(size_t)TOK*K2];    // [xh | xl]
__device__ __align__(16) __half g_wqkv[(size_t)NQKV*DD];   // fp16 weights
__device__ __align__(16) __half g_woc [(size_t)DD*DD];
__device__ __align__(16) __half g_cc  [(size_t)TOK*DD];    // ctx, single fp16

__device__ __align__(16) __half g_qh[TOK*DD];
__device__ __align__(16) __half g_ql[TOK*DD];
__device__ __align__(16) __half g_kh[TOK*KVD];
__device__ __align__(16) __half g_vh[TOK*KVD];

// ---------------------------------------------------------------------------
// helpers
// ---------------------------------------------------------------------------
__device__ __forceinline__ uint32_t smem_u32(const void* p) {
    uint32_t a;
    asm("{ .reg .u64 t; cvta.to.shared.u64 t, %1; cvt.u32.u64 %0, t; }" : "=r"(a) : "l"(p));
    return a;
}

#define CP_ASYNC16(dst, src) \
    asm volatile("cp.async.cg.shared.global [%0], [%1], 16;" :: "r"(dst), "l"(src))
#define CP_COMMIT()   asm volatile("cp.async.commit_group;" ::: "memory")
#define CP_WAIT(n)    asm volatile("cp.async.wait_group %0;" :: "n"(n) : "memory")

#define LDM_X4(r0, r1, r2, r3, addr) \
    asm volatile("ldmatrix.sync.aligned.m8n8.x4.shared.b16 {%0,%1,%2,%3}, [%4];" \
        : "=r"(r0), "=r"(r1), "=r"(r2), "=r"(r3) : "r"(addr))

#define LDM_X4T(r0, r1, r2, r3, addr) \
    asm volatile("ldmatrix.sync.aligned.m8n8.x4.trans.shared.b16 {%0,%1,%2,%3}, [%4];" \
        : "=r"(r0), "=r"(r1), "=r"(r2), "=r"(r3) : "r"(addr))

#define MMA16816(d, a, b) \
    asm volatile("mma.sync.aligned.m16n8k16.row.col.f32.f16.f16.f32 " \
        "{%0,%1,%2,%3},{%4,%5,%6,%7},{%8,%9},{%0,%1,%2,%3};" \
        : "+f"((d)[0]), "+f"((d)[1]), "+f"((d)[2]), "+f"((d)[3]) \
        : "r"((a)[0]), "r"((a)[1]), "r"((a)[2]), "r"((a)[3]), \
          "r"((b)[0]), "r"((b)[1]))

__device__ __forceinline__ uint32_t pack_f16(float a, float b) {
    __half2 h = __floats2half2_rn(a, b);
    return *reinterpret_cast<uint32_t*>(&h);
}
__device__ __forceinline__ float2 unpack_f16(uint32_t u) {
    __half2 h = *reinterpret_cast<__half2*>(&u);
    return __half22float2(h);
}
__device__ __forceinline__ float ex2f(float x) {
    float r; asm("ex2.approx.f32 %0, %1;" : "=f"(r) : "f"(x)); return r;
}

// ---------------------------------------------------------------------------
// fp32 -> [hi | lo] fp16 split (row length 2K)
// ---------------------------------------------------------------------------
__global__ void split_f16_kernel(const float* __restrict__ in,
                                 __half* __restrict__ out, int K, int total4)
{
    int idx = blockIdx.x * blockDim.x + threadIdx.x;
    if (idx >= total4) return;
    float4 v = ((const float4*)in)[idx];
    int K4 = K >> 2;
    int r  = idx / K4;
    int k  = (idx - r * K4) << 2;
    uint32_t h0 = pack_f16(v.x, v.y);
    uint32_t h1 = pack_f16(v.z, v.w);
    float2 f0 = unpack_f16(h0), f1 = unpack_f16(h1);
    uint32_t l0 = pack_f16(v.x - f0.x, v.y - f0.y);
    uint32_t l1 = pack_f16(v.z - f1.x, v.w - f1.y);
    __half* row = out + (size_t)r * (2*K);
    *(uint2*)(row + k)     = make_uint2(h0, h1);
    *(uint2*)(row + K + k) = make_uint2(l0, l1);
}

// fp32 -> fp16 plain convert
__global__ void conv_f16_kernel(const float* __restrict__ in,
                                __half* __restrict__ out, int total4)
{
    int idx = blockIdx.x * blockDim.x + threadIdx.x;
    if (idx >= total4) return;
    float4 v = ((const float4*)in)[idx];
    ((uint2*)out)[idx] = make_uint2(pack_f16(v.x, v.y), pack_f16(v.z, v.w));
}

// ---------------------------------------------------------------------------
// common GEMM geometry
// ---------------------------------------------------------------------------
#define CTM   128
#define CTN   128
#define GBK   64
#define NCH   (DD / GBK)            // 64
#define ROWB  144                   // 64 fp16 (128B) + 16B pad
#define TILE  (128 * ROWB)          // 18432

// ---------------------------------------------------------------------------
// QKV GEMM, shared-B 2-pass: QKV = (xh + xl) @ fp16(W)^T, fused rope+split.
// 2 stages of [Ah|Al|B] (55 KB), occ 2.
// ---------------------------------------------------------------------------
#define NST   2
#define STAGE (3 * TILE)            // 55296
#define GSMEM (NST * STAGE)         // 110592

__global__ __launch_bounds__(256, 2) void gemm_qkv(
    const __half* __restrict__ A, const __half* __restrict__ B,
    const float* __restrict__ bq, const float* __restrict__ bk,
    const float* __restrict__ bv,
    const float* __restrict__ fc, const int* __restrict__ spos,
    __half* __restrict__ qh, __half* __restrict__ ql,
    __half* __restrict__ kh, __half* __restrict__ vh)
{
    extern __shared__ char smraw[];
    const int t    = threadIdx.x;
    const int lane = t & 31;
    const int wid  = t >> 5;
    const int wm   = wid & 1;
    const int wn   = wid >> 1;
    const int m0   = blockIdx.x * CTM;
    const int n0   = blockIdx.y * CTN;
    const uint32_t sb = smem_u32(smraw);

    float acc[4][4][4];
#pragma unroll
    for (int i = 0; i < 4; i++)
#pragma unroll
        for (int j = 0; j < 4; j++)
#pragma unroll
            for (int r = 0; r < 4; r++) acc[i][j][r] = 0.f;

    const __half* Ahs[4];
    const __half* Bs[4];
    uint32_t doff[4];
#pragma unroll
    for (int i = 0; i < 4; i++) {
        int id  = t + i * 256;
        int row = id >> 3;
        int c8  = id & 7;
        doff[i] = row * ROWB + c8 * 16;
        Ahs[i]  = A + (size_t)(m0 + row) * K2 + c8 * 8;
        Bs[i]   = B + (size_t)(n0 + row) * DD + c8 * 8;
    }

#define LOAD_STAGE(st, k0) do {                                        \
    uint32_t base = sb + (st) * STAGE;                                 \
    _Pragma("unroll")                                                  \
    for (int i = 0; i < 4; i++)                                        \
        CP_ASYNC16(base + doff[i], Ahs[i] + (k0));                     \
    _Pragma("unroll")                                                  \
    for (int i = 0; i < 4; i++)                                        \
        CP_ASYNC16(base + TILE + doff[i], Ahs[i] + DD + (k0));         \
    _Pragma("unroll")                                                  \
    for (int i = 0; i < 4; i++)                                        \
        CP_ASYNC16(base + 2 * TILE + doff[i], Bs[i] + (k0));           \
} while (0)

    LOAD_STAGE(0, 0);
    CP_COMMIT();

    const uint32_t aoffs = (wm * 64 + (lane & 15)) * ROWB + ((lane >> 4) << 4);
    const uint32_t boffs = (wn * 32 + (lane & 15)) * ROWB + ((lane >> 4) << 4);

    for (int c = 0; c < NCH; c++) {
        const int st = c & 1;
        CP_WAIT(0);
        __syncthreads();
        if (c + 1 < NCH) {
            LOAD_STAGE(st ^ 1, (c + 1) * GBK);
            CP_COMMIT();
        }

        const uint32_t ab  = sb + st * STAGE;
        const uint32_t ab2 = ab + TILE;
        const uint32_t bb  = ab + 2 * TILE;

#pragma unroll
        for (int ks = 0; ks < 4; ks++) {
            uint32_t a[4][4], a2[4][4];
            uint32_t bf[4][2];
#pragma unroll
            for (int mi = 0; mi < 4; mi++) {
                LDM_X4(a[mi][0], a[mi][1], a[mi][2], a[mi][3],
                       ab + aoffs + mi * 16 * ROWB + ks * 32);
                LDM_X4(a2[mi][0], a2[mi][1], a2[mi][2], a2[mi][3],
                       ab2 + aoffs + mi * 16 * ROWB + ks * 32);
            }
#pragma unroll
            for (int p = 0; p < 2; p++) {
                uint32_t r0, r1, r2, r3;
                LDM_X4(r0, r1, r2, r3, bb + boffs + p * 16 * ROWB + ks * 32);
                bf[2*p][0]   = r0; bf[2*p][1]   = r2;
                bf[2*p+1][0] = r1; bf[2*p+1][1] = r3;
            }
#pragma unroll
            for (int mi = 0; mi < 4; mi++)
#pragma unroll
                for (int ni = 0; ni < 4; ni++) {
                    MMA16816(acc[mi][ni], a[mi],  bf[ni]);
                    MMA16816(acc[mi][ni], a2[mi], bf[ni]);
                }
        }
    }
#undef LOAD_STAGE

    // fused QKV epilogue
    const int spv = spos[0];
    int seg, cbase;
    if (n0 < DD)            { seg = 0; cbase = 0; }
    else if (n0 < DD + KVD) { seg = 1; cbase = DD; }
    else                    { seg = 2; cbase = DD + KVD; }
    const float* bias = (seg == 0) ? bq : (seg == 1 ? bk : bv);
    __half* dh = (seg == 0) ? qh : (seg == 1 ? kh : vh);
    const int   ldd = (seg == 0) ? DD : KVD;
    const float sc  = (seg == 0) ? QSCALE : 1.0f;

#pragma unroll
    for (int mi = 0; mi < 4; mi++) {
        int ra = m0 + wm * 64 + mi * 16 + (lane >> 2);
        int rb = ra + 8;
        int sa  = ra & (SS - 1);
        int sbt = rb & (SS - 1);
#pragma unroll
        for (int ni = 0; ni < 4; ni++) {
            int c  = n0 + wn * 32 + ni * 8 + (lane & 3) * 2;
            int cl = c - cbase;
            float b0 = bias[cl], b1 = bias[cl + 1];
            float v0 = acc[mi][ni][0] + b0, v1 = acc[mi][ni][1] + b1;
            float v2 = acc[mi][ni][2] + b0, v3 = acc[mi][ni][3] + b1;
            if (seg < 2) {
                int p = (c & 127) >> 1;
                float2 fa = *(const float2*)(fc + ((size_t)(spv + sa)  * 64 + p) * 2);
                float2 fb = *(const float2*)(fc + ((size_t)(spv + sbt) * 64 + p) * 2);
                float o0 = (v0 * fa.x - v1 * fa.y) * sc;
                float o1 = (v0 * fa.y + v1 * fa.x) * sc;
                float o2 = (v2 * fb.x - v3 * fb.y) * sc;
                float o3 = (v2 * fb.y + v3 * fb.x) * sc;
                v0 = o0; v1 = o1; v2 = o2; v3 = o3;
            }
            uint32_t h0 = pack_f16(v0, v1);
            uint32_t h1 = pack_f16(v2, v3);
            *(uint32_t*)(dh + (size_t)ra * ldd + cl) = h0;
            *(uint32_t*)(dh + (size_t)rb * ldd + cl) = h1;
            if (seg == 0) {
                float2 f0 = unpack_f16(h0), f1 = unpack_f16(h1);
                *(uint32_t*)(ql + (size_t)ra * ldd + cl) = pack_f16(v0 - f0.x, v1 - f0.y);
                *(uint32_t*)(ql + (size_t)rb * ldd + cl) = pack_f16(v2 - f1.x, v3 - f1.y);
            }
        }
    }
}

// ---------------------------------------------------------------------------
// Output projection: single-pass fp16 GEMM, out = cc @ Wo^T + bo (fp32 out).
// 3 stages of [A|B] (37 KB), occ 2, CP_WAIT(1).
// ---------------------------------------------------------------------------
#define ONST   3
#define OSTAGE (2 * TILE)           // 36864
#define OSMEM  (ONST * OSTAGE)      // 110592

__global__ __launch_bounds__(256, 2) void gemm_out(
    const __half* __restrict__ A, const __half* __restrict__ B,
    const float* __restrict__ bias, float* __restrict__ C, int N)
{
    extern __shared__ char smraw[];
    const int t    = threadIdx.x;
    const int lane = t & 31;
    const int wid  = t >> 5;
    const int wm   = wid & 1;
    const int wn   = wid >> 1;
    const int m0   = blockIdx.x * CTM;
    const int n0   = blockIdx.y * CTN;
    const uint32_t sb = smem_u32(smraw);

    float acc[4][4][4];
#pragma unroll
    for (int i = 0; i < 4; i++)
#pragma unroll
        for (int j = 0; j < 4; j++)
#pragma unroll
            for (int r = 0; r < 4; r++) acc[i][j][r] = 0.f;

    const __half* As[4];
    const __half* Bs[4];
    uint32_t doff[4];
#pragma unroll
    for (int i = 0; i < 4; i++) {
        int id  = t + i * 256;
        int row = id >> 3;
        int c8  = id & 7;
        doff[i] = row * ROWB + c8 * 16;
        As[i]   = A + (size_t)(m0 + row) * DD + c8 * 8;
        Bs[i]   = B + (size_t)(n0 + row) * DD + c8 * 8;
    }

#define OLOAD(st, k0) do {                                             \
    uint32_t base = sb + (st) * OSTAGE;                                \
    _Pragma("unroll")                                                  \
    for (int i = 0; i < 4; i++)                                        \
        CP_ASYNC16(base + doff[i], As[i] + (k0));                      \
    _Pragma("unroll")                                                  \
    for (int i = 0; i < 4; i++)                                        \
        CP_ASYNC16(base + TILE + doff[i], Bs[i] + (k0));               \
} while (0)

    OLOAD(0, 0);
    CP_COMMIT();
    OLOAD(1, GBK);
    CP_COMMIT();

    const uint32_t aoffs = (wm * 64 + (lane & 15)) * ROWB + ((lane >> 4) << 4);
    const uint32_t boffs = (wn * 32 + (lane & 15)) * ROWB + ((lane >> 4) << 4);

    int st = 0;
    for (int c = 0; c < NCH; c++) {
        CP_WAIT(1);
        __syncthreads();
        if (c + 2 < NCH) {
            int st2 = st + 2; if (st2 >= ONST) st2 -= ONST;
            OLOAD(st2, (c + 2) * GBK);
        }
        CP_COMMIT();

        const uint32_t ab = sb + st * OSTAGE;
        const uint32_t bb = ab + TILE;

#pragma unroll
        for (int ks = 0; ks < 4; ks++) {
            uint32_t a[4][4];
            uint32_t bf[4][2];
#pragma unroll
            for (int mi = 0; mi < 4; mi++)
                LDM_X4(a[mi][0], a[mi][1], a[mi][2], a[mi][3],
                       ab + aoffs + mi * 16 * ROWB + ks * 32);
#pragma unroll
            for (int p = 0; p < 2; p++) {
                uint32_t r0, r1, r2, r3;
                LDM_X4(r0, r1, r2, r3, bb + boffs + p * 16 * ROWB + ks * 32);
                bf[2*p][0]   = r0; bf[2*p][1]   = r2;
                bf[2*p+1][0] = r1; bf[2*p+1][1] = r3;
            }
#pragma unroll
            for (int mi = 0; mi < 4; mi++)
#pragma unroll
                for (int ni = 0; ni < 4; ni++)
                    MMA16816(acc[mi][ni], a[mi], bf[ni]);
        }
        if (++st == ONST) st = 0;
    }
#undef OLOAD

#pragma unroll
    for (int mi = 0; mi < 4; mi++) {
        int r0 = m0 + wm * 64 + mi * 16 + (lane >> 2);
#pragma unroll
        for (int ni = 0; ni < 4; ni++) {
            int col = n0 + wn * 32 + ni * 8 + (lane & 3) * 2;
            float2 bv2 = *(const float2*)(bias + col);
            float2 o0 = make_float2(acc[mi][ni][0] + bv2.x, acc[mi][ni][1] + bv2.y);
            float2 o1 = make_float2(acc[mi][ni][2] + bv2.x, acc[mi][ni][3] + bv2.y);
            *(float2*)(C + (size_t)r0 * N + col)       = o0;
            *(float2*)(C + (size_t)(r0 + 8) * N + col) = o1;
        }
    }
}

// ---------------------------------------------------------------------------
// Tensor-core causal flash attention, fp16.
// Q (hi+lo) in registers; K,V single fp16; 4-stage KV ring.
// Epilogue: single fp16 ctx write (row length DD).
// ---------------------------------------------------------------------------
#define AROW     272
#define SQ_SZ    (128 * AROW)
#define KT_SZ    (64 * AROW)
#define STG_VH   KT_SZ
#define STG_SZ   (2 * KT_SZ)
#define ATT_NST  4
#define ATT_SMEM (ATT_NST * STG_SZ)

__device__ __forceinline__ void att_load_kv(
    uint32_t dst, const __half* khb, const __half* vhb, int n0, int t)
{
#pragma unroll
    for (int i = 0; i < 4; ++i) {
        int id = t + i * 256;
        int r  = id >> 4, c = id & 15;
        uint32_t o  = r * AROW + c * 16;
        size_t   go = (size_t)(n0 + r) * KVD + c * 8;
        CP_ASYNC16(dst + o, khb + go);
        CP_ASYNC16(dst + STG_VH + o, vhb + go);
    }
}

__global__ __launch_bounds__(256, 1) void attn_mma(
    const __half* __restrict__ qh, const __half* __restrict__ ql,
    const __half* __restrict__ kh, const __half* __restrict__ vh,
    __half* __restrict__ cc)
{
    extern __shared__ char sm[];
    const int b   = blockIdx.z;
    const int h   = blockIdx.y;
    const int mb  = gridDim.x - 1 - blockIdx.x;
    const int m0  = mb * 128;
    const int kvh = h / GROUP;
    const int t    = threadIdx.x;
    const int lane = t & 31;
    const int w    = t >> 5;

    const uint32_t sb  = smem_u32(sm);
    const uint32_t sQh = sb + 2 * STG_SZ;
    const uint32_t sQl = sb + 3 * STG_SZ;

    const __half* qhb = qh + ((size_t)(b*SS + m0) * QH + h) * HD;
    const __half* qlb = ql + ((size_t)(b*SS + m0) * QH + h) * HD;
    const __half* khb = kh + ((size_t)b*SS*KVH + kvh) * HD;
    const __half* vhb = vh + ((size_t)b*SS*KVH + kvh) * HD;

    const int ntiles = 2 * mb + 2;

#pragma unroll
    for (int i = 0; i < 8; ++i) {
        int id = t + i * 256;
        int r  = id >> 4, c = id & 15;
        uint32_t o  = r * AROW + c * 16;
        size_t   go = (size_t)r * (QH*HD) + c * 8;
        CP_ASYNC16(sQh + o, qhb + go);
        CP_ASYNC16(sQl + o, qlb + go);
    }
    att_load_kv(sb, khb, vhb, 0, t);
    CP_COMMIT();
    if (ntiles > 1) att_load_kv(sb + STG_SZ, khb, vhb, 64, t);
    CP_COMMIT();

    const uint32_t qoff = (w * 16 + (lane & 15)) * AROW + ((lane >> 4) << 4);
    const uint32_t koff = (lane & 15) * AROW + ((lane >> 4) << 4);
    const int vrow = (lane & 7) + ((lane >> 4) << 3);
    const uint32_t vcol = ((lane >> 3) & 1) << 4;

    CP_WAIT(1);
    __syncthreads();
    uint32_t Aq[8][4], Al[8][4];
#pragma unroll
    for (int ch = 0; ch < 8; ++ch) {
        LDM_X4(Aq[ch][0], Aq[ch][1], Aq[ch][2], Aq[ch][3], sQh + qoff + ch * 32);
        LDM_X4(Al[ch][0], Al[ch][1], Al[ch][2], Al[ch][3], sQl + qoff + ch * 32);
    }
    __syncthreads();
    if (ntiles > 2) att_load_kv(sb + 2 * STG_SZ, khb, vhb, 128, t);
    CP_COMMIT();
    if (ntiles > 3) att_load_kv(sb + 3 * STG_SZ, khb, vhb, 192, t);
    CP_COMMIT();

    float O[16][4];
#pragma unroll
    for (int i = 0; i < 16; i++)
#pragma unroll
        for (int j = 0; j < 4; j++) O[i][j] = 0.f;
    float mx0 = -INFINITY, mx1 = -INFINITY, l0 = 0.f, l1 = 0.f;

    const int row0 = m0 + w * 16 + (lane >> 2);
    const int row1 = row0 + 8;
    const int wrow_hi = m0 + w * 16 + 15;
    const int wrow_lo = m0 + w * 16;

    for (int it = 0; it < ntiles; ++it) {
        const int n0 = it * 64;
        CP_WAIT(3);
        __syncthreads();
        const uint32_t stg = sb + (it & 3) * STG_SZ;

        if (n0 <= wrow_hi) {
            float S[8][4];
#pragma unroll
            for (int i = 0; i < 8; i++)
#pragma unroll
                for (int j = 0; j < 4; j++) S[i][j] = 0.f;

#pragma unroll
            for (int ch = 0; ch < 8; ++ch) {
#pragma unroll
                for (int p = 0; p < 4; ++p) {
                    uint32_t h0,h1,h2,h3;
                    LDM_X4(h0,h1,h2,h3, stg + koff + p*(16*AROW) + ch*32);
                    uint32_t bh0[2] = {h0, h2}, bh1[2] = {h1, h3};
                    MMA16816(S[2*p],   Aq[ch], bh0);
                    MMA16816(S[2*p+1], Aq[ch], bh1);
                    MMA16816(S[2*p],   Al[ch], bh0);
                    MMA16816(S[2*p+1], Al[ch], bh1);
                }
            }

            if (n0 + 63 > wrow_lo) {
#pragma unroll
                for (int p = 0; p < 8; ++p) {
                    int c = n0 + p * 8 + (lane & 3) * 2;
                    if (c     > row0) S[p][0] = -INFINITY;
                    if (c + 1 > row0) S[p][1] = -INFINITY;
                    if (c     > row1) S[p][2] = -INFINITY;
                    if (c + 1 > row1) S[p][3] = -INFINITY;
                }
            }

            float t0 = -INFINITY, t1 = -INFINITY;
#pragma unroll
            for (int p = 0; p < 8; ++p) {
                t0 = fmaxf(t0, fmaxf(S[p][0], S[p][1]));
                t1 = fmaxf(t1, fmaxf(S[p][2], S[p][3]));
            }
            t0 = fmaxf(t0, __shfl_xor_sync(0xffffffffu, t0, 1));
            t0 = fmaxf(t0, __shfl_xor_sync(0xffffffffu, t0, 2));
            t1 = fmaxf(t1, __shfl_xor_sync(0xffffffffu, t1, 1));
            t1 = fmaxf(t1, __shfl_xor_sync(0xffffffffu, t1, 2));
            float mn0 = fmaxf(mx0, t0), mn1 = fmaxf(mx1, t1);
            float cr0 = ex2f(mx0 - mn0), cr1 = ex2f(mx1 - mn1);
            mx0 = mn0; mx1 = mn1;

            float sa0 = 0.f, sa1 = 0.f;
#pragma unroll
            for (int p = 0; p < 8; ++p) {
                S[p][0] = ex2f(S[p][0] - mn0);
                S[p][1] = ex2f(S[p][1] - mn0);
                S[p][2] = ex2f(S[p][2] - mn1);
                S[p][3] = ex2f(S[p][3] - mn1);
                sa0 += S[p][0] + S[p][1];
                sa1 += S[p][2] + S[p][3];
            }
            sa0 += __shfl_xor_sync(0xffffffffu, sa0, 1);
            sa0 += __shfl_xor_sync(0xffffffffu, sa0, 2);
            sa1 += __shfl_xor_sync(0xffffffffu, sa1, 1);
            sa1 += __shfl_xor_sync(0xffffffffu, sa1, 2);
            l0 = l0 * cr0 + sa0;
            l1 = l1 * cr1 + sa1;

#pragma unroll
            for (int i = 0; i < 16; i++) {
                O[i][0] *= cr0; O[i][1] *= cr0;
                O[i][2] *= cr1; O[i][3] *= cr1;
            }

#pragma unroll
            for (int jc = 0; jc < 4; ++jc) {
                uint32_t ph[4], pl[4];
#pragma unroll
                for (int q2 = 0; q2 < 2; ++q2) {
                    float p0 = S[2*jc + q2][0], p1 = S[2*jc + q2][1];
                    float p2 = S[2*jc + q2][2], p3 = S[2*jc + q2][3];
                    uint32_t hp0 = pack_f16(p0, p1);
                    uint32_t hp1 = pack_f16(p2, p3);
                    float2 f0 = unpack_f16(hp0), f1 = unpack_f16(hp1);
                    ph[2*q2]   = hp0;  ph[2*q2+1] = hp1;
                    pl[2*q2]   = pack_f16(p0 - f0.x, p1 - f0.y);
                    pl[2*q2+1] = pack_f16(p2 - f1.x, p3 - f1.y);
                }
                const uint32_t vro = (jc * 16 + vrow) * AROW + vcol;
#pragma unroll
                for (int db = 0; db < 8; ++db) {
                    uint32_t a0,a1,a2,a3;
                    LDM_X4T(a0,a1,a2,a3, stg + STG_VH + vro + db * 32);
                    uint32_t bh0[2] = {a0, a2}, bh1[2] = {a1, a3};
                    MMA16816(O[2*db],   ph, bh0);
                    MMA16816(O[2*db+1], ph, bh1);
                    MMA16816(O[2*db],   pl, bh0);
                    MMA16816(O[2*db+1], pl, bh1);
                }
            }
        }

        __syncthreads();
        if (it + ATT_NST < ntiles)
            att_load_kv(stg, khb, vhb, (it + ATT_NST) * 64, t);
        CP_COMMIT();
    }

    // normalize + single fp16 write to cc (row length DD)
    float inv0 = 1.0f / l0, inv1 = 1.0f / l1;
    const size_t base0 = (size_t)(b * SS + row0) * DD;
    const size_t base1 = (size_t)(b * SS + row1) * DD;
    const int colb = h * 128 + (lane & 3) * 2;
#pragma unroll
    for (int dt = 0; dt < 16; ++dt) {
        int col = colb + dt * 8;
        *(uint32_t*)(cc + base0 + col) = pack_f16(O[dt][0] * inv0, O[dt][1] * inv0);
        *(uint32_t*)(cc + base1 + col) = pack_f16(O[dt][2] * inv1, O[dt][3] * inv1);
    }
}

// ---------------------------------------------------------------------------
// launch
// ---------------------------------------------------------------------------
extern "C" void kernel_launch(void* const* d_in, const int* in_sizes, int n_in,
                              void* d_out, int out_size)
{
    const float* xs   = (const float*)d_in[0];
    const int*   spos = (const int*)  d_in[1];
    const float* fc   = (const float*)d_in[2];
    const float* Wq   = (const float*)d_in[3];
    const float* bq   = (const float*)d_in[4];
    const float* Wk   = (const float*)d_in[5];
    const float* bk   = (const float*)d_in[6];
    const float* Wv   = (const float*)d_in[7];
    const float* bv   = (const float*)d_in[8];
    const float* Wo   = (const float*)d_in[9];
    const float* bo   = (const float*)d_in[10];
    float* out = (float*)d_out;

    __half *xc, *wqkv, *woc, *cc, *qhp, *qlp, *khp, *vhp;
    cudaGetSymbolAddress((void**)&xc,   g_xc);
    cudaGetSymbolAddress((void**)&wqkv, g_wqkv);
    cudaGetSymbolAddress((void**)&woc,  g_woc);
    cudaGetSymbolAddress((void**)&cc,   g_cc);
    cudaGetSymbolAddress((void**)&qhp,  g_qh);
    cudaGetSymbolAddress((void**)&qlp,  g_ql);
    cudaGetSymbolAddress((void**)&khp,  g_kh);
    cudaGetSymbolAddress((void**)&vhp,  g_vh);

    cudaFuncSetAttribute(gemm_qkv, cudaFuncAttributeMaxDynamicSharedMemorySize, GSMEM);
    cudaFuncSetAttribute(gemm_out, cudaFuncAttributeMaxDynamicSharedMemorySize, OSMEM);
    cudaFuncSetAttribute(attn_mma, cudaFuncAttributeMaxDynamicSharedMemorySize, ATT_SMEM);

    // conversions (launches 1-5)
    {
        int n;
        n = TOK*DD/4;  split_f16_kernel<<<(n+255)/256, 256>>>(xs, xc, DD, n);
        n = DD*DD/4;   conv_f16_kernel<<<(n+255)/256, 256>>>(Wq, wqkv, n);
        n = KVD*DD/4;  conv_f16_kernel<<<(n+255)/256, 256>>>(Wk, wqkv + (size_t)DD*DD, n);
        n = KVD*DD/4;  conv_f16_kernel<<<(n+255)/256, 256>>>(Wv, wqkv + (size_t)(DD+KVD)*DD, n);
        n = DD*DD/4;   conv_f16_kernel<<<(n+255)/256, 256>>>(Wo, woc, n);
    }

    // fused QKV projection + rope + split (launch 6)
    gemm_qkv<<<dim3(TOK/CTM, NQKV/CTN), 256, GSMEM>>>(
        xc, wqkv, bq, bk, bv, fc, spos, qhp, qlp, khp, vhp);

    // attention (launch 7)
    attn_mma<<<dim3(SS/128, QH, BB), 256, ATT_SMEM>>>(qhp, qlp, khp, vhp, cc);

    // output projection (launch 8)
    gemm_out<<<dim3(TOK/CTM, DD/CTN), 256, OSMEM>>>(cc, woc, bo, out, DD);
}

// round 13
// speedup vs baseline: 2.2458x; 1.1614x over previous
#include <cuda_runtime.h>
#include <cuda_fp16.h>
#include <math.h>
#include <stdint.h>

// Problem constants
#define BB   2
#define SS   2048
#define DD   4096
#define QH   32
#define KVH  8
#define HD   128
#define KVD  (KVH*HD)      // 1024
#define GROUP (QH/KVH)     // 4
#define TOK  (BB*SS)       // 4096
#define K2   (2*DD)        // 8192 : x split length [hi|lo]
#define NQKV (DD + 2*KVD)  // 6144

#define QSCALE (0.08838834764831845f * 1.4426950408889634f)

// ---------------------------------------------------------------------------
// Scratch
// ---------------------------------------------------------------------------
__device__ __align__(16) __half g_xc  [(size_t)TOK*K2];    // [xh | xl]
__device__ __align__(16) __half g_wqkv[(size_t)NQKV*DD];   // fp16 weights
__device__ __align__(16) __half g_woc [(size_t)DD*DD];
__device__ __align__(16) __half g_cc  [(size_t)TOK*DD];    // ctx, single fp16

__device__ __align__(16) __half g_qh[TOK*DD];
__device__ __align__(16) __half g_ql[TOK*DD];
__device__ __align__(16) __half g_kh[TOK*KVD];
__device__ __align__(16) __half g_vh[TOK*KVD];

// ---------------------------------------------------------------------------
// helpers
// ---------------------------------------------------------------------------
__device__ __forceinline__ uint32_t smem_u32(const void* p) {
    uint32_t a;
    asm("{ .reg .u64 t; cvta.to.shared.u64 t, %1; cvt.u32.u64 %0, t; }" : "=r"(a) : "l"(p));
    return a;
}

#define CP_ASYNC16(dst, src) \
    asm volatile("cp.async.cg.shared.global [%0], [%1], 16;" :: "r"(dst), "l"(src))
#define CP_COMMIT()   asm volatile("cp.async.commit_group;" ::: "memory")
#define CP_WAIT(n)    asm volatile("cp.async.wait_group %0;" :: "n"(n) : "memory")

#define LDM_X4(r0, r1, r2, r3, addr) \
    asm volatile("ldmatrix.sync.aligned.m8n8.x4.shared.b16 {%0,%1,%2,%3}, [%4];" \
        : "=r"(r0), "=r"(r1), "=r"(r2), "=r"(r3) : "r"(addr))

#define LDM_X4T(r0, r1, r2, r3, addr) \
    asm volatile("ldmatrix.sync.aligned.m8n8.x4.trans.shared.b16 {%0,%1,%2,%3}, [%4];" \
        : "=r"(r0), "=r"(r1), "=r"(r2), "=r"(r3) : "r"(addr))

#define MMA16816(d, a, b) \
    asm volatile("mma.sync.aligned.m16n8k16.row.col.f32.f16.f16.f32 " \
        "{%0,%1,%2,%3},{%4,%5,%6,%7},{%8,%9},{%0,%1,%2,%3};" \
        : "+f"((d)[0]), "+f"((d)[1]), "+f"((d)[2]), "+f"((d)[3]) \
        : "r"((a)[0]), "r"((a)[1]), "r"((a)[2]), "r"((a)[3]), \
          "r"((b)[0]), "r"((b)[1]))

__device__ __forceinline__ uint32_t pack_f16(float a, float b) {
    __half2 h = __floats2half2_rn(a, b);
    return *reinterpret_cast<uint32_t*>(&h);
}
__device__ __forceinline__ float2 unpack_f16(uint32_t u) {
    __half2 h = *reinterpret_cast<__half2*>(&u);
    return __half22float2(h);
}
__device__ __forceinline__ float ex2f(float x) {
    float r; asm("ex2.approx.f32 %0, %1;" : "=f"(r) : "f"(x)); return r;
}

// ---------------------------------------------------------------------------
// fp32 -> [hi | lo] fp16 split (row length 2K)
// ---------------------------------------------------------------------------
__global__ void split_f16_kernel(const float* __restrict__ in,
                                 __half* __restrict__ out, int K, int total4)
{
    int idx = blockIdx.x * blockDim.x + threadIdx.x;
    if (idx >= total4) return;
    float4 v = ((const float4*)in)[idx];
    int K4 = K >> 2;
    int r  = idx / K4;
    int k  = (idx - r * K4) << 2;
    uint32_t h0 = pack_f16(v.x, v.y);
    uint32_t h1 = pack_f16(v.z, v.w);
    float2 f0 = unpack_f16(h0), f1 = unpack_f16(h1);
    uint32_t l0 = pack_f16(v.x - f0.x, v.y - f0.y);
    uint32_t l1 = pack_f16(v.z - f1.x, v.w - f1.y);
    __half* row = out + (size_t)r * (2*K);
    *(uint2*)(row + k)     = make_uint2(h0, h1);
    *(uint2*)(row + K + k) = make_uint2(l0, l1);
}

// fp32 -> fp16 plain convert
__global__ void conv_f16_kernel(const float* __restrict__ in,
                                __half* __restrict__ out, int total4)
{
    int idx = blockIdx.x * blockDim.x + threadIdx.x;
    if (idx >= total4) return;
    float4 v = ((const float4*)in)[idx];
    ((uint2*)out)[idx] = make_uint2(pack_f16(v.x, v.y), pack_f16(v.z, v.w));
}

// ---------------------------------------------------------------------------
// common GEMM geometry
// ---------------------------------------------------------------------------
#define CTM   128
#define CTN   128
#define GBK   64
#define NCH   (DD / GBK)            // 64
#define ROWB  144                   // 64 fp16 (128B) + 16B pad
#define TILE  (128 * ROWB)          // 18432

// ---------------------------------------------------------------------------
// QKV GEMM: Q columns = (xh + xl) @ W^T (2-pass), K/V columns = xh @ W^T
// (1-pass: k,v are stored single-fp16 anyway so xl adds no accuracy).
// 2 stages of [Ah|Al|B] (55 KB), occ 2.  Fused rope + q hi/lo split.
// ---------------------------------------------------------------------------
#define NST   2
#define STAGE (3 * TILE)            // 55296
#define GSMEM (NST * STAGE)         // 110592

__global__ __launch_bounds__(256, 2) void gemm_qkv(
    const __half* __restrict__ A, const __half* __restrict__ B,
    const float* __restrict__ bq, const float* __restrict__ bk,
    const float* __restrict__ bv,
    const float* __restrict__ fc, const int* __restrict__ spos,
    __half* __restrict__ qh, __half* __restrict__ ql,
    __half* __restrict__ kh, __half* __restrict__ vh)
{
    extern __shared__ char smraw[];
    const int t    = threadIdx.x;
    const int lane = t & 31;
    const int wid  = t >> 5;
    const int wm   = wid & 1;
    const int wn   = wid >> 1;
    const int m0   = blockIdx.x * CTM;
    const int n0   = blockIdx.y * CTN;
    const bool twop = (n0 < DD);          // q segment: 2-pass
    const uint32_t sb = smem_u32(smraw);

    float acc[4][4][4];
#pragma unroll
    for (int i = 0; i < 4; i++)
#pragma unroll
        for (int j = 0; j < 4; j++)
#pragma unroll
            for (int r = 0; r < 4; r++) acc[i][j][r] = 0.f;

    const __half* Ahs[4];
    const __half* Bs[4];
    uint32_t doff[4];
#pragma unroll
    for (int i = 0; i < 4; i++) {
        int id  = t + i * 256;
        int row = id >> 3;
        int c8  = id & 7;
        doff[i] = row * ROWB + c8 * 16;
        Ahs[i]  = A + (size_t)(m0 + row) * K2 + c8 * 8;
        Bs[i]   = B + (size_t)(n0 + row) * DD + c8 * 8;
    }

#define LOAD_STAGE(st, k0) do {                                        \
    uint32_t base = sb + (st) * STAGE;                                 \
    _Pragma("unroll")                                                  \
    for (int i = 0; i < 4; i++)                                        \
        CP_ASYNC16(base + doff[i], Ahs[i] + (k0));                     \
    if (twop) {                                                        \
        _Pragma("unroll")                                              \
        for (int i = 0; i < 4; i++)                                    \
            CP_ASYNC16(base + TILE + doff[i], Ahs[i] + DD + (k0));     \
    }                                                                  \
    _Pragma("unroll")                                                  \
    for (int i = 0; i < 4; i++)                                        \
        CP_ASYNC16(base + 2 * TILE + doff[i], Bs[i] + (k0));           \
} while (0)

    LOAD_STAGE(0, 0);
    CP_COMMIT();

    const uint32_t aoffs = (wm * 64 + (lane & 15)) * ROWB + ((lane >> 4) << 4);
    const uint32_t boffs = (wn * 32 + (lane & 15)) * ROWB + ((lane >> 4) << 4);

    for (int c = 0; c < NCH; c++) {
        const int st = c & 1;
        CP_WAIT(0);
        __syncthreads();
        if (c + 1 < NCH) {
            LOAD_STAGE(st ^ 1, (c + 1) * GBK);
            CP_COMMIT();
        }

        const uint32_t ab  = sb + st * STAGE;
        const uint32_t ab2 = ab + TILE;
        const uint32_t bb  = ab + 2 * TILE;

#pragma unroll
        for (int ks = 0; ks < 4; ks++) {
            uint32_t a[4][4], a2[4][4];
            uint32_t bf[4][2];
#pragma unroll
            for (int mi = 0; mi < 4; mi++) {
                LDM_X4(a[mi][0], a[mi][1], a[mi][2], a[mi][3],
                       ab + aoffs + mi * 16 * ROWB + ks * 32);
            }
            if (twop) {
#pragma unroll
                for (int mi = 0; mi < 4; mi++)
                    LDM_X4(a2[mi][0], a2[mi][1], a2[mi][2], a2[mi][3],
                           ab2 + aoffs + mi * 16 * ROWB + ks * 32);
            }
#pragma unroll
            for (int p = 0; p < 2; p++) {
                uint32_t r0, r1, r2, r3;
                LDM_X4(r0, r1, r2, r3, bb + boffs + p * 16 * ROWB + ks * 32);
                bf[2*p][0]   = r0; bf[2*p][1]   = r2;
                bf[2*p+1][0] = r1; bf[2*p+1][1] = r3;
            }
#pragma unroll
            for (int mi = 0; mi < 4; mi++)
#pragma unroll
                for (int ni = 0; ni < 4; ni++)
                    MMA16816(acc[mi][ni], a[mi], bf[ni]);
            if (twop) {
#pragma unroll
                for (int mi = 0; mi < 4; mi++)
#pragma unroll
                    for (int ni = 0; ni < 4; ni++)
                        MMA16816(acc[mi][ni], a2[mi], bf[ni]);
            }
        }
    }
#undef LOAD_STAGE

    // fused QKV epilogue
    const int spv = spos[0];
    int seg, cbase;
    if (n0 < DD)            { seg = 0; cbase = 0; }
    else if (n0 < DD + KVD) { seg = 1; cbase = DD; }
    else                    { seg = 2; cbase = DD + KVD; }
    const float* bias = (seg == 0) ? bq : (seg == 1 ? bk : bv);
    __half* dh = (seg == 0) ? qh : (seg == 1 ? kh : vh);
    const int   ldd = (seg == 0) ? DD : KVD;
    const float sc  = (seg == 0) ? QSCALE : 1.0f;

#pragma unroll
    for (int mi = 0; mi < 4; mi++) {
        int ra = m0 + wm * 64 + mi * 16 + (lane >> 2);
        int rb = ra + 8;
        int sa  = ra & (SS - 1);
        int sbt = rb & (SS - 1);
#pragma unroll
        for (int ni = 0; ni < 4; ni++) {
            int c  = n0 + wn * 32 + ni * 8 + (lane & 3) * 2;
            int cl = c - cbase;
            float b0 = bias[cl], b1 = bias[cl + 1];
            float v0 = acc[mi][ni][0] + b0, v1 = acc[mi][ni][1] + b1;
            float v2 = acc[mi][ni][2] + b0, v3 = acc[mi][ni][3] + b1;
            if (seg < 2) {
                int p = (c & 127) >> 1;
                float2 fa = *(const float2*)(fc + ((size_t)(spv + sa)  * 64 + p) * 2);
                float2 fb = *(const float2*)(fc + ((size_t)(spv + sbt) * 64 + p) * 2);
                float o0 = (v0 * fa.x - v1 * fa.y) * sc;
                float o1 = (v0 * fa.y + v1 * fa.x) * sc;
                float o2 = (v2 * fb.x - v3 * fb.y) * sc;
                float o3 = (v2 * fb.y + v3 * fb.x) * sc;
                v0 = o0; v1 = o1; v2 = o2; v3 = o3;
            }
            uint32_t h0 = pack_f16(v0, v1);
            uint32_t h1 = pack_f16(v2, v3);
            *(uint32_t*)(dh + (size_t)ra * ldd + cl) = h0;
            *(uint32_t*)(dh + (size_t)rb * ldd + cl) = h1;
            if (seg == 0) {
                float2 f0 = unpack_f16(h0), f1 = unpack_f16(h1);
                *(uint32_t*)(ql + (size_t)ra * ldd + cl) = pack_f16(v0 - f0.x, v1 - f0.y);
                *(uint32_t*)(ql + (size_t)rb * ldd + cl) = pack_f16(v2 - f1.x, v3 - f1.y);
            }
        }
    }
}

// ---------------------------------------------------------------------------
// Output projection: single-pass fp16 GEMM, out = cc @ Wo^T + bo (fp32 out).
// 3 stages of [A|B] (37 KB), occ 2, CP_WAIT(1).
// ---------------------------------------------------------------------------
#define ONST   3
#define OSTAGE (2 * TILE)           // 36864
#define OSMEM  (ONST * OSTAGE)      // 110592

__global__ __launch_bounds__(256, 2) void gemm_out(
    const __half* __restrict__ A, const __half* __restrict__ B,
    const float* __restrict__ bias, float* __restrict__ C, int N)
{
    extern __shared__ char smraw[];
    const int t    = threadIdx.x;
    const int lane = t & 31;
    const int wid  = t >> 5;
    const int wm   = wid & 1;
    const int wn   = wid >> 1;
    const int m0   = blockIdx.x * CTM;
    const int n0   = blockIdx.y * CTN;
    const uint32_t sb = smem_u32(smraw);

    float acc[4][4][4];
#pragma unroll
    for (int i = 0; i < 4; i++)
#pragma unroll
        for (int j = 0; j < 4; j++)
#pragma unroll
            for (int r = 0; r < 4; r++) acc[i][j][r] = 0.f;

    const __half* As[4];
    const __half* Bs[4];
    uint32_t doff[4];
#pragma unroll
    for (int i = 0; i < 4; i++) {
        int id  = t + i * 256;
        int row = id >> 3;
        int c8  = id & 7;
        doff[i] = row * ROWB + c8 * 16;
        As[i]   = A + (size_t)(m0 + row) * DD + c8 * 8;
        Bs[i]   = B + (size_t)(n0 + row) * DD + c8 * 8;
    }

#define OLOAD(st, k0) do {                                             \
    uint32_t base = sb + (st) * OSTAGE;                                \
    _Pragma("unroll")                                                  \
    for (int i = 0; i < 4; i++)                                        \
        CP_ASYNC16(base + doff[i], As[i] + (k0));                      \
    _Pragma("unroll")                                                  \
    for (int i = 0; i < 4; i++)                                        \
        CP_ASYNC16(base + TILE + doff[i], Bs[i] + (k0));               \
} while (0)

    OLOAD(0, 0);
    CP_COMMIT();
    OLOAD(1, GBK);
    CP_COMMIT();

    const uint32_t aoffs = (wm * 64 + (lane & 15)) * ROWB + ((lane >> 4) << 4);
    const uint32_t boffs = (wn * 32 + (lane & 15)) * ROWB + ((lane >> 4) << 4);

    int st = 0;
    for (int c = 0; c < NCH; c++) {
        CP_WAIT(1);
        __syncthreads();
        if (c + 2 < NCH) {
            int st2 = st + 2; if (st2 >= ONST) st2 -= ONST;
            OLOAD(st2, (c + 2) * GBK);
        }
        CP_COMMIT();

        const uint32_t ab = sb + st * OSTAGE;
        const uint32_t bb = ab + TILE;

#pragma unroll
        for (int ks = 0; ks < 4; ks++) {
            uint32_t a[4][4];
            uint32_t bf[4][2];
#pragma unroll
            for (int mi = 0; mi < 4; mi++)
                LDM_X4(a[mi][0], a[mi][1], a[mi][2], a[mi][3],
                       ab + aoffs + mi * 16 * ROWB + ks * 32);
#pragma unroll
            for (int p = 0; p < 2; p++) {
                uint32_t r0, r1, r2, r3;
                LDM_X4(r0, r1, r2, r3, bb + boffs + p * 16 * ROWB + ks * 32);
                bf[2*p][0]   = r0; bf[2*p][1]   = r2;
                bf[2*p+1][0] = r1; bf[2*p+1][1] = r3;
            }
#pragma unroll
            for (int mi = 0; mi < 4; mi++)
#pragma unroll
                for (int ni = 0; ni < 4; ni++)
                    MMA16816(acc[mi][ni], a[mi], bf[ni]);
        }
        if (++st == ONST) st = 0;
    }
#undef OLOAD

#pragma unroll
    for (int mi = 0; mi < 4; mi++) {
        int r0 = m0 + wm * 64 + mi * 16 + (lane >> 2);
#pragma unroll
        for (int ni = 0; ni < 4; ni++) {
            int col = n0 + wn * 32 + ni * 8 + (lane & 3) * 2;
            float2 bv2 = *(const float2*)(bias + col);
            float2 o0 = make_float2(acc[mi][ni][0] + bv2.x, acc[mi][ni][1] + bv2.y);
            float2 o1 = make_float2(acc[mi][ni][2] + bv2.x, acc[mi][ni][3] + bv2.y);
            *(float2*)(C + (size_t)r0 * N + col)       = o0;
            *(float2*)(C + (size_t)(r0 + 8) * N + col) = o1;
        }
    }
}

// ---------------------------------------------------------------------------
// Tensor-core causal flash attention, fp16.
// Q (hi+lo) in registers; K,V single fp16; P single fp16 (lo-pass dropped);
// 4-stage KV ring; single fp16 ctx write.
// ---------------------------------------------------------------------------
#define AROW     272
#define SQ_SZ    (128 * AROW)
#define KT_SZ    (64 * AROW)
#define STG_VH   KT_SZ
#define STG_SZ   (2 * KT_SZ)
#define ATT_NST  4
#define ATT_SMEM (ATT_NST * STG_SZ)

__device__ __forceinline__ void att_load_kv(
    uint32_t dst, const __half* khb, const __half* vhb, int n0, int t)
{
#pragma unroll
    for (int i = 0; i < 4; ++i) {
        int id = t + i * 256;
        int r  = id >> 4, c = id & 15;
        uint32_t o  = r * AROW + c * 16;
        size_t   go = (size_t)(n0 + r) * KVD + c * 8;
        CP_ASYNC16(dst + o, khb + go);
        CP_ASYNC16(dst + STG_VH + o, vhb + go);
    }
}

__global__ __launch_bounds__(256, 1) void attn_mma(
    const __half* __restrict__ qh, const __half* __restrict__ ql,
    const __half* __restrict__ kh, const __half* __restrict__ vh,
    __half* __restrict__ cc)
{
    extern __shared__ char sm[];
    const int b   = blockIdx.z;
    const int h   = blockIdx.y;
    const int mb  = gridDim.x - 1 - blockIdx.x;
    const int m0  = mb * 128;
    const int kvh = h / GROUP;
    const int t    = threadIdx.x;
    const int lane = t & 31;
    const int w    = t >> 5;

    const uint32_t sb  = smem_u32(sm);
    const uint32_t sQh = sb + 2 * STG_SZ;
    const uint32_t sQl = sb + 3 * STG_SZ;

    const __half* qhb = qh + ((size_t)(b*SS + m0) * QH + h) * HD;
    const __half* qlb = ql + ((size_t)(b*SS + m0) * QH + h) * HD;
    const __half* khb = kh + ((size_t)b*SS*KVH + kvh) * HD;
    const __half* vhb = vh + ((size_t)b*SS*KVH + kvh) * HD;

    const int ntiles = 2 * mb + 2;

#pragma unroll
    for (int i = 0; i < 8; ++i) {
        int id = t + i * 256;
        int r  = id >> 4, c = id & 15;
        uint32_t o  = r * AROW + c * 16;
        size_t   go = (size_t)r * (QH*HD) + c * 8;
        CP_ASYNC16(sQh + o, qhb + go);
        CP_ASYNC16(sQl + o, qlb + go);
    }
    att_load_kv(sb, khb, vhb, 0, t);
    CP_COMMIT();
    if (ntiles > 1) att_load_kv(sb + STG_SZ, khb, vhb, 64, t);
    CP_COMMIT();

    const uint32_t qoff = (w * 16 + (lane & 15)) * AROW + ((lane >> 4) << 4);
    const uint32_t koff = (lane & 15) * AROW + ((lane >> 4) << 4);
    const int vrow = (lane & 7) + ((lane >> 4) << 3);
    const uint32_t vcol = ((lane >> 3) & 1) << 4;

    CP_WAIT(1);
    __syncthreads();
    uint32_t Aq[8][4], Al[8][4];
#pragma unroll
    for (int ch = 0; ch < 8; ++ch) {
        LDM_X4(Aq[ch][0], Aq[ch][1], Aq[ch][2], Aq[ch][3], sQh + qoff + ch * 32);
        LDM_X4(Al[ch][0], Al[ch][1], Al[ch][2], Al[ch][3], sQl + qoff + ch * 32);
    }
    __syncthreads();
    if (ntiles > 2) att_load_kv(sb + 2 * STG_SZ, khb, vhb, 128, t);
    CP_COMMIT();
    if (ntiles > 3) att_load_kv(sb + 3 * STG_SZ, khb, vhb, 192, t);
    CP_COMMIT();

    float O[16][4];
#pragma unroll
    for (int i = 0; i < 16; i++)
#pragma unroll
        for (int j = 0; j < 4; j++) O[i][j] = 0.f;
    float mx0 = -INFINITY, mx1 = -INFINITY, l0 = 0.f, l1 = 0.f;

    const int row0 = m0 + w * 16 + (lane >> 2);
    const int row1 = row0 + 8;
    const int wrow_hi = m0 + w * 16 + 15;
    const int wrow_lo = m0 + w * 16;

    for (int it = 0; it < ntiles; ++it) {
        const int n0 = it * 64;
        CP_WAIT(3);
        __syncthreads();
        const uint32_t stg = sb + (it & 3) * STG_SZ;

        if (n0 <= wrow_hi) {
            float S[8][4];
#pragma unroll
            for (int i = 0; i < 8; i++)
#pragma unroll
                for (int j = 0; j < 4; j++) S[i][j] = 0.f;

#pragma unroll
            for (int ch = 0; ch < 8; ++ch) {
#pragma unroll
                for (int p = 0; p < 4; ++p) {
                    uint32_t h0,h1,h2,h3;
                    LDM_X4(h0,h1,h2,h3, stg + koff + p*(16*AROW) + ch*32);
                    uint32_t bh0[2] = {h0, h2}, bh1[2] = {h1, h3};
                    MMA16816(S[2*p],   Aq[ch], bh0);
                    MMA16816(S[2*p+1], Aq[ch], bh1);
                    MMA16816(S[2*p],   Al[ch], bh0);
                    MMA16816(S[2*p+1], Al[ch], bh1);
                }
            }

            if (n0 + 63 > wrow_lo) {
#pragma unroll
                for (int p = 0; p < 8; ++p) {
                    int c = n0 + p * 8 + (lane & 3) * 2;
                    if (c     > row0) S[p][0] = -INFINITY;
                    if (c + 1 > row0) S[p][1] = -INFINITY;
                    if (c     > row1) S[p][2] = -INFINITY;
                    if (c + 1 > row1) S[p][3] = -INFINITY;
                }
            }

            float t0 = -INFINITY, t1 = -INFINITY;
#pragma unroll
            for (int p = 0; p < 8; ++p) {
                t0 = fmaxf(t0, fmaxf(S[p][0], S[p][1]));
                t1 = fmaxf(t1, fmaxf(S[p][2], S[p][3]));
            }
            t0 = fmaxf(t0, __shfl_xor_sync(0xffffffffu, t0, 1));
            t0 = fmaxf(t0, __shfl_xor_sync(0xffffffffu, t0, 2));
            t1 = fmaxf(t1, __shfl_xor_sync(0xffffffffu, t1, 1));
            t1 = fmaxf(t1, __shfl_xor_sync(0xffffffffu, t1, 2));
            float mn0 = fmaxf(mx0, t0), mn1 = fmaxf(mx1, t1);
            float cr0 = ex2f(mx0 - mn0), cr1 = ex2f(mx1 - mn1);
            mx0 = mn0; mx1 = mn1;

            float sa0 = 0.f, sa1 = 0.f;
#pragma unroll
            for (int p = 0; p < 8; ++p) {
                S[p][0] = ex2f(S[p][0] - mn0);
                S[p][1] = ex2f(S[p][1] - mn0);
                S[p][2] = ex2f(S[p][2] - mn1);
                S[p][3] = ex2f(S[p][3] - mn1);
                sa0 += S[p][0] + S[p][1];
                sa1 += S[p][2] + S[p][3];
            }
            sa0 += __shfl_xor_sync(0xffffffffu, sa0, 1);
            sa0 += __shfl_xor_sync(0xffffffffu, sa0, 2);
            sa1 += __shfl_xor_sync(0xffffffffu, sa1, 1);
            sa1 += __shfl_xor_sync(0xffffffffu, sa1, 2);
            l0 = l0 * cr0 + sa0;
            l1 = l1 * cr1 + sa1;

#pragma unroll
            for (int i = 0; i < 16; i++) {
                O[i][0] *= cr0; O[i][1] *= cr0;
                O[i][2] *= cr1; O[i][3] *= cr1;
            }

#pragma unroll
            for (int jc = 0; jc < 4; ++jc) {
                uint32_t ph[4];
#pragma unroll
                for (int q2 = 0; q2 < 2; ++q2) {
                    ph[2*q2]   = pack_f16(S[2*jc + q2][0], S[2*jc + q2][1]);
                    ph[2*q2+1] = pack_f16(S[2*jc + q2][2], S[2*jc + q2][3]);
                }
                const uint32_t vro = (jc * 16 + vrow) * AROW + vcol;
#pragma unroll
                for (int db = 0; db < 8; ++db) {
                    uint32_t a0,a1,a2,a3;
                    LDM_X4T(a0,a1,a2,a3, stg + STG_VH + vro + db * 32);
                    uint32_t bh0[2] = {a0, a2}, bh1[2] = {a1, a3};
                    MMA16816(O[2*db],   ph, bh0);
                    MMA16816(O[2*db+1], ph, bh1);
                }
            }
        }

        __syncthreads();
        if (it + ATT_NST < ntiles)
            att_load_kv(stg, khb, vhb, (it + ATT_NST) * 64, t);
        CP_COMMIT();
    }

    // normalize + single fp16 write to cc (row length DD)
    float inv0 = 1.0f / l0, inv1 = 1.0f / l1;
    const size_t base0 = (size_t)(b * SS + row0) * DD;
    const size_t base1 = (size_t)(b * SS + row1) * DD;
    const int colb = h * 128 + (lane & 3) * 2;
#pragma unroll
    for (int dt = 0; dt < 16; ++dt) {
        int col = colb + dt * 8;
        *(uint32_t*)(cc + base0 + col) = pack_f16(O[dt][0] * inv0, O[dt][1] * inv0);
        *(uint32_t*)(cc + base1 + col) = pack_f16(O[dt][2] * inv1, O[dt][3] * inv1);
    }
}

// ---------------------------------------------------------------------------
// launch
// ---------------------------------------------------------------------------
extern "C" void kernel_launch(void* const* d_in, const int* in_sizes, int n_in,
                              void* d_out, int out_size)
{
    const float* xs   = (const float*)d_in[0];
    const int*   spos = (const int*)  d_in[1];
    const float* fc   = (const float*)d_in[2];
    const float* Wq   = (const float*)d_in[3];
    const float* bq   = (const float*)d_in[4];
    const float* Wk   = (const float*)d_in[5];
    const float* bk   = (const float*)d_in[6];
    const float* Wv   = (const float*)d_in[7];
    const float* bv   = (const float*)d_in[8];
    const float* Wo   = (const float*)d_in[9];
    const float* bo   = (const float*)d_in[10];
    float* out = (float*)d_out;

    __half *xc, *wqkv, *woc, *cc, *qhp, *qlp, *khp, *vhp;
    cudaGetSymbolAddress((void**)&xc,   g_xc);
    cudaGetSymbolAddress((void**)&wqkv, g_wqkv);
    cudaGetSymbolAddress((void**)&woc,  g_woc);
    cudaGetSymbolAddress((void**)&cc,   g_cc);
    cudaGetSymbolAddress((void**)&qhp,  g_qh);
    cudaGetSymbolAddress((void**)&qlp,  g_ql);
    cudaGetSymbolAddress((void**)&khp,  g_kh);
    cudaGetSymbolAddress((void**)&vhp,  g_vh);

    cudaFuncSetAttribute(gemm_qkv, cudaFuncAttributeMaxDynamicSharedMemorySize, GSMEM);
    cudaFuncSetAttribute(gemm_out, cudaFuncAttributeMaxDynamicSharedMemorySize, OSMEM);
    cudaFuncSetAttribute(attn_mma, cudaFuncAttributeMaxDynamicSharedMemorySize, ATT_SMEM);

    // conversions (launches 1-5)
    {
        int n;
        n = TOK*DD/4;  split_f16_kernel<<<(n+255)/256, 256>>>(xs, xc, DD, n);
        n = DD*DD/4;   conv_f16_kernel<<<(n+255)/256, 256>>>(Wq, wqkv, n);
        n = KVD*DD/4;  conv_f16_kernel<<<(n+255)/256, 256>>>(Wk, wqkv + (size_t)DD*DD, n);
        n = KVD*DD/4;  conv_f16_kernel<<<(n+255)/256, 256>>>(Wv, wqkv + (size_t)(DD+KVD)*DD, n);
        n = DD*DD/4;   conv_f16_kernel<<<(n+255)/256, 256>>>(Wo, woc, n);
    }

    // fused QKV projection + rope + split (launch 6)
    gemm_qkv<<<dim3(TOK/CTM, NQKV/CTN), 256, GSMEM>>>(
        xc, wqkv, bq, bk, bv, fc, spos, qhp, qlp, khp, vhp);

    // attention (launch 7)
    attn_mma<<<dim3(SS/128, QH, BB), 256, ATT_SMEM>>>(qhp, qlp, khp, vhp, cc);

    // output projection (launch 8)
    gemm_out<<<dim3(TOK/CTM, DD/CTN), 256, OSMEM>>>(cc, woc, bo, out, DD);
}

// round 14
// speedup vs baseline: 2.2616x; 1.0070x over previous
#include <cuda_runtime.h>
#include <cuda_fp16.h>
#include <math.h>
#include <stdint.h>

// Problem constants
#define BB   2
#define SS   2048
#define DD   4096
#define QH   32
#define KVH  8
#define HD   128
#define KVD  (KVH*HD)      // 1024
#define GROUP (QH/KVH)     // 4
#define TOK  (BB*SS)       // 4096
#define K2   (2*DD)        // 8192 : x split length [hi|lo]
#define NQKV (DD + 2*KVD)  // 6144

#define QSCALE (0.08838834764831845f * 1.4426950408889634f)

// ---------------------------------------------------------------------------
// Scratch
// ---------------------------------------------------------------------------
__device__ __align__(16) __half g_xc  [(size_t)TOK*K2];    // [xh | xl]
__device__ __align__(16) __half g_wqkv[(size_t)NQKV*DD];   // fp16 weights
__device__ __align__(16) __half g_woc [(size_t)DD*DD];
__device__ __align__(16) __half g_cc  [(size_t)TOK*DD];    // ctx, single fp16

__device__ __align__(16) __half g_qh[TOK*DD];
__device__ __align__(16) __half g_ql[TOK*DD];
__device__ __align__(16) __half g_kh[TOK*KVD];
__device__ __align__(16) __half g_vh[TOK*KVD];

// ---------------------------------------------------------------------------
// helpers
// ---------------------------------------------------------------------------
__device__ __forceinline__ uint32_t smem_u32(const void* p) {
    uint32_t a;
    asm("{ .reg .u64 t; cvta.to.shared.u64 t, %1; cvt.u32.u64 %0, t; }" : "=r"(a) : "l"(p));
    return a;
}

#define CP_ASYNC16(dst, src) \
    asm volatile("cp.async.cg.shared.global [%0], [%1], 16;" :: "r"(dst), "l"(src))
#define CP_COMMIT()   asm volatile("cp.async.commit_group;" ::: "memory")
#define CP_WAIT(n)    asm volatile("cp.async.wait_group %0;" :: "n"(n) : "memory")

#define LDM_X4(r0, r1, r2, r3, addr) \
    asm volatile("ldmatrix.sync.aligned.m8n8.x4.shared.b16 {%0,%1,%2,%3}, [%4];" \
        : "=r"(r0), "=r"(r1), "=r"(r2), "=r"(r3) : "r"(addr))

#define LDM_X4T(r0, r1, r2, r3, addr) \
    asm volatile("ldmatrix.sync.aligned.m8n8.x4.trans.shared.b16 {%0,%1,%2,%3}, [%4];" \
        : "=r"(r0), "=r"(r1), "=r"(r2), "=r"(r3) : "r"(addr))

#define MMA16816(d, a, b) \
    asm volatile("mma.sync.aligned.m16n8k16.row.col.f32.f16.f16.f32 " \
        "{%0,%1,%2,%3},{%4,%5,%6,%7},{%8,%9},{%0,%1,%2,%3};" \
        : "+f"((d)[0]), "+f"((d)[1]), "+f"((d)[2]), "+f"((d)[3]) \
        : "r"((a)[0]), "r"((a)[1]), "r"((a)[2]), "r"((a)[3]), \
          "r"((b)[0]), "r"((b)[1]))

__device__ __forceinline__ uint32_t pack_f16(float a, float b) {
    __half2 h = __floats2half2_rn(a, b);
    return *reinterpret_cast<uint32_t*>(&h);
}
__device__ __forceinline__ float2 unpack_f16(uint32_t u) {
    __half2 h = *reinterpret_cast<__half2*>(&u);
    return __half22float2(h);
}
__device__ __forceinline__ float ex2f(float x) {
    float r; asm("ex2.approx.f32 %0, %1;" : "=f"(r) : "f"(x)); return r;
}

// ---------------------------------------------------------------------------
// Fused conversion kernel: one launch covers
//   region 0: x  -> [xh|xl] split           (TOK*DD items of 4 floats)
//   region 1: Wq -> wqkv[0]                 (DD*DD/4)
//   region 2: Wk -> wqkv[DD*DD]             (KVD*DD/4)
//   region 3: Wv -> wqkv[(DD+KVD)*DD]       (KVD*DD/4)
//   region 4: Wo -> woc                     (DD*DD/4)
// ---------------------------------------------------------------------------
#define CN0 (TOK*DD/4)
#define CN1 (DD*DD/4)
#define CN2 (KVD*DD/4)
#define CN3 (KVD*DD/4)
#define CN4 (DD*DD/4)
#define CNTOT (CN0+CN1+CN2+CN3+CN4)

__global__ void convert_all(const float* __restrict__ xs,
                            const float* __restrict__ Wq,
                            const float* __restrict__ Wk,
                            const float* __restrict__ Wv,
                            const float* __restrict__ Wo,
                            __half* __restrict__ xc,
                            __half* __restrict__ wqkv,
                            __half* __restrict__ woc)
{
    int gid = blockIdx.x * blockDim.x + threadIdx.x;
    if (gid >= CNTOT) return;
    if (gid < CN0) {
        // x hi/lo split, row length 2*DD
        float4 v = ((const float4*)xs)[gid];
        int K4 = DD >> 2;
        int r  = gid / K4;
        int k  = (gid - r * K4) << 2;
        uint32_t h0 = pack_f16(v.x, v.y);
        uint32_t h1 = pack_f16(v.z, v.w);
        float2 f0 = unpack_f16(h0), f1 = unpack_f16(h1);
        uint32_t l0 = pack_f16(v.x - f0.x, v.y - f0.y);
        uint32_t l1 = pack_f16(v.z - f1.x, v.w - f1.y);
        __half* row = xc + (size_t)r * K2;
        *(uint2*)(row + k)      = make_uint2(h0, h1);
        *(uint2*)(row + DD + k) = make_uint2(l0, l1);
        return;
    }
    gid -= CN0;
    const float* src;
    __half* dst;
    if (gid < CN1)                 { src = Wq; dst = wqkv; }
    else if (gid < CN1 + CN2)      { gid -= CN1; src = Wk; dst = wqkv + (size_t)DD*DD; }
    else if (gid < CN1 + CN2 + CN3){ gid -= CN1 + CN2; src = Wv; dst = wqkv + (size_t)(DD+KVD)*DD; }
    else                           { gid -= CN1 + CN2 + CN3; src = Wo; dst = woc; }
    float4 v = ((const float4*)src)[gid];
    ((uint2*)dst)[gid] = make_uint2(pack_f16(v.x, v.y), pack_f16(v.z, v.w));
}

// ---------------------------------------------------------------------------
// common GEMM geometry
// ---------------------------------------------------------------------------
#define CTM   128
#define CTN   128
#define GBK   64
#define NCH   (DD / GBK)            // 64
#define ROWB  144                   // 64 fp16 (128B) + 16B pad
#define TILE  (128 * ROWB)          // 18432

// ---------------------------------------------------------------------------
// QKV GEMM: Q columns = (xh + xl) @ W^T (2-pass), K/V columns = xh @ W^T.
// 2 stages of [Ah|Al|B] (55 KB), occ 2.  Fused rope + q hi/lo split.
// ---------------------------------------------------------------------------
#define NST   2
#define STAGE (3 * TILE)            // 55296
#define GSMEM (NST * STAGE)         // 110592

__global__ __launch_bounds__(256, 2) void gemm_qkv(
    const __half* __restrict__ A, const __half* __restrict__ B,
    const float* __restrict__ bq, const float* __restrict__ bk,
    const float* __restrict__ bv,
    const float* __restrict__ fc, const int* __restrict__ spos,
    __half* __restrict__ qh, __half* __restrict__ ql,
    __half* __restrict__ kh, __half* __restrict__ vh)
{
    extern __shared__ char smraw[];
    const int t    = threadIdx.x;
    const int lane = t & 31;
    const int wid  = t >> 5;
    const int wm   = wid & 1;
    const int wn   = wid >> 1;
    const int m0   = blockIdx.x * CTM;
    const int n0   = blockIdx.y * CTN;
    const bool twop = (n0 < DD);          // q segment: 2-pass
    const uint32_t sb = smem_u32(smraw);

    float acc[4][4][4];
#pragma unroll
    for (int i = 0; i < 4; i++)
#pragma unroll
        for (int j = 0; j < 4; j++)
#pragma unroll
            for (int r = 0; r < 4; r++) acc[i][j][r] = 0.f;

    const __half* Ahs[4];
    const __half* Bs[4];
    uint32_t doff[4];
#pragma unroll
    for (int i = 0; i < 4; i++) {
        int id  = t + i * 256;
        int row = id >> 3;
        int c8  = id & 7;
        doff[i] = row * ROWB + c8 * 16;
        Ahs[i]  = A + (size_t)(m0 + row) * K2 + c8 * 8;
        Bs[i]   = B + (size_t)(n0 + row) * DD + c8 * 8;
    }

#define LOAD_STAGE(st, k0) do {                                        \
    uint32_t base = sb + (st) * STAGE;                                 \
    _Pragma("unroll")                                                  \
    for (int i = 0; i < 4; i++)                                        \
        CP_ASYNC16(base + doff[i], Ahs[i] + (k0));                     \
    if (twop) {                                                        \
        _Pragma("unroll")                                              \
        for (int i = 0; i < 4; i++)                                    \
            CP_ASYNC16(base + TILE + doff[i], Ahs[i] + DD + (k0));     \
    }                                                                  \
    _Pragma("unroll")                                                  \
    for (int i = 0; i < 4; i++)                                        \
        CP_ASYNC16(base + 2 * TILE + doff[i], Bs[i] + (k0));           \
} while (0)

    LOAD_STAGE(0, 0);
    CP_COMMIT();

    const uint32_t aoffs = (wm * 64 + (lane & 15)) * ROWB + ((lane >> 4) << 4);
    const uint32_t boffs = (wn * 32 + (lane & 15)) * ROWB + ((lane >> 4) << 4);

    for (int c = 0; c < NCH; c++) {
        const int st = c & 1;
        CP_WAIT(0);
        __syncthreads();
        if (c + 1 < NCH) {
            LOAD_STAGE(st ^ 1, (c + 1) * GBK);
            CP_COMMIT();
        }

        const uint32_t ab  = sb + st * STAGE;
        const uint32_t ab2 = ab + TILE;
        const uint32_t bb  = ab + 2 * TILE;

#pragma unroll
        for (int ks = 0; ks < 4; ks++) {
            uint32_t a[4][4], a2[4][4];
            uint32_t bf[4][2];
#pragma unroll
            for (int mi = 0; mi < 4; mi++) {
                LDM_X4(a[mi][0], a[mi][1], a[mi][2], a[mi][3],
                       ab + aoffs + mi * 16 * ROWB + ks * 32);
            }
            if (twop) {
#pragma unroll
                for (int mi = 0; mi < 4; mi++)
                    LDM_X4(a2[mi][0], a2[mi][1], a2[mi][2], a2[mi][3],
                           ab2 + aoffs + mi * 16 * ROWB + ks * 32);
            }
#pragma unroll
            for (int p = 0; p < 2; p++) {
                uint32_t r0, r1, r2, r3;
                LDM_X4(r0, r1, r2, r3, bb + boffs + p * 16 * ROWB + ks * 32);
                bf[2*p][0]   = r0; bf[2*p][1]   = r2;
                bf[2*p+1][0] = r1; bf[2*p+1][1] = r3;
            }
#pragma unroll
            for (int mi = 0; mi < 4; mi++)
#pragma unroll
                for (int ni = 0; ni < 4; ni++)
                    MMA16816(acc[mi][ni], a[mi], bf[ni]);
            if (twop) {
#pragma unroll
                for (int mi = 0; mi < 4; mi++)
#pragma unroll
                    for (int ni = 0; ni < 4; ni++)
                        MMA16816(acc[mi][ni], a2[mi], bf[ni]);
            }
        }
    }
#undef LOAD_STAGE

    // fused QKV epilogue
    const int spv = spos[0];
    int seg, cbase;
    if (n0 < DD)            { seg = 0; cbase = 0; }
    else if (n0 < DD + KVD) { seg = 1; cbase = DD; }
    else                    { seg = 2; cbase = DD + KVD; }
    const float* bias = (seg == 0) ? bq : (seg == 1 ? bk : bv);
    __half* dh = (seg == 0) ? qh : (seg == 1 ? kh : vh);
    const int   ldd = (seg == 0) ? DD : KVD;
    const float sc  = (seg == 0) ? QSCALE : 1.0f;

#pragma unroll
    for (int mi = 0; mi < 4; mi++) {
        int ra = m0 + wm * 64 + mi * 16 + (lane >> 2);
        int rb = ra + 8;
        int sa  = ra & (SS - 1);
        int sbt = rb & (SS - 1);
#pragma unroll
        for (int ni = 0; ni < 4; ni++) {
            int c  = n0 + wn * 32 + ni * 8 + (lane & 3) * 2;
            int cl = c - cbase;
            float b0 = bias[cl], b1 = bias[cl + 1];
            float v0 = acc[mi][ni][0] + b0, v1 = acc[mi][ni][1] + b1;
            float v2 = acc[mi][ni][2] + b0, v3 = acc[mi][ni][3] + b1;
            if (seg < 2) {
                int p = (c & 127) >> 1;
                float2 fa = *(const float2*)(fc + ((size_t)(spv + sa)  * 64 + p) * 2);
                float2 fb = *(const float2*)(fc + ((size_t)(spv + sbt) * 64 + p) * 2);
                float o0 = (v0 * fa.x - v1 * fa.y) * sc;
                float o1 = (v0 * fa.y + v1 * fa.x) * sc;
                float o2 = (v2 * fb.x - v3 * fb.y) * sc;
                float o3 = (v2 * fb.y + v3 * fb.x) * sc;
                v0 = o0; v1 = o1; v2 = o2; v3 = o3;
            }
            uint32_t h0 = pack_f16(v0, v1);
            uint32_t h1 = pack_f16(v2, v3);
            *(uint32_t*)(dh + (size_t)ra * ldd + cl) = h0;
            *(uint32_t*)(dh + (size_t)rb * ldd + cl) = h1;
            if (seg == 0) {
                float2 f0 = unpack_f16(h0), f1 = unpack_f16(h1);
                *(uint32_t*)(ql + (size_t)ra * ldd + cl) = pack_f16(v0 - f0.x, v1 - f0.y);
                *(uint32_t*)(ql + (size_t)rb * ldd + cl) = pack_f16(v2 - f1.x, v3 - f1.y);
            }
        }
    }
}

// ---------------------------------------------------------------------------
// Output projection: single-pass fp16 GEMM, out = cc @ Wo^T + bo (fp32 out).
// 3 stages of [A|B] (37 KB), occ 2, CP_WAIT(1).
// ---------------------------------------------------------------------------
#define ONST   3
#define OSTAGE (2 * TILE)           // 36864
#define OSMEM  (ONST * OSTAGE)      // 110592

__global__ __launch_bounds__(256, 2) void gemm_out(
    const __half* __restrict__ A, const __half* __restrict__ B,
    const float* __restrict__ bias, float* __restrict__ C, int N)
{
    extern __shared__ char smraw[];
    const int t    = threadIdx.x;
    const int lane = t & 31;
    const int wid  = t >> 5;
    const int wm   = wid & 1;
    const int wn   = wid >> 1;
    const int m0   = blockIdx.x * CTM;
    const int n0   = blockIdx.y * CTN;
    const uint32_t sb = smem_u32(smraw);

    float acc[4][4][4];
#pragma unroll
    for (int i = 0; i < 4; i++)
#pragma unroll
        for (int j = 0; j < 4; j++)
#pragma unroll
            for (int r = 0; r < 4; r++) acc[i][j][r] = 0.f;

    const __half* As[4];
    const __half* Bs[4];
    uint32_t doff[4];
#pragma unroll
    for (int i = 0; i < 4; i++) {
        int id  = t + i * 256;
        int row = id >> 3;
        int c8  = id & 7;
        doff[i] = row * ROWB + c8 * 16;
        As[i]   = A + (size_t)(m0 + row) * DD + c8 * 8;
        Bs[i]   = B + (size_t)(n0 + row) * DD + c8 * 8;
    }

#define OLOAD(st, k0) do {                                             \
    uint32_t base = sb + (st) * OSTAGE;                                \
    _Pragma("unroll")                                                  \
    for (int i = 0; i < 4; i++)                                        \
        CP_ASYNC16(base + doff[i], As[i] + (k0));                      \
    _Pragma("unroll")                                                  \
    for (int i = 0; i < 4; i++)                                        \
        CP_ASYNC16(base + TILE + doff[i], Bs[i] + (k0));               \
} while (0)

    OLOAD(0, 0);
    CP_COMMIT();
    OLOAD(1, GBK);
    CP_COMMIT();

    const uint32_t aoffs = (wm * 64 + (lane & 15)) * ROWB + ((lane >> 4) << 4);
    const uint32_t boffs = (wn * 32 + (lane & 15)) * ROWB + ((lane >> 4) << 4);

    int st = 0;
    for (int c = 0; c < NCH; c++) {
        CP_WAIT(1);
        __syncthreads();
        if (c + 2 < NCH) {
            int st2 = st + 2; if (st2 >= ONST) st2 -= ONST;
            OLOAD(st2, (c + 2) * GBK);
        }
        CP_COMMIT();

        const uint32_t ab = sb + st * OSTAGE;
        const uint32_t bb = ab + TILE;

#pragma unroll
        for (int ks = 0; ks < 4; ks++) {
            uint32_t a[4][4];
            uint32_t bf[4][2];
#pragma unroll
            for (int mi = 0; mi < 4; mi++)
                LDM_X4(a[mi][0], a[mi][1], a[mi][2], a[mi][3],
                       ab + aoffs + mi * 16 * ROWB + ks * 32);
#pragma unroll
            for (int p = 0; p < 2; p++) {
                uint32_t r0, r1, r2, r3;
                LDM_X4(r0, r1, r2, r3, bb + boffs + p * 16 * ROWB + ks * 32);
                bf[2*p][0]   = r0; bf[2*p][1]   = r2;
                bf[2*p+1][0] = r1; bf[2*p+1][1] = r3;
            }
#pragma unroll
            for (int mi = 0; mi < 4; mi++)
#pragma unroll
                for (int ni = 0; ni < 4; ni++)
                    MMA16816(acc[mi][ni], a[mi], bf[ni]);
        }
        if (++st == ONST) st = 0;
    }
#undef OLOAD

#pragma unroll
    for (int mi = 0; mi < 4; mi++) {
        int r0 = m0 + wm * 64 + mi * 16 + (lane >> 2);
#pragma unroll
        for (int ni = 0; ni < 4; ni++) {
            int col = n0 + wn * 32 + ni * 8 + (lane & 3) * 2;
            float2 bv2 = *(const float2*)(bias + col);
            float2 o0 = make_float2(acc[mi][ni][0] + bv2.x, acc[mi][ni][1] + bv2.y);
            float2 o1 = make_float2(acc[mi][ni][2] + bv2.x, acc[mi][ni][3] + bv2.y);
            *(float2*)(C + (size_t)r0 * N + col)       = o0;
            *(float2*)(C + (size_t)(r0 + 8) * N + col) = o1;
        }
    }
}

// ---------------------------------------------------------------------------
// Tensor-core causal flash attention, fp16.
// Q (hi+lo) in registers; K,V single fp16; P single fp16; 4-stage KV ring.
// Single __syncthreads per tile: WAIT(2) -> sync -> prefetch(it+3) -> compute.
// ---------------------------------------------------------------------------
#define AROW     272
#define SQ_SZ    (128 * AROW)
#define KT_SZ    (64 * AROW)
#define STG_VH   KT_SZ
#define STG_SZ   (2 * KT_SZ)
#define ATT_NST  4
#define ATT_SMEM (ATT_NST * STG_SZ)

__device__ __forceinline__ void att_load_kv(
    uint32_t dst, const __half* khb, const __half* vhb, int n0, int t)
{
#pragma unroll
    for (int i = 0; i < 4; ++i) {
        int id = t + i * 256;
        int r  = id >> 4, c = id & 15;
        uint32_t o  = r * AROW + c * 16;
        size_t   go = (size_t)(n0 + r) * KVD + c * 8;
        CP_ASYNC16(dst + o, khb + go);
        CP_ASYNC16(dst + STG_VH + o, vhb + go);
    }
}

__global__ __launch_bounds__(256, 1) void attn_mma(
    const __half* __restrict__ qh, const __half* __restrict__ ql,
    const __half* __restrict__ kh, const __half* __restrict__ vh,
    __half* __restrict__ cc)
{
    extern __shared__ char sm[];
    const int b   = blockIdx.z;
    const int h   = blockIdx.y;
    const int mb  = gridDim.x - 1 - blockIdx.x;
    const int m0  = mb * 128;
    const int kvh = h / GROUP;
    const int t    = threadIdx.x;
    const int lane = t & 31;
    const int w    = t >> 5;

    const uint32_t sb  = smem_u32(sm);
    const uint32_t sQh = sb + 2 * STG_SZ;
    const uint32_t sQl = sb + 3 * STG_SZ;

    const __half* qhb = qh + ((size_t)(b*SS + m0) * QH + h) * HD;
    const __half* qlb = ql + ((size_t)(b*SS + m0) * QH + h) * HD;
    const __half* khb = kh + ((size_t)b*SS*KVH + kvh) * HD;
    const __half* vhb = vh + ((size_t)b*SS*KVH + kvh) * HD;

    const int ntiles = 2 * mb + 2;

    // group 0: Q + kv0 ; group 1: kv1
#pragma unroll
    for (int i = 0; i < 8; ++i) {
        int id = t + i * 256;
        int r  = id >> 4, c = id & 15;
        uint32_t o  = r * AROW + c * 16;
        size_t   go = (size_t)r * (QH*HD) + c * 8;
        CP_ASYNC16(sQh + o, qhb + go);
        CP_ASYNC16(sQl + o, qlb + go);
    }
    att_load_kv(sb, khb, vhb, 0, t);
    CP_COMMIT();
    if (ntiles > 1) att_load_kv(sb + STG_SZ, khb, vhb, 64, t);
    CP_COMMIT();

    const uint32_t qoff = (w * 16 + (lane & 15)) * AROW + ((lane >> 4) << 4);
    const uint32_t koff = (lane & 15) * AROW + ((lane >> 4) << 4);
    const int vrow = (lane & 7) + ((lane >> 4) << 3);
    const uint32_t vcol = ((lane >> 3) & 1) << 4;

    // one-time Q register load (retires group 0 -> tile 0 ready)
    CP_WAIT(1);
    __syncthreads();
    uint32_t Aq[8][4], Al[8][4];
#pragma unroll
    for (int ch = 0; ch < 8; ++ch) {
        LDM_X4(Aq[ch][0], Aq[ch][1], Aq[ch][2], Aq[ch][3], sQh + qoff + ch * 32);
        LDM_X4(Al[ch][0], Al[ch][1], Al[ch][2], Al[ch][3], sQl + qoff + ch * 32);
    }
    __syncthreads();   // Q consumed -> stages 2,3 free
    // group 2: kv2 into stage 2
    if (ntiles > 2) att_load_kv(sb + 2 * STG_SZ, khb, vhb, 128, t);
    CP_COMMIT();
    // outstanding: {kv1, kv2}; tile 0 retired.

    float O[16][4];
#pragma unroll
    for (int i = 0; i < 16; i++)
#pragma unroll
        for (int j = 0; j < 4; j++) O[i][j] = 0.f;
    float mx0 = -INFINITY, mx1 = -INFINITY, l0 = 0.f, l1 = 0.f;

    const int row0 = m0 + w * 16 + (lane >> 2);
    const int row1 = row0 + 8;
    const int wrow_hi = m0 + w * 16 + 15;
    const int wrow_lo = m0 + w * 16;

    for (int it = 0; it < ntiles; ++it) {
        const int n0 = it * 64;
        // retire tile it (outstanding before wait: tiles it..it+2 = 3 groups max)
        CP_WAIT(2);
        __syncthreads();      // tile it visible; tile it-1's stage fully consumed
        if (it + 3 < ntiles)
            att_load_kv(sb + ((it + 3) & 3) * STG_SZ, khb, vhb, (it + 3) * 64, t);
        CP_COMMIT();          // unconditional: 1 group per iteration

        const uint32_t stg = sb + (it & 3) * STG_SZ;

        if (n0 <= wrow_hi) {
            float S[8][4];
#pragma unroll
            for (int i = 0; i < 8; i++)
#pragma unroll
                for (int j = 0; j < 4; j++) S[i][j] = 0.f;

#pragma unroll
            for (int ch = 0; ch < 8; ++ch) {
#pragma unroll
                for (int p = 0; p < 4; ++p) {
                    uint32_t h0,h1,h2,h3;
                    LDM_X4(h0,h1,h2,h3, stg + koff + p*(16*AROW) + ch*32);
                    uint32_t bh0[2] = {h0, h2}, bh1[2] = {h1, h3};
                    MMA16816(S[2*p],   Aq[ch], bh0);
                    MMA16816(S[2*p+1], Aq[ch], bh1);
                    MMA16816(S[2*p],   Al[ch], bh0);
                    MMA16816(S[2*p+1], Al[ch], bh1);
                }
            }

            if (n0 + 63 > wrow_lo) {
#pragma unroll
                for (int p = 0; p < 8; ++p) {
                    int c = n0 + p * 8 + (lane & 3) * 2;
                    if (c     > row0) S[p][0] = -INFINITY;
                    if (c + 1 > row0) S[p][1] = -INFINITY;
                    if (c     > row1) S[p][2] = -INFINITY;
                    if (c + 1 > row1) S[p][3] = -INFINITY;
                }
            }

            float t0 = -INFINITY, t1 = -INFINITY;
#pragma unroll
            for (int p = 0; p < 8; ++p) {
                t0 = fmaxf(t0, fmaxf(S[p][0], S[p][1]));
                t1 = fmaxf(t1, fmaxf(S[p][2], S[p][3]));
            }
            t0 = fmaxf(t0, __shfl_xor_sync(0xffffffffu, t0, 1));
            t0 = fmaxf(t0, __shfl_xor_sync(0xffffffffu, t0, 2));
            t1 = fmaxf(t1, __shfl_xor_sync(0xffffffffu, t1, 1));
            t1 = fmaxf(t1, __shfl_xor_sync(0xffffffffu, t1, 2));
            float mn0 = fmaxf(mx0, t0), mn1 = fmaxf(mx1, t1);
            float cr0 = ex2f(mx0 - mn0), cr1 = ex2f(mx1 - mn1);
            mx0 = mn0; mx1 = mn1;

            float sa0 = 0.f, sa1 = 0.f;
#pragma unroll
            for (int p = 0; p < 8; ++p) {
                S[p][0] = ex2f(S[p][0] - mn0);
                S[p][1] = ex2f(S[p][1] - mn0);
                S[p][2] = ex2f(S[p][2] - mn1);
                S[p][3] = ex2f(S[p][3] - mn1);
                sa0 += S[p][0] + S[p][1];
                sa1 += S[p][2] + S[p][3];
            }
            sa0 += __shfl_xor_sync(0xffffffffu, sa0, 1);
            sa0 += __shfl_xor_sync(0xffffffffu, sa0, 2);
            sa1 += __shfl_xor_sync(0xffffffffu, sa1, 1);
            sa1 += __shfl_xor_sync(0xffffffffu, sa1, 2);
            l0 = l0 * cr0 + sa0;
            l1 = l1 * cr1 + sa1;

#pragma unroll
            for (int i = 0; i < 16; i++) {
                O[i][0] *= cr0; O[i][1] *= cr0;
                O[i][2] *= cr1; O[i][3] *= cr1;
            }

#pragma unroll
            for (int jc = 0; jc < 4; ++jc) {
                uint32_t ph[4];
#pragma unroll
                for (int q2 = 0; q2 < 2; ++q2) {
                    ph[2*q2]   = pack_f16(S[2*jc + q2][0], S[2*jc + q2][1]);
                    ph[2*q2+1] = pack_f16(S[2*jc + q2][2], S[2*jc + q2][3]);
                }
                const uint32_t vro = (jc * 16 + vrow) * AROW + vcol;
#pragma unroll
                for (int db = 0; db < 8; ++db) {
                    uint32_t a0,a1,a2,a3;
                    LDM_X4T(a0,a1,a2,a3, stg + STG_VH + vro + db * 32);
                    uint32_t bh0[2] = {a0, a2}, bh1[2] = {a1, a3};
                    MMA16816(O[2*db],   ph, bh0);
                    MMA16816(O[2*db+1], ph, bh1);
                }
            }
        }
    }

    // normalize + single fp16 write to cc (row length DD)
    float inv0 = 1.0f / l0, inv1 = 1.0f / l1;
    const size_t base0 = (size_t)(b * SS + row0) * DD;
    const size_t base1 = (size_t)(b * SS + row1) * DD;
    const int colb = h * 128 + (lane & 3) * 2;
#pragma unroll
    for (int dt = 0; dt < 16; ++dt) {
        int col = colb + dt * 8;
        *(uint32_t*)(cc + base0 + col) = pack_f16(O[dt][0] * inv0, O[dt][1] * inv0);
        *(uint32_t*)(cc + base1 + col) = pack_f16(O[dt][2] * inv1, O[dt][3] * inv1);
    }
}

// ---------------------------------------------------------------------------
// launch
// ---------------------------------------------------------------------------
extern "C" void kernel_launch(void* const* d_in, const int* in_sizes, int n_in,
                              void* d_out, int out_size)
{
    const float* xs   = (const float*)d_in[0];
    const int*   spos = (const int*)  d_in[1];
    const float* fc   = (const float*)d_in[2];
    const float* Wq   = (const float*)d_in[3];
    const float* bq   = (const float*)d_in[4];
    const float* Wk   = (const float*)d_in[5];
    const float* bk   = (const float*)d_in[6];
    const float* Wv   = (const float*)d_in[7];
    const float* bv   = (const float*)d_in[8];
    const float* Wo   = (const float*)d_in[9];
    const float* bo   = (const float*)d_in[10];
    float* out = (float*)d_out;

    __half *xc, *wqkv, *woc, *cc, *qhp, *qlp, *khp, *vhp;
    cudaGetSymbolAddress((void**)&xc,   g_xc);
    cudaGetSymbolAddress((void**)&wqkv, g_wqkv);
    cudaGetSymbolAddress((void**)&woc,  g_woc);
    cudaGetSymbolAddress((void**)&cc,   g_cc);
    cudaGetSymbolAddress((void**)&qhp,  g_qh);
    cudaGetSymbolAddress((void**)&qlp,  g_ql);
    cudaGetSymbolAddress((void**)&khp,  g_kh);
    cudaGetSymbolAddress((void**)&vhp,  g_vh);

    cudaFuncSetAttribute(gemm_qkv, cudaFuncAttributeMaxDynamicSharedMemorySize, GSMEM);
    cudaFuncSetAttribute(gemm_out, cudaFuncAttributeMaxDynamicSharedMemorySize, OSMEM);
    cudaFuncSetAttribute(attn_mma, cudaFuncAttributeMaxDynamicSharedMemorySize, ATT_SMEM);

    // fused conversions (launch 1)
    convert_all<<<(CNTOT + 255) / 256, 256>>>(xs, Wq, Wk, Wv, Wo, xc, wqkv, woc);

    // fused QKV projection + rope + split (launch 2)
    gemm_qkv<<<dim3(TOK/CTM, NQKV/CTN), 256, GSMEM>>>(
        xc, wqkv, bq, bk, bv, fc, spos, qhp, qlp, khp, vhp);

    // attention (launch 3)
    attn_mma<<<dim3(SS/128, QH, BB), 256, ATT_SMEM>>>(qhp, qlp, khp, vhp, cc);

    // output projection (launch 4)
    gemm_out<<<dim3(TOK/CTM, DD/CTN), 256, OSMEM>>>(cc, woc, bo, out, DD);
}

// round 15
// speedup vs baseline: 2.2624x; 1.0004x over previous
#include <cuda_runtime.h>
#include <cuda_fp16.h>
#include <math.h>
#include <stdint.h>

// Problem constants
#define BB   2
#define SS   2048
#define DD   4096
#define QH   32
#define KVH  8
#define HD   128
#define KVD  (KVH*HD)      // 1024
#define GROUP (QH/KVH)     // 4
#define TOK  (BB*SS)       // 4096
#define K2   (2*DD)        // 8192 : x split length [hi|lo]
#define NQKV (DD + 2*KVD)  // 6144

#define QSCALE (0.08838834764831845f * 1.4426950408889634f)

// ---------------------------------------------------------------------------
// Scratch
// ---------------------------------------------------------------------------
__device__ __align__(16) __half g_xc  [(size_t)TOK*K2];    // [xh | xl]
__device__ __align__(16) __half g_wqkv[(size_t)NQKV*DD];   // fp16 weights
__device__ __align__(16) __half g_woc [(size_t)DD*DD];
__device__ __align__(16) __half g_cc  [(size_t)TOK*DD];    // ctx, single fp16

__device__ __align__(16) __half g_qh[TOK*DD];
__device__ __align__(16) __half g_ql[TOK*DD];
__device__ __align__(16) __half g_kh[TOK*KVD];
__device__ __align__(16) __half g_vh[TOK*KVD];

// ---------------------------------------------------------------------------
// helpers
// ---------------------------------------------------------------------------
__device__ __forceinline__ uint32_t smem_u32(const void* p) {
    uint32_t a;
    asm("{ .reg .u64 t; cvta.to.shared.u64 t, %1; cvt.u32.u64 %0, t; }" : "=r"(a) : "l"(p));
    return a;
}

#define CP_ASYNC16(dst, src) \
    asm volatile("cp.async.cg.shared.global [%0], [%1], 16;" :: "r"(dst), "l"(src))
#define CP_COMMIT()   asm volatile("cp.async.commit_group;" ::: "memory")
#define CP_WAIT(n)    asm volatile("cp.async.wait_group %0;" :: "n"(n) : "memory")

#define LDM_X4(r0, r1, r2, r3, addr) \
    asm volatile("ldmatrix.sync.aligned.m8n8.x4.shared.b16 {%0,%1,%2,%3}, [%4];" \
        : "=r"(r0), "=r"(r1), "=r"(r2), "=r"(r3) : "r"(addr))

#define LDM_X4T(r0, r1, r2, r3, addr) \
    asm volatile("ldmatrix.sync.aligned.m8n8.x4.trans.shared.b16 {%0,%1,%2,%3}, [%4];" \
        : "=r"(r0), "=r"(r1), "=r"(r2), "=r"(r3) : "r"(addr))

#define MMA16816(d, a, b) \
    asm volatile("mma.sync.aligned.m16n8k16.row.col.f32.f16.f16.f32 " \
        "{%0,%1,%2,%3},{%4,%5,%6,%7},{%8,%9},{%0,%1,%2,%3};" \
        : "+f"((d)[0]), "+f"((d)[1]), "+f"((d)[2]), "+f"((d)[3]) \
        : "r"((a)[0]), "r"((a)[1]), "r"((a)[2]), "r"((a)[3]), \
          "r"((b)[0]), "r"((b)[1]))

__device__ __forceinline__ uint32_t pack_f16(float a, float b) {
    __half2 h = __floats2half2_rn(a, b);
    return *reinterpret_cast<uint32_t*>(&h);
}
__device__ __forceinline__ float2 unpack_f16(uint32_t u) {
    __half2 h = *reinterpret_cast<__half2*>(&u);
    return __half22float2(h);
}
__device__ __forceinline__ float ex2f(float x) {
    float r; asm("ex2.approx.f32 %0, %1;" : "=f"(r) : "f"(x)); return r;
}

// ---------------------------------------------------------------------------
// Fused conversion kernel (one launch, 5 regions)
// ---------------------------------------------------------------------------
#define CN0 (TOK*DD/4)
#define CN1 (DD*DD/4)
#define CN2 (KVD*DD/4)
#define CN3 (KVD*DD/4)
#define CN4 (DD*DD/4)
#define CNTOT (CN0+CN1+CN2+CN3+CN4)

__global__ void convert_all(const float* __restrict__ xs,
                            const float* __restrict__ Wq,
                            const float* __restrict__ Wk,
                            const float* __restrict__ Wv,
                            const float* __restrict__ Wo,
                            __half* __restrict__ xc,
                            __half* __restrict__ wqkv,
                            __half* __restrict__ woc)
{
    int gid = blockIdx.x * blockDim.x + threadIdx.x;
    if (gid >= CNTOT) return;
    if (gid < CN0) {
        float4 v = ((const float4*)xs)[gid];
        int K4 = DD >> 2;
        int r  = gid / K4;
        int k  = (gid - r * K4) << 2;
        uint32_t h0 = pack_f16(v.x, v.y);
        uint32_t h1 = pack_f16(v.z, v.w);
        float2 f0 = unpack_f16(h0), f1 = unpack_f16(h1);
        uint32_t l0 = pack_f16(v.x - f0.x, v.y - f0.y);
        uint32_t l1 = pack_f16(v.z - f1.x, v.w - f1.y);
        __half* row = xc + (size_t)r * K2;
        *(uint2*)(row + k)      = make_uint2(h0, h1);
        *(uint2*)(row + DD + k) = make_uint2(l0, l1);
        return;
    }
    gid -= CN0;
    const float* src;
    __half* dst;
    if (gid < CN1)                 { src = Wq; dst = wqkv; }
    else if (gid < CN1 + CN2)      { gid -= CN1; src = Wk; dst = wqkv + (size_t)DD*DD; }
    else if (gid < CN1 + CN2 + CN3){ gid -= CN1 + CN2; src = Wv; dst = wqkv + (size_t)(DD+KVD)*DD; }
    else                           { gid -= CN1 + CN2 + CN3; src = Wo; dst = woc; }
    float4 v = ((const float4*)src)[gid];
    ((uint2*)dst)[gid] = make_uint2(pack_f16(v.x, v.y), pack_f16(v.z, v.w));
}

// ---------------------------------------------------------------------------
// common GEMM geometry
// ---------------------------------------------------------------------------
#define CTM   128
#define CTN   128
#define GBK   64
#define NCH   (DD / GBK)            // 64
#define ROWB  144                   // 64 fp16 (128B) + 16B pad
#define TILE  (128 * ROWB)          // 18432

// ---------------------------------------------------------------------------
// QKV GEMM: Q columns = (xh + xl) @ W^T (2-pass), K/V columns = xh @ W^T.
// 2 stages of [Ah|Al|B] (55 KB), occ 2.  Fused rope + q hi/lo split.
// ---------------------------------------------------------------------------
#define NST   2
#define STAGE (3 * TILE)            // 55296
#define GSMEM (NST * STAGE)         // 110592

__global__ __launch_bounds__(256, 2) void gemm_qkv(
    const __half* __restrict__ A, const __half* __restrict__ B,
    const float* __restrict__ bq, const float* __restrict__ bk,
    const float* __restrict__ bv,
    const float* __restrict__ fc, const int* __restrict__ spos,
    __half* __restrict__ qh, __half* __restrict__ ql,
    __half* __restrict__ kh, __half* __restrict__ vh)
{
    extern __shared__ char smraw[];
    const int t    = threadIdx.x;
    const int lane = t & 31;
    const int wid  = t >> 5;
    const int wm   = wid & 1;
    const int wn   = wid >> 1;
    const int m0   = blockIdx.x * CTM;
    const int n0   = blockIdx.y * CTN;
    const bool twop = (n0 < DD);          // q segment: 2-pass
    const uint32_t sb = smem_u32(smraw);

    float acc[4][4][4];
#pragma unroll
    for (int i = 0; i < 4; i++)
#pragma unroll
        for (int j = 0; j < 4; j++)
#pragma unroll
            for (int r = 0; r < 4; r++) acc[i][j][r] = 0.f;

    const __half* Ahs[4];
    const __half* Bs[4];
    uint32_t doff[4];
#pragma unroll
    for (int i = 0; i < 4; i++) {
        int id  = t + i * 256;
        int row = id >> 3;
        int c8  = id & 7;
        doff[i] = row * ROWB + c8 * 16;
        Ahs[i]  = A + (size_t)(m0 + row) * K2 + c8 * 8;
        Bs[i]   = B + (size_t)(n0 + row) * DD + c8 * 8;
    }

#define LOAD_STAGE(st, k0) do {                                        \
    uint32_t base = sb + (st) * STAGE;                                 \
    _Pragma("unroll")                                                  \
    for (int i = 0; i < 4; i++)                                        \
        CP_ASYNC16(base + doff[i], Ahs[i] + (k0));                     \
    if (twop) {                                                        \
        _Pragma("unroll")                                              \
        for (int i = 0; i < 4; i++)                                    \
            CP_ASYNC16(base + TILE + doff[i], Ahs[i] + DD + (k0));     \
    }                                                                  \
    _Pragma("unroll")                                                  \
    for (int i = 0; i < 4; i++)                                        \
        CP_ASYNC16(base + 2 * TILE + doff[i], Bs[i] + (k0));           \
} while (0)

    LOAD_STAGE(0, 0);
    CP_COMMIT();

    const uint32_t aoffs = (wm * 64 + (lane & 15)) * ROWB + ((lane >> 4) << 4);
    const uint32_t boffs = (wn * 32 + (lane & 15)) * ROWB + ((lane >> 4) << 4);

    for (int c = 0; c < NCH; c++) {
        const int st = c & 1;
        CP_WAIT(0);
        __syncthreads();
        if (c + 1 < NCH) {
            LOAD_STAGE(st ^ 1, (c + 1) * GBK);
            CP_COMMIT();
        }

        const uint32_t ab  = sb + st * STAGE;
        const uint32_t ab2 = ab + TILE;
        const uint32_t bb  = ab + 2 * TILE;

#pragma unroll
        for (int ks = 0; ks < 4; ks++) {
            uint32_t a[4][4], a2[4][4];
            uint32_t bf[4][2];
#pragma unroll
            for (int mi = 0; mi < 4; mi++) {
                LDM_X4(a[mi][0], a[mi][1], a[mi][2], a[mi][3],
                       ab + aoffs + mi * 16 * ROWB + ks * 32);
            }
            if (twop) {
#pragma unroll
                for (int mi = 0; mi < 4; mi++)
                    LDM_X4(a2[mi][0], a2[mi][1], a2[mi][2], a2[mi][3],
                           ab2 + aoffs + mi * 16 * ROWB + ks * 32);
            }
#pragma unroll
            for (int p = 0; p < 2; p++) {
                uint32_t r0, r1, r2, r3;
                LDM_X4(r0, r1, r2, r3, bb + boffs + p * 16 * ROWB + ks * 32);
                bf[2*p][0]   = r0; bf[2*p][1]   = r2;
                bf[2*p+1][0] = r1; bf[2*p+1][1] = r3;
            }
#pragma unroll
            for (int mi = 0; mi < 4; mi++)
#pragma unroll
                for (int ni = 0; ni < 4; ni++)
                    MMA16816(acc[mi][ni], a[mi], bf[ni]);
            if (twop) {
#pragma unroll
                for (int mi = 0; mi < 4; mi++)
#pragma unroll
                    for (int ni = 0; ni < 4; ni++)
                        MMA16816(acc[mi][ni], a2[mi], bf[ni]);
            }
        }
    }
#undef LOAD_STAGE

    // fused QKV epilogue
    const int spv = spos[0];
    int seg, cbase;
    if (n0 < DD)            { seg = 0; cbase = 0; }
    else if (n0 < DD + KVD) { seg = 1; cbase = DD; }
    else                    { seg = 2; cbase = DD + KVD; }
    const float* bias = (seg == 0) ? bq : (seg == 1 ? bk : bv);
    __half* dh = (seg == 0) ? qh : (seg == 1 ? kh : vh);
    const int   ldd = (seg == 0) ? DD : KVD;
    const float sc  = (seg == 0) ? QSCALE : 1.0f;

#pragma unroll
    for (int mi = 0; mi < 4; mi++) {
        int ra = m0 + wm * 64 + mi * 16 + (lane >> 2);
        int rb = ra + 8;
        int sa  = ra & (SS - 1);
        int sbt = rb & (SS - 1);
#pragma unroll
        for (int ni = 0; ni < 4; ni++) {
            int c  = n0 + wn * 32 + ni * 8 + (lane & 3) * 2;
            int cl = c - cbase;
            float b0 = bias[cl], b1 = bias[cl + 1];
            float v0 = acc[mi][ni][0] + b0, v1 = acc[mi][ni][1] + b1;
            float v2 = acc[mi][ni][2] + b0, v3 = acc[mi][ni][3] + b1;
            if (seg < 2) {
                int p = (c & 127) >> 1;
                float2 fa = *(const float2*)(fc + ((size_t)(spv + sa)  * 64 + p) * 2);
                float2 fb = *(const float2*)(fc + ((size_t)(spv + sbt) * 64 + p) * 2);
                float o0 = (v0 * fa.x - v1 * fa.y) * sc;
                float o1 = (v0 * fa.y + v1 * fa.x) * sc;
                float o2 = (v2 * fb.x - v3 * fb.y) * sc;
                float o3 = (v2 * fb.y + v3 * fb.x) * sc;
                v0 = o0; v1 = o1; v2 = o2; v3 = o3;
            }
            uint32_t h0 = pack_f16(v0, v1);
            uint32_t h1 = pack_f16(v2, v3);
            *(uint32_t*)(dh + (size_t)ra * ldd + cl) = h0;
            *(uint32_t*)(dh + (size_t)rb * ldd + cl) = h1;
            if (seg == 0) {
                float2 f0 = unpack_f16(h0), f1 = unpack_f16(h1);
                *(uint32_t*)(ql + (size_t)ra * ldd + cl) = pack_f16(v0 - f0.x, v1 - f0.y);
                *(uint32_t*)(ql + (size_t)rb * ldd + cl) = pack_f16(v2 - f1.x, v3 - f1.y);
            }
        }
    }
}

// ---------------------------------------------------------------------------
// Output projection: single-pass fp16 GEMM with B-fragment double buffering.
// 3 stages of [A|B] (37 KB), occ 2, CP_WAIT(1).
// ---------------------------------------------------------------------------
#define ONST   3
#define OSTAGE (2 * TILE)           // 36864
#define OSMEM  (ONST * OSTAGE)      // 110592

__global__ __launch_bounds__(256, 2) void gemm_out(
    const __half* __restrict__ A, const __half* __restrict__ B,
    const float* __restrict__ bias, float* __restrict__ C, int N)
{
    extern __shared__ char smraw[];
    const int t    = threadIdx.x;
    const int lane = t & 31;
    const int wid  = t >> 5;
    const int wm   = wid & 1;
    const int wn   = wid >> 1;
    const int m0   = blockIdx.x * CTM;
    const int n0   = blockIdx.y * CTN;
    const uint32_t sb = smem_u32(smraw);

    float acc[4][4][4];
#pragma unroll
    for (int i = 0; i < 4; i++)
#pragma unroll
        for (int j = 0; j < 4; j++)
#pragma unroll
            for (int r = 0; r < 4; r++) acc[i][j][r] = 0.f;

    const __half* As[4];
    const __half* Bs[4];
    uint32_t doff[4];
#pragma unroll
    for (int i = 0; i < 4; i++) {
        int id  = t + i * 256;
        int row = id >> 3;
        int c8  = id & 7;
        doff[i] = row * ROWB + c8 * 16;
        As[i]   = A + (size_t)(m0 + row) * DD + c8 * 8;
        Bs[i]   = B + (size_t)(n0 + row) * DD + c8 * 8;
    }

#define OLOAD(st, k0) do {                                             \
    uint32_t base = sb + (st) * OSTAGE;                                \
    _Pragma("unroll")                                                  \
    for (int i = 0; i < 4; i++)                                        \
        CP_ASYNC16(base + doff[i], As[i] + (k0));                      \
    _Pragma("unroll")                                                  \
    for (int i = 0; i < 4; i++)                                        \
        CP_ASYNC16(base + TILE + doff[i], Bs[i] + (k0));               \
} while (0)

    OLOAD(0, 0);
    CP_COMMIT();
    OLOAD(1, GBK);
    CP_COMMIT();

    const uint32_t aoffs = (wm * 64 + (lane & 15)) * ROWB + ((lane >> 4) << 4);
    const uint32_t boffs = (wn * 32 + (lane & 15)) * ROWB + ((lane >> 4) << 4);

    int st = 0;
    for (int c = 0; c < NCH; c++) {
        CP_WAIT(1);
        __syncthreads();
        if (c + 2 < NCH) {
            int st2 = st + 2; if (st2 >= ONST) st2 -= ONST;
            OLOAD(st2, (c + 2) * GBK);
        }
        CP_COMMIT();

        const uint32_t ab = sb + st * OSTAGE;
        const uint32_t bb = ab + TILE;

        // B fragment double buffer: preload ks=0, prefetch ks+1 during MMAs
        uint32_t bf[2][4][2];
        {
            uint32_t r0, r1, r2, r3;
            LDM_X4(r0, r1, r2, r3, bb + boffs);
            bf[0][0][0] = r0; bf[0][0][1] = r2;
            bf[0][1][0] = r1; bf[0][1][1] = r3;
            LDM_X4(r0, r1, r2, r3, bb + boffs + 16 * ROWB);
            bf[0][2][0] = r0; bf[0][2][1] = r2;
            bf[0][3][0] = r1; bf[0][3][1] = r3;
        }

#pragma unroll
        for (int ks = 0; ks < 4; ks++) {
            const int cur = ks & 1;
            uint32_t a[4][4];
#pragma unroll
            for (int mi = 0; mi < 4; mi++)
                LDM_X4(a[mi][0], a[mi][1], a[mi][2], a[mi][3],
                       ab + aoffs + mi * 16 * ROWB + ks * 32);
            if (ks < 3) {
                uint32_t r0, r1, r2, r3;
                LDM_X4(r0, r1, r2, r3, bb + boffs + (ks + 1) * 32);
                bf[cur^1][0][0] = r0; bf[cur^1][0][1] = r2;
                bf[cur^1][1][0] = r1; bf[cur^1][1][1] = r3;
                LDM_X4(r0, r1, r2, r3, bb + boffs + 16 * ROWB + (ks + 1) * 32);
                bf[cur^1][2][0] = r0; bf[cur^1][2][1] = r2;
                bf[cur^1][3][0] = r1; bf[cur^1][3][1] = r3;
            }
#pragma unroll
            for (int mi = 0; mi < 4; mi++)
#pragma unroll
                for (int ni = 0; ni < 4; ni++)
                    MMA16816(acc[mi][ni], a[mi], bf[cur][ni]);
        }
        if (++st == ONST) st = 0;
    }
#undef OLOAD

#pragma unroll
    for (int mi = 0; mi < 4; mi++) {
        int r0 = m0 + wm * 64 + mi * 16 + (lane >> 2);
#pragma unroll
        for (int ni = 0; ni < 4; ni++) {
            int col = n0 + wn * 32 + ni * 8 + (lane & 3) * 2;
            float2 bv2 = *(const float2*)(bias + col);
            float2 o0 = make_float2(acc[mi][ni][0] + bv2.x, acc[mi][ni][1] + bv2.y);
            float2 o1 = make_float2(acc[mi][ni][2] + bv2.x, acc[mi][ni][3] + bv2.y);
            *(float2*)(C + (size_t)r0 * N + col)       = o0;
            *(float2*)(C + (size_t)(r0 + 8) * N + col) = o1;
        }
    }
}

// ---------------------------------------------------------------------------
// Tensor-core causal flash attention, fp16 (unchanged from R14).
// ---------------------------------------------------------------------------
#define AROW     272
#define SQ_SZ    (128 * AROW)
#define KT_SZ    (64 * AROW)
#define STG_VH   KT_SZ
#define STG_SZ   (2 * KT_SZ)
#define ATT_NST  4
#define ATT_SMEM (ATT_NST * STG_SZ)

__device__ __forceinline__ void att_load_kv(
    uint32_t dst, const __half* khb, const __half* vhb, int n0, int t)
{
#pragma unroll
    for (int i = 0; i < 4; ++i) {
        int id = t + i * 256;
        int r  = id >> 4, c = id & 15;
        uint32_t o  = r * AROW + c * 16;
        size_t   go = (size_t)(n0 + r) * KVD + c * 8;
        CP_ASYNC16(dst + o, khb + go);
        CP_ASYNC16(dst + STG_VH + o, vhb + go);
    }
}

__global__ __launch_bounds__(256, 1) void attn_mma(
    const __half* __restrict__ qh, const __half* __restrict__ ql,
    const __half* __restrict__ kh, const __half* __restrict__ vh,
    __half* __restrict__ cc)
{
    extern __shared__ char sm[];
    const int b   = blockIdx.z;
    const int h   = blockIdx.y;
    const int mb  = gridDim.x - 1 - blockIdx.x;
    const int m0  = mb * 128;
    const int kvh = h / GROUP;
    const int t    = threadIdx.x;
    const int lane = t & 31;
    const int w    = t >> 5;

    const uint32_t sb  = smem_u32(sm);
    const uint32_t sQh = sb + 2 * STG_SZ;
    const uint32_t sQl = sb + 3 * STG_SZ;

    const __half* qhb = qh + ((size_t)(b*SS + m0) * QH + h) * HD;
    const __half* qlb = ql + ((size_t)(b*SS + m0) * QH + h) * HD;
    const __half* khb = kh + ((size_t)b*SS*KVH + kvh) * HD;
    const __half* vhb = vh + ((size_t)b*SS*KVH + kvh) * HD;

    const int ntiles = 2 * mb + 2;

#pragma unroll
    for (int i = 0; i < 8; ++i) {
        int id = t + i * 256;
        int r  = id >> 4, c = id & 15;
        uint32_t o  = r * AROW + c * 16;
        size_t   go = (size_t)r * (QH*HD) + c * 8;
        CP_ASYNC16(sQh + o, qhb + go);
        CP_ASYNC16(sQl + o, qlb + go);
    }
    att_load_kv(sb, khb, vhb, 0, t);
    CP_COMMIT();
    if (ntiles > 1) att_load_kv(sb + STG_SZ, khb, vhb, 64, t);
    CP_COMMIT();

    const uint32_t qoff = (w * 16 + (lane & 15)) * AROW + ((lane >> 4) << 4);
    const uint32_t koff = (lane & 15) * AROW + ((lane >> 4) << 4);
    const int vrow = (lane & 7) + ((lane >> 4) << 3);
    const uint32_t vcol = ((lane >> 3) & 1) << 4;

    CP_WAIT(1);
    __syncthreads();
    uint32_t Aq[8][4], Al[8][4];
#pragma unroll
    for (int ch = 0; ch < 8; ++ch) {
        LDM_X4(Aq[ch][0], Aq[ch][1], Aq[ch][2], Aq[ch][3], sQh + qoff + ch * 32);
        LDM_X4(Al[ch][0], Al[ch][1], Al[ch][2], Al[ch][3], sQl + qoff + ch * 32);
    }
    __syncthreads();
    if (ntiles > 2) att_load_kv(sb + 2 * STG_SZ, khb, vhb, 128, t);
    CP_COMMIT();

    float O[16][4];
#pragma unroll
    for (int i = 0; i < 16; i++)
#pragma unroll
        for (int j = 0; j < 4; j++) O[i][j] = 0.f;
    float mx0 = -INFINITY, mx1 = -INFINITY, l0 = 0.f, l1 = 0.f;

    const int row0 = m0 + w * 16 + (lane >> 2);
    const int row1 = row0 + 8;
    const int wrow_hi = m0 + w * 16 + 15;
    const int wrow_lo = m0 + w * 16;

    for (int it = 0; it < ntiles; ++it) {
        const int n0 = it * 64;
        CP_WAIT(2);
        __syncthreads();
        if (it + 3 < ntiles)
            att_load_kv(sb + ((it + 3) & 3) * STG_SZ, khb, vhb, (it + 3) * 64, t);
        CP_COMMIT();

        const uint32_t stg = sb + (it & 3) * STG_SZ;

        if (n0 <= wrow_hi) {
            float S[8][4];
#pragma unroll
            for (int i = 0; i < 8; i++)
#pragma unroll
                for (int j = 0; j < 4; j++) S[i][j] = 0.f;

#pragma unroll
            for (int ch = 0; ch < 8; ++ch) {
#pragma unroll
                for (int p = 0; p < 4; ++p) {
                    uint32_t h0,h1,h2,h3;
                    LDM_X4(h0,h1,h2,h3, stg + koff + p*(16*AROW) + ch*32);
                    uint32_t bh0[2] = {h0, h2}, bh1[2] = {h1, h3};
                    MMA16816(S[2*p],   Aq[ch], bh0);
                    MMA16816(S[2*p+1], Aq[ch], bh1);
                    MMA16816(S[2*p],   Al[ch], bh0);
                    MMA16816(S[2*p+1], Al[ch], bh1);
                }
            }

            if (n0 + 63 > wrow_lo) {
#pragma unroll
                for (int p = 0; p < 8; ++p) {
                    int c = n0 + p * 8 + (lane & 3) * 2;
                    if (c     > row0) S[p][0] = -INFINITY;
                    if (c + 1 > row0) S[p][1] = -INFINITY;
                    if (c     > row1) S[p][2] = -INFINITY;
                    if (c + 1 > row1) S[p][3] = -INFINITY;
                }
            }

            float t0 = -INFINITY, t1 = -INFINITY;
#pragma unroll
            for (int p = 0; p < 8; ++p) {
                t0 = fmaxf(t0, fmaxf(S[p][0], S[p][1]));
                t1 = fmaxf(t1, fmaxf(S[p][2], S[p][3]));
            }
            t0 = fmaxf(t0, __shfl_xor_sync(0xffffffffu, t0, 1));
            t0 = fmaxf(t0, __shfl_xor_sync(0xffffffffu, t0, 2));
            t1 = fmaxf(t1, __shfl_xor_sync(0xffffffffu, t1, 1));
            t1 = fmaxf(t1, __shfl_xor_sync(0xffffffffu, t1, 2));
            float mn0 = fmaxf(mx0, t0), mn1 = fmaxf(mx1, t1);
            float cr0 = ex2f(mx0 - mn0), cr1 = ex2f(mx1 - mn1);
            mx0 = mn0; mx1 = mn1;

            float sa0 = 0.f, sa1 = 0.f;
#pragma unroll
            for (int p = 0; p < 8; ++p) {
                S[p][0] = ex2f(S[p][0] - mn0);
                S[p][1] = ex2f(S[p][1] - mn0);
                S[p][2] = ex2f(S[p][2] - mn1);
                S[p][3] = ex2f(S[p][3] - mn1);
                sa0 += S[p][0] + S[p][1];
                sa1 += S[p][2] + S[p][3];
            }
            sa0 += __shfl_xor_sync(0xffffffffu, sa0, 1);
            sa0 += __shfl_xor_sync(0xffffffffu, sa0, 2);
            sa1 += __shfl_xor_sync(0xffffffffu, sa1, 1);
            sa1 += __shfl_xor_sync(0xffffffffu, sa1, 2);
            l0 = l0 * cr0 + sa0;
            l1 = l1 * cr1 + sa1;

#pragma unroll
            for (int i = 0; i < 16; i++) {
                O[i][0] *= cr0; O[i][1] *= cr0;
                O[i][2] *= cr1; O[i][3] *= cr1;
            }

#pragma unroll
            for (int jc = 0; jc < 4; ++jc) {
                uint32_t ph[4];
#pragma unroll
                for (int q2 = 0; q2 < 2; ++q2) {
                    ph[2*q2]   = pack_f16(S[2*jc + q2][0], S[2*jc + q2][1]);
                    ph[2*q2+1] = pack_f16(S[2*jc + q2][2], S[2*jc + q2][3]);
                }
                const uint32_t vro = (jc * 16 + vrow) * AROW + vcol;
#pragma unroll
                for (int db = 0; db < 8; ++db) {
                    uint32_t a0,a1,a2,a3;
                    LDM_X4T(a0,a1,a2,a3, stg + STG_VH + vro + db * 32);
                    uint32_t bh0[2] = {a0, a2}, bh1[2] = {a1, a3};
                    MMA16816(O[2*db],   ph, bh0);
                    MMA16816(O[2*db+1], ph, bh1);
                }
            }
        }
    }

    float inv0 = 1.0f / l0, inv1 = 1.0f / l1;
    const size_t base0 = (size_t)(b * SS + row0) * DD;
    const size_t base1 = (size_t)(b * SS + row1) * DD;
    const int colb = h * 128 + (lane & 3) * 2;
#pragma unroll
    for (int dt = 0; dt < 16; ++dt) {
        int col = colb + dt * 8;
        *(uint32_t*)(cc + base0 + col) = pack_f16(O[dt][0] * inv0, O[dt][1] * inv0);
        *(uint32_t*)(cc + base1 + col) = pack_f16(O[dt][2] * inv1, O[dt][3] * inv1);
    }
}

// ---------------------------------------------------------------------------
// launch
// ---------------------------------------------------------------------------
extern "C" void kernel_launch(void* const* d_in, const int* in_sizes, int n_in,
                              void* d_out, int out_size)
{
    const float* xs   = (const float*)d_in[0];
    const int*   spos = (const int*)  d_in[1];
    const float* fc   = (const float*)d_in[2];
    const float* Wq   = (const float*)d_in[3];
    const float* bq   = (const float*)d_in[4];
    const float* Wk   = (const float*)d_in[5];
    const float* bk   = (const float*)d_in[6];
    const float* Wv   = (const float*)d_in[7];
    const float* bv   = (const float*)d_in[8];
    const float* Wo   = (const float*)d_in[9];
    const float* bo   = (const float*)d_in[10];
    float* out = (float*)d_out;

    __half *xc, *wqkv, *woc, *cc, *qhp, *qlp, *khp, *vhp;
    cudaGetSymbolAddress((void**)&xc,   g_xc);
    cudaGetSymbolAddress((void**)&wqkv, g_wqkv);
    cudaGetSymbolAddress((void**)&woc,  g_woc);
    cudaGetSymbolAddress((void**)&cc,   g_cc);
    cudaGetSymbolAddress((void**)&qhp,  g_qh);
    cudaGetSymbolAddress((void**)&qlp,  g_ql);
    cudaGetSymbolAddress((void**)&khp,  g_kh);
    cudaGetSymbolAddress((void**)&vhp,  g_vh);

    cudaFuncSetAttribute(gemm_qkv, cudaFuncAttributeMaxDynamicSharedMemorySize, GSMEM);
    cudaFuncSetAttribute(gemm_out, cudaFuncAttributeMaxDynamicSharedMemorySize, OSMEM);
    cudaFuncSetAttribute(attn_mma, cudaFuncAttributeMaxDynamicSharedMemorySize, ATT_SMEM);

    // fused conversions (launch 1)
    convert_all<<<(CNTOT + 255) / 256, 256>>>(xs, Wq, Wk, Wv, Wo, xc, wqkv, woc);

    // fused QKV projection + rope + split (launch 2)
    gemm_qkv<<<dim3(TOK/CTM, NQKV/CTN), 256, GSMEM>>>(
        xc, wqkv, bq, bk, bv, fc, spos, qhp, qlp, khp, vhp);

    // attention (launch 3)
    attn_mma<<<dim3(SS/128, QH, BB), 256, ATT_SMEM>>>(qhp, qlp, khp, vhp, cc);

    // output projection (launch 4)
    gemm_out<<<dim3(TOK/CTM, DD/CTN), 256, OSMEM>>>(cc, woc, bo, out, DD);
}